// round 4
// baseline (speedup 1.0000x reference)
#include <cuda_runtime.h>
#include <cstdint>

#define VOC   32768
#define DIM   512
#define BATCH 4096
#define TOPK  64
#define MAXSEL 128

// dots tile config (mma.sync tf32): CTA 128x128, 8 warps of 32x64
#define MT 128
#define NT 128
#define KC 32
#define KITERS (DIM / KC)        // 16
#define LDP 36                   // padded floats per smem row
#define A_FLOATS (MT * LDP)      // 4608
#define B_FLOATS (NT * LDP)      // 4608
#define ST_FLOATS (2 * A_FLOATS + 2 * B_FLOATS)   // 18432
#define ST_BYTES  (ST_FLOATS * 4)                 // 73728

// ---------------- scratch (static device globals; no allocation allowed) ----
__device__ float g_v [(size_t)VOC * DIM];
__device__ float g_qh[(size_t)BATCH * DIM];
__device__ float g_ql[(size_t)BATCH * DIM];
__device__ float g_kh[(size_t)VOC * DIM];
__device__ float g_kl[(size_t)VOC * DIM];
__device__ float g_dots[(size_t)BATCH * VOC];   // 512 MB

// ---------------- PTX helpers ------------------------------------------------
__device__ __forceinline__ uint32_t smem_u32(const void* p) {
    uint32_t a;
    asm("{ .reg .u64 t; cvta.to.shared.u64 t, %1; cvt.u32.u64 %0, t; }"
        : "=r"(a) : "l"(p));
    return a;
}
#define CP_ASYNC16(dst, src) \
    asm volatile("cp.async.cg.shared.global [%0], [%1], 16;" \
                 :: "r"(dst), "l"(src) : "memory")
#define CP_COMMIT()  asm volatile("cp.async.commit_group;" ::: "memory")

__device__ __forceinline__ void mma_tf32(float& c0, float& c1, float& c2, float& c3,
                                         uint32_t a0, uint32_t a1, uint32_t a2, uint32_t a3,
                                         uint32_t b0, uint32_t b1) {
    asm volatile(
        "mma.sync.aligned.m16n8k8.row.col.f32.tf32.tf32.f32 "
        "{%0,%1,%2,%3}, {%4,%5,%6,%7}, {%8,%9}, {%0,%1,%2,%3};"
        : "+f"(c0), "+f"(c1), "+f"(c2), "+f"(c3)
        : "r"(a0), "r"(a1), "r"(a2), "r"(a3), "r"(b0), "r"(b1));
}

__device__ __forceinline__ float to_tf32(float a) {
    uint32_t b;
    asm("cvt.rna.tf32.f32 %0, %1;" : "=r"(b) : "f"(a));
    return __uint_as_float(b);
}

// ---------------- misc helpers ----------------------------------------------
__device__ __forceinline__ unsigned int f2k(float f) {
    unsigned int u = __float_as_uint(f);
    return (u & 0x80000000u) ? ~u : (u | 0x80000000u);
}
__device__ __forceinline__ float k2f(unsigned int k) {
    unsigned int u = (k & 0x80000000u) ? (k ^ 0x80000000u) : ~k;
    return __uint_as_float(u);
}

// ---------------- SGEMM (fp32, FFMA) for q/k/v projections -------------------
// SPLIT: write tf32 split (hi -> C, lo -> C2) of acc+bias instead of fp32.
template <bool BIAS, bool SPLIT>
__global__ __launch_bounds__(256)
void sgemm128(const float* __restrict__ A, const float* __restrict__ B,
              const float* __restrict__ bias, float* __restrict__ C,
              float* __restrict__ C2,
              int M, int N, int K)
{
    __shared__ float As[8][128];
    __shared__ float Bs[8][128];

    const int tid = threadIdx.x;
    const int bm = blockIdx.y * 128;
    const int bn = blockIdx.x * 128;

    const int a_row = tid >> 1;
    const int a_col = (tid & 1) * 4;
    const int b_row = tid >> 5;
    const int b_col = (tid & 31) * 4;

    const int tx = tid & 15;
    const int ty = tid >> 4;

    float acc[8][8];
#pragma unroll
    for (int i = 0; i < 8; i++)
#pragma unroll
        for (int j = 0; j < 8; j++) acc[i][j] = 0.0f;

    for (int k0 = 0; k0 < K; k0 += 8) {
        float4 av = *reinterpret_cast<const float4*>(
            A + (size_t)(bm + a_row) * K + (k0 + a_col));
        As[a_col + 0][a_row] = av.x;
        As[a_col + 1][a_row] = av.y;
        As[a_col + 2][a_row] = av.z;
        As[a_col + 3][a_row] = av.w;

        float4 bv = *reinterpret_cast<const float4*>(
            B + (size_t)(k0 + b_row) * N + (bn + b_col));
        *reinterpret_cast<float4*>(&Bs[b_row][b_col]) = bv;
        __syncthreads();

#pragma unroll
        for (int kk = 0; kk < 8; kk++) {
            float af[8], bf[8];
            float4 t;
            t = *reinterpret_cast<const float4*>(&As[kk][ty * 8]);
            af[0] = t.x; af[1] = t.y; af[2] = t.z; af[3] = t.w;
            t = *reinterpret_cast<const float4*>(&As[kk][ty * 8 + 4]);
            af[4] = t.x; af[5] = t.y; af[6] = t.z; af[7] = t.w;
            t = *reinterpret_cast<const float4*>(&Bs[kk][tx * 8]);
            bf[0] = t.x; bf[1] = t.y; bf[2] = t.z; bf[3] = t.w;
            t = *reinterpret_cast<const float4*>(&Bs[kk][tx * 8 + 4]);
            bf[4] = t.x; bf[5] = t.y; bf[6] = t.z; bf[7] = t.w;
#pragma unroll
            for (int i = 0; i < 8; i++)
#pragma unroll
                for (int j = 0; j < 8; j++)
                    acc[i][j] += af[i] * bf[j];
        }
        __syncthreads();
    }

#pragma unroll
    for (int i = 0; i < 8; i++) {
        const int row = bm + ty * 8 + i;
        const int col = bn + tx * 8;
#pragma unroll
        for (int j = 0; j < 8; j += 4) {
            float o[4];
#pragma unroll
            for (int t = 0; t < 4; t++) {
                o[t] = acc[i][j + t];
                if (BIAS) o[t] += bias[col + j + t];
            }
            if (SPLIT) {
                float4 h4, l4;
                float* hp = &h4.x;
                float* lp = &l4.x;
#pragma unroll
                for (int t = 0; t < 4; t++) {
                    float h = to_tf32(o[t]);
                    hp[t] = h;
                    lp[t] = to_tf32(o[t] - h);
                }
                *reinterpret_cast<float4*>(C  + (size_t)row * N + col + j) = h4;
                *reinterpret_cast<float4*>(C2 + (size_t)row * N + col + j) = l4;
            } else {
                float4 v4;
                v4.x = o[0]; v4.y = o[1]; v4.z = o[2]; v4.w = o[3];
                *reinterpret_cast<float4*>(C + (size_t)row * N + col + j) = v4;
            }
        }
    }
}

// ---------------- dots = q @ k^T via mma.sync 3xTF32 ------------------------
// CTA tile 128x128, 8 warps (4m x 2n) of 32x64, KC=32 double-buffered cp.async.
__global__ __launch_bounds__(256)
void dots_mma(const float* __restrict__ Ahi, const float* __restrict__ Alo,
              const float* __restrict__ Bhi, const float* __restrict__ Blo,
              float* __restrict__ C)
{
    extern __shared__ __align__(16) float smem[];
    const uint32_t sb = smem_u32(smem);

    const int tid = threadIdx.x;
    const int lane = tid & 31;
    const int wid = tid >> 5;
    const int warpM = wid >> 1;       // 0..3 -> 32 rows each
    const int warpN = wid & 1;        // 0..1 -> 64 cols each
    const int bm = blockIdx.x * MT;   // m fastest -> q tiles stay L2 resident
    const int bn = blockIdx.y * NT;

    const int r = lane >> 2;          // 0..7
    const int c4 = lane & 3;          // 0..3

    float acc[2][8][4];
#pragma unroll
    for (int mt = 0; mt < 2; mt++)
#pragma unroll
        for (int nt = 0; nt < 8; nt++)
#pragma unroll
            for (int i = 0; i < 4; i++) acc[mt][nt][i] = 0.0f;

    const int half = tid >> 7;        // 0: hi plane, 1: lo plane
    const int prow = tid & 127;

    // prefetch K-chunk `it` into stage `s` (16 cp.async16 per thread)
    auto prefetch = [&](int it, int s) {
        const int k0 = it * KC;
        const uint32_t st = sb + (uint32_t)s * ST_BYTES;
        const float* ga = (half ? Alo : Ahi) + (size_t)(bm + prow) * DIM + k0;
        const uint32_t da = st + ((uint32_t)half * A_FLOATS + (uint32_t)prow * LDP) * 4;
        const float* gb = (half ? Blo : Bhi) + (size_t)(bn + prow) * DIM + k0;
        const uint32_t db = st + (2u * A_FLOATS + (uint32_t)half * B_FLOATS
                                  + (uint32_t)prow * LDP) * 4;
#pragma unroll
        for (int c = 0; c < 8; c++) {
            CP_ASYNC16(da + c * 16, ga + c * 4);
            CP_ASYNC16(db + c * 16, gb + c * 4);
        }
        CP_COMMIT();
    };

    prefetch(0, 0);

    int aoff[2], boff[8];
#pragma unroll
    for (int mt = 0; mt < 2; mt++)
        aoff[mt] = (warpM * 32 + mt * 16 + r) * LDP + c4;
#pragma unroll
    for (int nt = 0; nt < 8; nt++)
        boff[nt] = (warpN * 64 + nt * 8 + r) * LDP + c4;

    for (int it = 0; it < KITERS; it++) {
        if (it + 1 < KITERS) {
            prefetch(it + 1, (it + 1) & 1);
            asm volatile("cp.async.wait_group %0;" :: "n"(1));
        } else {
            asm volatile("cp.async.wait_group %0;" :: "n"(0));
        }
        __syncthreads();

        const float* stage = smem + (size_t)(it & 1) * ST_FLOATS;
        const float* Ah = stage;
        const float* Al = stage + A_FLOATS;
        const float* Bh = stage + 2 * A_FLOATS;
        const float* Bl = Bh + B_FLOATS;

#pragma unroll
        for (int ks = 0; ks < 4; ks++) {
            const int kb = ks * 8;
            uint32_t ah[2][4], al[2][4], bh[8][2], bl[8][2];
#pragma unroll
            for (int mt = 0; mt < 2; mt++) {
                const int o = aoff[mt] + kb;
                ah[mt][0] = __float_as_uint(Ah[o]);
                ah[mt][1] = __float_as_uint(Ah[o + 8 * LDP]);
                ah[mt][2] = __float_as_uint(Ah[o + 4]);
                ah[mt][3] = __float_as_uint(Ah[o + 8 * LDP + 4]);
                al[mt][0] = __float_as_uint(Al[o]);
                al[mt][1] = __float_as_uint(Al[o + 8 * LDP]);
                al[mt][2] = __float_as_uint(Al[o + 4]);
                al[mt][3] = __float_as_uint(Al[o + 8 * LDP + 4]);
            }
#pragma unroll
            for (int nt = 0; nt < 8; nt++) {
                const int o = boff[nt] + kb;
                bh[nt][0] = __float_as_uint(Bh[o]);
                bh[nt][1] = __float_as_uint(Bh[o + 4]);
                bl[nt][0] = __float_as_uint(Bl[o]);
                bl[nt][1] = __float_as_uint(Bl[o + 4]);
            }
#pragma unroll
            for (int mt = 0; mt < 2; mt++)
#pragma unroll
                for (int nt = 0; nt < 8; nt++) {
                    float* a = acc[mt][nt];
                    mma_tf32(a[0], a[1], a[2], a[3],
                             ah[mt][0], ah[mt][1], ah[mt][2], ah[mt][3],
                             bh[nt][0], bh[nt][1]);
                    mma_tf32(a[0], a[1], a[2], a[3],
                             al[mt][0], al[mt][1], al[mt][2], al[mt][3],
                             bh[nt][0], bh[nt][1]);
                    mma_tf32(a[0], a[1], a[2], a[3],
                             ah[mt][0], ah[mt][1], ah[mt][2], ah[mt][3],
                             bl[nt][0], bl[nt][1]);
                }
        }
        __syncthreads();
    }

    // epilogue: c0,c1 at (row, 2c4), (row, 2c4+1); c2,c3 at row+8
#pragma unroll
    for (int mt = 0; mt < 2; mt++) {
        const int row = bm + warpM * 32 + mt * 16 + r;
#pragma unroll
        for (int nt = 0; nt < 8; nt++) {
            const int col = bn + warpN * 64 + nt * 8 + 2 * c4;
            float2 v0; v0.x = acc[mt][nt][0]; v0.y = acc[mt][nt][1];
            float2 v1; v1.x = acc[mt][nt][2]; v1.y = acc[mt][nt][3];
            *reinterpret_cast<float2*>(C + (size_t)row * VOC + col) = v0;
            *reinterpret_cast<float2*>(C + (size_t)(row + 8) * VOC + col) = v1;
        }
    }
}

// ---------------- per-row top-k threshold + softmax + sparse A@V ------------
__global__ __launch_bounds__(256)
void topk_softmax_gather(const float* __restrict__ dots,
                         const float* __restrict__ v,
                         float* __restrict__ out)
{
    extern __shared__ unsigned int keys[];            // VOC entries = 128KB
    __shared__ unsigned int hist[256];
    __shared__ unsigned int scanbuf[2][256];
    __shared__ unsigned int u_red[256];
    __shared__ float        f_red[256];
    __shared__ int   sel_idx[MAXSEL];
    __shared__ float sel_w[MAXSEL];
    __shared__ unsigned int s_prefix;
    __shared__ int s_r;

    const int tid = threadIdx.x;
    const int row = blockIdx.x;
    const float* drow = dots + (size_t)row * VOC;

    unsigned int kmax = 0;
    for (int i = tid; i < VOC; i += 256) {
        unsigned int k = f2k(drow[i]);
        keys[i] = k;
        kmax = max(kmax, k);
    }
    u_red[tid] = kmax;
    __syncthreads();
#pragma unroll
    for (int s = 128; s > 0; s >>= 1) {
        if (tid < s) u_red[tid] = max(u_red[tid], u_red[tid + s]);
        __syncthreads();
    }
    const float mval = k2f(u_red[0]);

    unsigned int prefix = 0, prefmask = 0;
    int r = TOPK;
    for (int pass = 0; pass < 4; pass++) {
        const int shift = 24 - 8 * pass;
        hist[tid] = 0;
        __syncthreads();
        for (int i = tid; i < VOC; i += 256) {
            unsigned int k = keys[i];
            if ((k & prefmask) == prefix)
                atomicAdd(&hist[(k >> shift) & 255u], 1u);
        }
        __syncthreads();
        scanbuf[0][tid] = hist[tid];
        __syncthreads();
        int src = 0;
        for (int off = 1; off < 256; off <<= 1) {
            unsigned int val = scanbuf[src][tid];
            if (tid + off < 256) val += scanbuf[src][tid + off];
            scanbuf[src ^ 1][tid] = val;
            __syncthreads();
            src ^= 1;
        }
        const unsigned int cumb  = scanbuf[src][tid];
        const unsigned int cumb1 = (tid == 255) ? 0u : scanbuf[src][tid + 1];
        if (cumb >= (unsigned int)r && cumb1 < (unsigned int)r) {
            s_prefix = prefix | ((unsigned int)tid << shift);
            s_r = r - (int)cumb1;
        }
        __syncthreads();
        prefix = s_prefix;
        r = s_r;
        prefmask |= 0xFFu << shift;
        __syncthreads();
    }
    const unsigned int thresh = prefix;

    int c = 0;
    for (int i = tid; i < VOC; i += 256)
        if (keys[i] >= thresh) c++;
    scanbuf[0][tid] = (unsigned int)c;
    __syncthreads();
    int src = 0;
    for (int off = 1; off < 256; off <<= 1) {
        unsigned int val = scanbuf[src][tid];
        if (tid >= off) val += scanbuf[src][tid - off];
        scanbuf[src ^ 1][tid] = val;
        __syncthreads();
        src ^= 1;
    }
    int pos = (tid == 0) ? 0 : (int)scanbuf[src][tid - 1];
    const int total = (int)scanbuf[src][255];

    float lsum = 0.0f;
    for (int i = tid; i < VOC; i += 256) {
        unsigned int k = keys[i];
        if (k >= thresh) {
            float w = expf(k2f(k) - mval);
            if (pos < MAXSEL) { sel_idx[pos] = i; sel_w[pos] = w; }
            lsum += w;
            pos++;
        }
    }
    f_red[tid] = lsum;
    __syncthreads();
#pragma unroll
    for (int s = 128; s > 0; s >>= 1) {
        if (tid < s) f_red[tid] += f_red[tid + s];
        __syncthreads();
    }
    const float Z = f_red[0];
    const int count = min(total, MAXSEL);

    float acc0 = 0.0f, acc1 = 0.0f;
    const int d0 = tid * 2;
    for (int s = 0; s < count; s++) {
        const float w = sel_w[s];
        const float2 vv = *reinterpret_cast<const float2*>(
            v + (size_t)sel_idx[s] * DIM + d0);
        acc0 += w * vv.x;
        acc1 += w * vv.y;
    }
    const float inv = 1.0f / Z;
    float2 o;
    o.x = acc0 * inv;
    o.y = acc1 * inv;
    *reinterpret_cast<float2*>(out + (size_t)row * DIM + d0) = o;
}

// ---------------- launch ----------------------------------------------------
extern "C" void kernel_launch(void* const* d_in, const int* in_sizes, int n_in,
                              void* d_out, int out_size)
{
    const float* x  = (const float*)d_in[0];
    const float* cb = (const float*)d_in[1];
    const float* Wq = (const float*)d_in[2];
    const float* bq = (const float*)d_in[3];
    const float* Wk = (const float*)d_in[4];
    const float* bk = (const float*)d_in[5];
    const float* Wv = (const float*)d_in[6];
    const float* bv = (const float*)d_in[7];
    float* out = (float*)d_out;

    float *v, *qh, *ql, *kh, *kl, *dots;
    cudaGetSymbolAddress((void**)&v,    g_v);
    cudaGetSymbolAddress((void**)&qh,   g_qh);
    cudaGetSymbolAddress((void**)&ql,   g_ql);
    cudaGetSymbolAddress((void**)&kh,   g_kh);
    cudaGetSymbolAddress((void**)&kl,   g_kl);
    cudaGetSymbolAddress((void**)&dots, g_dots);

    cudaFuncSetAttribute(topk_softmax_gather,
                         cudaFuncAttributeMaxDynamicSharedMemorySize,
                         VOC * (int)sizeof(unsigned int));
    cudaFuncSetAttribute(dots_mma,
                         cudaFuncAttributeMaxDynamicSharedMemorySize,
                         2 * ST_BYTES);

    dim3 blk(256);

    // projections: q,k fused with tf32 split; v plain fp32
    sgemm128<true, true><<<dim3(DIM / 128, BATCH / 128), blk>>>(
        x, Wq, bq, qh, ql, BATCH, DIM, DIM);
    sgemm128<true, true><<<dim3(DIM / 128, VOC / 128), blk>>>(
        cb, Wk, bk, kh, kl, VOC, DIM, DIM);
    sgemm128<true, false><<<dim3(DIM / 128, VOC / 128), blk>>>(
        cb, Wv, bv, v, nullptr, VOC, DIM, DIM);

    // dots = q @ k^T via mma.sync 3xTF32
    dots_mma<<<dim3(BATCH / MT, VOC / NT), blk, 2 * ST_BYTES>>>(
        qh, ql, kh, kl, dots);

    // per-row top-64 threshold + softmax + sparse gather of v
    topk_softmax_gather<<<BATCH, blk, VOC * (int)sizeof(unsigned int)>>>(
        dots, v, out);
}

// round 5
// speedup vs baseline: 1.0859x; 1.0859x over previous
#include <cuda_runtime.h>
#include <cstdint>

#define VOC   32768
#define DIM   512
#define BATCH 4096
#define TOPK  64
#define MAXSEL 128

// dots tile config (mma.sync tf32): CTA 128x128, 8 warps of 32x64
#define MT 128
#define NT 128
#define KC 16
#define KITERS (DIM / KC)        // 32
#define LDP 20                   // padded floats per smem row (KC + 4)
#define A_FLOATS (MT * LDP)      // 2560
#define B_FLOATS (NT * LDP)      // 2560
#define ST_FLOATS (2 * A_FLOATS + 2 * B_FLOATS)   // 10240
#define ST_BYTES  (ST_FLOATS * 4)                 // 40960

// ---------------- scratch (static device globals; no allocation allowed) ----
__device__ float g_v [(size_t)VOC * DIM];
__device__ float g_qh[(size_t)BATCH * DIM];
__device__ float g_ql[(size_t)BATCH * DIM];
__device__ float g_kh[(size_t)VOC * DIM];
__device__ float g_kl[(size_t)VOC * DIM];
__device__ float g_dots[(size_t)BATCH * VOC];   // 512 MB

// ---------------- PTX helpers ------------------------------------------------
__device__ __forceinline__ uint32_t smem_u32(const void* p) {
    uint32_t a;
    asm("{ .reg .u64 t; cvta.to.shared.u64 t, %1; cvt.u32.u64 %0, t; }"
        : "=r"(a) : "l"(p));
    return a;
}
#define CP_ASYNC16(dst, src) \
    asm volatile("cp.async.cg.shared.global [%0], [%1], 16;" \
                 :: "r"(dst), "l"(src) : "memory")
#define CP_COMMIT()  asm volatile("cp.async.commit_group;" ::: "memory")

__device__ __forceinline__ void mma_tf32(float& c0, float& c1, float& c2, float& c3,
                                         uint32_t a0, uint32_t a1, uint32_t a2, uint32_t a3,
                                         uint32_t b0, uint32_t b1) {
    asm volatile(
        "mma.sync.aligned.m16n8k8.row.col.f32.tf32.tf32.f32 "
        "{%0,%1,%2,%3}, {%4,%5,%6,%7}, {%8,%9}, {%0,%1,%2,%3};"
        : "+f"(c0), "+f"(c1), "+f"(c2), "+f"(c3)
        : "r"(a0), "r"(a1), "r"(a2), "r"(a3), "r"(b0), "r"(b1));
}

__device__ __forceinline__ float to_tf32(float a) {
    uint32_t b;
    asm("cvt.rna.tf32.f32 %0, %1;" : "=r"(b) : "f"(a));
    return __uint_as_float(b);
}

// ---------------- misc helpers ----------------------------------------------
__device__ __forceinline__ unsigned int f2k(float f) {
    unsigned int u = __float_as_uint(f);
    return (u & 0x80000000u) ? ~u : (u | 0x80000000u);
}
__device__ __forceinline__ float k2f(unsigned int k) {
    unsigned int u = (k & 0x80000000u) ? (k ^ 0x80000000u) : ~k;
    return __uint_as_float(u);
}

// ---------------- SGEMM (fp32, FFMA) for q/k/v projections -------------------
// SPLIT: write tf32 split (hi -> C, lo -> C2) of acc+bias instead of fp32.
template <bool BIAS, bool SPLIT>
__global__ __launch_bounds__(256)
void sgemm128(const float* __restrict__ A, const float* __restrict__ B,
              const float* __restrict__ bias, float* __restrict__ C,
              float* __restrict__ C2,
              int M, int N, int K)
{
    __shared__ float As[8][128];
    __shared__ float Bs[8][128];

    const int tid = threadIdx.x;
    const int bm = blockIdx.y * 128;
    const int bn = blockIdx.x * 128;

    const int a_row = tid >> 1;
    const int a_col = (tid & 1) * 4;
    const int b_row = tid >> 5;
    const int b_col = (tid & 31) * 4;

    const int tx = tid & 15;
    const int ty = tid >> 4;

    float acc[8][8];
#pragma unroll
    for (int i = 0; i < 8; i++)
#pragma unroll
        for (int j = 0; j < 8; j++) acc[i][j] = 0.0f;

    for (int k0 = 0; k0 < K; k0 += 8) {
        float4 av = *reinterpret_cast<const float4*>(
            A + (size_t)(bm + a_row) * K + (k0 + a_col));
        As[a_col + 0][a_row] = av.x;
        As[a_col + 1][a_row] = av.y;
        As[a_col + 2][a_row] = av.z;
        As[a_col + 3][a_row] = av.w;

        float4 bv = *reinterpret_cast<const float4*>(
            B + (size_t)(k0 + b_row) * N + (bn + b_col));
        *reinterpret_cast<float4*>(&Bs[b_row][b_col]) = bv;
        __syncthreads();

#pragma unroll
        for (int kk = 0; kk < 8; kk++) {
            float af[8], bf[8];
            float4 t;
            t = *reinterpret_cast<const float4*>(&As[kk][ty * 8]);
            af[0] = t.x; af[1] = t.y; af[2] = t.z; af[3] = t.w;
            t = *reinterpret_cast<const float4*>(&As[kk][ty * 8 + 4]);
            af[4] = t.x; af[5] = t.y; af[6] = t.z; af[7] = t.w;
            t = *reinterpret_cast<const float4*>(&Bs[kk][tx * 8]);
            bf[0] = t.x; bf[1] = t.y; bf[2] = t.z; bf[3] = t.w;
            t = *reinterpret_cast<const float4*>(&Bs[kk][tx * 8 + 4]);
            bf[4] = t.x; bf[5] = t.y; bf[6] = t.z; bf[7] = t.w;
#pragma unroll
            for (int i = 0; i < 8; i++)
#pragma unroll
                for (int j = 0; j < 8; j++)
                    acc[i][j] += af[i] * bf[j];
        }
        __syncthreads();
    }

#pragma unroll
    for (int i = 0; i < 8; i++) {
        const int row = bm + ty * 8 + i;
        const int col = bn + tx * 8;
#pragma unroll
        for (int j = 0; j < 8; j += 4) {
            float o[4];
#pragma unroll
            for (int t = 0; t < 4; t++) {
                o[t] = acc[i][j + t];
                if (BIAS) o[t] += bias[col + j + t];
            }
            if (SPLIT) {
                float4 h4, l4;
                float* hp = &h4.x;
                float* lp = &l4.x;
#pragma unroll
                for (int t = 0; t < 4; t++) {
                    float h = to_tf32(o[t]);
                    hp[t] = h;
                    lp[t] = to_tf32(o[t] - h);
                }
                *reinterpret_cast<float4*>(C  + (size_t)row * N + col + j) = h4;
                *reinterpret_cast<float4*>(C2 + (size_t)row * N + col + j) = l4;
            } else {
                float4 v4;
                v4.x = o[0]; v4.y = o[1]; v4.z = o[2]; v4.w = o[3];
                *reinterpret_cast<float4*>(C + (size_t)row * N + col + j) = v4;
            }
        }
    }
}

// ---------------- dots = q @ k^T via mma.sync 3xTF32 ------------------------
// CTA tile 128x128, 8 warps (4m x 2n) of 32x64, KC=16 double-buffered cp.async.
// 2 CTAs/SM (80KB smem each) to overlap LDS/MMA across barriers.
__global__ __launch_bounds__(256, 2)
void dots_mma(const float* __restrict__ Ahi, const float* __restrict__ Alo,
              const float* __restrict__ Bhi, const float* __restrict__ Blo,
              float* __restrict__ C)
{
    extern __shared__ __align__(16) float smem[];
    const uint32_t sb = smem_u32(smem);

    const int tid = threadIdx.x;
    const int lane = tid & 31;
    const int wid = tid >> 5;
    const int warpM = wid >> 1;       // 0..3 -> 32 rows each
    const int warpN = wid & 1;        // 0..1 -> 64 cols each
    const int bm = blockIdx.x * MT;   // m fastest -> q tiles stay L2 resident
    const int bn = blockIdx.y * NT;

    const int r = lane >> 2;          // 0..7
    const int c4 = lane & 3;          // 0..3

    float acc[2][8][4];
#pragma unroll
    for (int mt = 0; mt < 2; mt++)
#pragma unroll
        for (int nt = 0; nt < 8; nt++)
#pragma unroll
            for (int i = 0; i < 4; i++) acc[mt][nt][i] = 0.0f;

    const int half = tid >> 7;        // 0: hi plane, 1: lo plane
    const int prow = tid & 127;

    // prefetch K-chunk `it` into stage `s` (8 cp.async16 per thread)
    auto prefetch = [&](int it, int s) {
        const int k0 = it * KC;
        const uint32_t st = sb + (uint32_t)s * ST_BYTES;
        const float* ga = (half ? Alo : Ahi) + (size_t)(bm + prow) * DIM + k0;
        const uint32_t da = st + ((uint32_t)half * A_FLOATS + (uint32_t)prow * LDP) * 4;
        const float* gb = (half ? Blo : Bhi) + (size_t)(bn + prow) * DIM + k0;
        const uint32_t db = st + (2u * A_FLOATS + (uint32_t)half * B_FLOATS
                                  + (uint32_t)prow * LDP) * 4;
#pragma unroll
        for (int c = 0; c < 4; c++) {
            CP_ASYNC16(da + c * 16, ga + c * 4);
            CP_ASYNC16(db + c * 16, gb + c * 4);
        }
        CP_COMMIT();
    };

    prefetch(0, 0);

    int aoff[2], boff[8];
#pragma unroll
    for (int mt = 0; mt < 2; mt++)
        aoff[mt] = (warpM * 32 + mt * 16 + r) * LDP + c4;
#pragma unroll
    for (int nt = 0; nt < 8; nt++)
        boff[nt] = (warpN * 64 + nt * 8 + r) * LDP + c4;

    for (int it = 0; it < KITERS; it++) {
        if (it + 1 < KITERS) {
            prefetch(it + 1, (it + 1) & 1);
            asm volatile("cp.async.wait_group %0;" :: "n"(1));
        } else {
            asm volatile("cp.async.wait_group %0;" :: "n"(0));
        }
        __syncthreads();

        const float* stage = smem + (size_t)(it & 1) * ST_FLOATS;
        const float* Ah = stage;
        const float* Al = stage + A_FLOATS;
        const float* Bh = stage + 2 * A_FLOATS;
        const float* Bl = Bh + B_FLOATS;

#pragma unroll
        for (int ks = 0; ks < 2; ks++) {
            const int kb = ks * 8;
            uint32_t ah[2][4], al[2][4], bh[8][2], bl[8][2];
#pragma unroll
            for (int mt = 0; mt < 2; mt++) {
                const int o = aoff[mt] + kb;
                ah[mt][0] = __float_as_uint(Ah[o]);
                ah[mt][1] = __float_as_uint(Ah[o + 8 * LDP]);
                ah[mt][2] = __float_as_uint(Ah[o + 4]);
                ah[mt][3] = __float_as_uint(Ah[o + 8 * LDP + 4]);
                al[mt][0] = __float_as_uint(Al[o]);
                al[mt][1] = __float_as_uint(Al[o + 8 * LDP]);
                al[mt][2] = __float_as_uint(Al[o + 4]);
                al[mt][3] = __float_as_uint(Al[o + 8 * LDP + 4]);
            }
#pragma unroll
            for (int nt = 0; nt < 8; nt++) {
                const int o = boff[nt] + kb;
                bh[nt][0] = __float_as_uint(Bh[o]);
                bh[nt][1] = __float_as_uint(Bh[o + 4]);
                bl[nt][0] = __float_as_uint(Bl[o]);
                bl[nt][1] = __float_as_uint(Bl[o + 4]);
            }
#pragma unroll
            for (int mt = 0; mt < 2; mt++)
#pragma unroll
                for (int nt = 0; nt < 8; nt++) {
                    float* a = acc[mt][nt];
                    mma_tf32(a[0], a[1], a[2], a[3],
                             ah[mt][0], ah[mt][1], ah[mt][2], ah[mt][3],
                             bh[nt][0], bh[nt][1]);
                    mma_tf32(a[0], a[1], a[2], a[3],
                             al[mt][0], al[mt][1], al[mt][2], al[mt][3],
                             bh[nt][0], bh[nt][1]);
                    mma_tf32(a[0], a[1], a[2], a[3],
                             ah[mt][0], ah[mt][1], ah[mt][2], ah[mt][3],
                             bl[nt][0], bl[nt][1]);
                }
        }
        __syncthreads();
    }

    // epilogue: c0,c1 at (row, 2c4), (row, 2c4+1); c2,c3 at row+8
#pragma unroll
    for (int mt = 0; mt < 2; mt++) {
        const int row = bm + warpM * 32 + mt * 16 + r;
#pragma unroll
        for (int nt = 0; nt < 8; nt++) {
            const int col = bn + warpN * 64 + nt * 8 + 2 * c4;
            float2 v0; v0.x = acc[mt][nt][0]; v0.y = acc[mt][nt][1];
            float2 v1; v1.x = acc[mt][nt][2]; v1.y = acc[mt][nt][3];
            *reinterpret_cast<float2*>(C + (size_t)row * VOC + col) = v0;
            *reinterpret_cast<float2*>(C + (size_t)(row + 8) * VOC + col) = v1;
        }
    }
}

// ---------------- per-row top-k threshold + softmax + sparse A@V ------------
__global__ __launch_bounds__(256)
void topk_softmax_gather(const float* __restrict__ dots,
                         const float* __restrict__ v,
                         float* __restrict__ out)
{
    extern __shared__ unsigned int keys[];            // VOC entries = 128KB
    __shared__ unsigned int hist[256];
    __shared__ unsigned int scanbuf[2][256];
    __shared__ unsigned int u_red[256];
    __shared__ float        f_red[256];
    __shared__ int   sel_idx[MAXSEL];
    __shared__ float sel_w[MAXSEL];
    __shared__ unsigned int s_prefix;
    __shared__ int s_r;

    const int tid = threadIdx.x;
    const int row = blockIdx.x;
    const float* drow = dots + (size_t)row * VOC;

    unsigned int kmax = 0;
    for (int i = tid; i < VOC; i += 256) {
        unsigned int k = f2k(drow[i]);
        keys[i] = k;
        kmax = max(kmax, k);
    }
    u_red[tid] = kmax;
    __syncthreads();
#pragma unroll
    for (int s = 128; s > 0; s >>= 1) {
        if (tid < s) u_red[tid] = max(u_red[tid], u_red[tid + s]);
        __syncthreads();
    }
    const float mval = k2f(u_red[0]);

    unsigned int prefix = 0, prefmask = 0;
    int r = TOPK;
    for (int pass = 0; pass < 4; pass++) {
        const int shift = 24 - 8 * pass;
        hist[tid] = 0;
        __syncthreads();
        for (int i = tid; i < VOC; i += 256) {
            unsigned int k = keys[i];
            if ((k & prefmask) == prefix)
                atomicAdd(&hist[(k >> shift) & 255u], 1u);
        }
        __syncthreads();
        scanbuf[0][tid] = hist[tid];
        __syncthreads();
        int src = 0;
        for (int off = 1; off < 256; off <<= 1) {
            unsigned int val = scanbuf[src][tid];
            if (tid + off < 256) val += scanbuf[src][tid + off];
            scanbuf[src ^ 1][tid] = val;
            __syncthreads();
            src ^= 1;
        }
        const unsigned int cumb  = scanbuf[src][tid];
        const unsigned int cumb1 = (tid == 255) ? 0u : scanbuf[src][tid + 1];
        if (cumb >= (unsigned int)r && cumb1 < (unsigned int)r) {
            s_prefix = prefix | ((unsigned int)tid << shift);
            s_r = r - (int)cumb1;
        }
        __syncthreads();
        prefix = s_prefix;
        r = s_r;
        prefmask |= 0xFFu << shift;
        __syncthreads();
    }
    const unsigned int thresh = prefix;

    int c = 0;
    for (int i = tid; i < VOC; i += 256)
        if (keys[i] >= thresh) c++;
    scanbuf[0][tid] = (unsigned int)c;
    __syncthreads();
    int src = 0;
    for (int off = 1; off < 256; off <<= 1) {
        unsigned int val = scanbuf[src][tid];
        if (tid >= off) val += scanbuf[src][tid - off];
        scanbuf[src ^ 1][tid] = val;
        __syncthreads();
        src ^= 1;
    }
    int pos = (tid == 0) ? 0 : (int)scanbuf[src][tid - 1];
    const int total = (int)scanbuf[src][255];

    float lsum = 0.0f;
    for (int i = tid; i < VOC; i += 256) {
        unsigned int k = keys[i];
        if (k >= thresh) {
            float w = expf(k2f(k) - mval);
            if (pos < MAXSEL) { sel_idx[pos] = i; sel_w[pos] = w; }
            lsum += w;
            pos++;
        }
    }
    f_red[tid] = lsum;
    __syncthreads();
#pragma unroll
    for (int s = 128; s > 0; s >>= 1) {
        if (tid < s) f_red[tid] += f_red[tid + s];
        __syncthreads();
    }
    const float Z = f_red[0];
    const int count = min(total, MAXSEL);

    float acc0 = 0.0f, acc1 = 0.0f;
    const int d0 = tid * 2;
    for (int s = 0; s < count; s++) {
        const float w = sel_w[s];
        const float2 vv = *reinterpret_cast<const float2*>(
            v + (size_t)sel_idx[s] * DIM + d0);
        acc0 += w * vv.x;
        acc1 += w * vv.y;
    }
    const float inv = 1.0f / Z;
    float2 o;
    o.x = acc0 * inv;
    o.y = acc1 * inv;
    *reinterpret_cast<float2*>(out + (size_t)row * DIM + d0) = o;
}

// ---------------- launch ----------------------------------------------------
extern "C" void kernel_launch(void* const* d_in, const int* in_sizes, int n_in,
                              void* d_out, int out_size)
{
    const float* x  = (const float*)d_in[0];
    const float* cb = (const float*)d_in[1];
    const float* Wq = (const float*)d_in[2];
    const float* bq = (const float*)d_in[3];
    const float* Wk = (const float*)d_in[4];
    const float* bk = (const float*)d_in[5];
    const float* Wv = (const float*)d_in[6];
    const float* bv = (const float*)d_in[7];
    float* out = (float*)d_out;

    float *v, *qh, *ql, *kh, *kl, *dots;
    cudaGetSymbolAddress((void**)&v,    g_v);
    cudaGetSymbolAddress((void**)&qh,   g_qh);
    cudaGetSymbolAddress((void**)&ql,   g_ql);
    cudaGetSymbolAddress((void**)&kh,   g_kh);
    cudaGetSymbolAddress((void**)&kl,   g_kl);
    cudaGetSymbolAddress((void**)&dots, g_dots);

    cudaFuncSetAttribute(topk_softmax_gather,
                         cudaFuncAttributeMaxDynamicSharedMemorySize,
                         VOC * (int)sizeof(unsigned int));
    cudaFuncSetAttribute(dots_mma,
                         cudaFuncAttributeMaxDynamicSharedMemorySize,
                         2 * ST_BYTES);

    dim3 blk(256);

    // projections: q,k fused with tf32 split; v plain fp32
    sgemm128<true, true><<<dim3(DIM / 128, BATCH / 128), blk>>>(
        x, Wq, bq, qh, ql, BATCH, DIM, DIM);
    sgemm128<true, true><<<dim3(DIM / 128, VOC / 128), blk>>>(
        cb, Wk, bk, kh, kl, VOC, DIM, DIM);
    sgemm128<true, false><<<dim3(DIM / 128, VOC / 128), blk>>>(
        cb, Wv, bv, v, nullptr, VOC, DIM, DIM);

    // dots = q @ k^T via mma.sync 3xTF32 (2 CTAs/SM)
    dots_mma<<<dim3(BATCH / MT, VOC / NT), blk, 2 * ST_BYTES>>>(
        qh, ql, kh, kl, dots);

    // per-row top-64 threshold + softmax + sparse gather of v
    topk_softmax_gather<<<BATCH, blk, VOC * (int)sizeof(unsigned int)>>>(
        dots, v, out);
}

// round 7
// speedup vs baseline: 1.3987x; 1.2880x over previous
#include <cuda_runtime.h>
#include <cstdint>

#define VOC   32768
#define DIM   512
#define BATCH 4096
#define TOPK  64
#define MAXSEL 128
#define MARGIN 0.008f

// dots tile config (mma.sync tf32 single-pass): CTA 128x128, 8 warps of 32x64
#define MT 128
#define NT 128
#define KC 16
#define KITERS (DIM / KC)        // 32
#define LDP 20                   // padded floats per smem row (KC + 4)
#define A_FLOATS (MT * LDP)      // 2560
#define B_FLOATS (NT * LDP)      // 2560
#define ST_FLOATS (A_FLOATS + B_FLOATS)          // 5120
#define ST_BYTES  (ST_FLOATS * 4)                // 20480
#define NSTAGE 3

// ---------------- scratch (static device globals; no allocation allowed) ----
__device__ float g_v [(size_t)VOC * DIM];
__device__ float g_qh[(size_t)BATCH * DIM];
__device__ float g_ql[(size_t)BATCH * DIM];
__device__ float g_kh[(size_t)VOC * DIM];
__device__ float g_kl[(size_t)VOC * DIM];
__device__ float g_dots[(size_t)BATCH * VOC];   // 512 MB (approx)

// ---------------- PTX helpers ------------------------------------------------
__device__ __forceinline__ uint32_t smem_u32(const void* p) {
    uint32_t a;
    asm("{ .reg .u64 t; cvta.to.shared.u64 t, %1; cvt.u32.u64 %0, t; }"
        : "=r"(a) : "l"(p));
    return a;
}
#define CP_ASYNC16(dst, src) \
    asm volatile("cp.async.cg.shared.global [%0], [%1], 16;" \
                 :: "r"(dst), "l"(src) : "memory")
#define CP_COMMIT()  asm volatile("cp.async.commit_group;" ::: "memory")

__device__ __forceinline__ void mma_tf32(float& c0, float& c1, float& c2, float& c3,
                                         uint32_t a0, uint32_t a1, uint32_t a2, uint32_t a3,
                                         uint32_t b0, uint32_t b1) {
    asm volatile(
        "mma.sync.aligned.m16n8k8.row.col.f32.tf32.tf32.f32 "
        "{%0,%1,%2,%3}, {%4,%5,%6,%7}, {%8,%9}, {%0,%1,%2,%3};"
        : "+f"(c0), "+f"(c1), "+f"(c2), "+f"(c3)
        : "r"(a0), "r"(a1), "r"(a2), "r"(a3), "r"(b0), "r"(b1));
}

__device__ __forceinline__ float to_tf32(float a) {
    uint32_t b;
    asm("cvt.rna.tf32.f32 %0, %1;" : "=r"(b) : "f"(a));
    return __uint_as_float(b);
}

// ---------------- misc helpers ----------------------------------------------
__device__ __forceinline__ unsigned int f2k(float f) {
    unsigned int u = __float_as_uint(f);
    return (u & 0x80000000u) ? ~u : (u | 0x80000000u);
}
__device__ __forceinline__ float k2f(unsigned int k) {
    unsigned int u = (k & 0x80000000u) ? (k ^ 0x80000000u) : ~k;
    return __uint_as_float(u);
}

// ---------------- SGEMM (fp32, FFMA) for q/k/v projections -------------------
// SPLIT: write tf32 split (hi -> C, lo -> C2) of acc+bias instead of fp32.
template <bool BIAS, bool SPLIT>
__global__ __launch_bounds__(256)
void sgemm128(const float* __restrict__ A, const float* __restrict__ B,
              const float* __restrict__ bias, float* __restrict__ C,
              float* __restrict__ C2,
              int M, int N, int K)
{
    __shared__ float As[8][128];
    __shared__ float Bs[8][128];

    const int tid = threadIdx.x;
    const int bm = blockIdx.y * 128;
    const int bn = blockIdx.x * 128;

    const int a_row = tid >> 1;
    const int a_col = (tid & 1) * 4;
    const int b_row = tid >> 5;
    const int b_col = (tid & 31) * 4;

    const int tx = tid & 15;
    const int ty = tid >> 4;

    float acc[8][8];
#pragma unroll
    for (int i = 0; i < 8; i++)
#pragma unroll
        for (int j = 0; j < 8; j++) acc[i][j] = 0.0f;

    for (int k0 = 0; k0 < K; k0 += 8) {
        float4 av = *reinterpret_cast<const float4*>(
            A + (size_t)(bm + a_row) * K + (k0 + a_col));
        As[a_col + 0][a_row] = av.x;
        As[a_col + 1][a_row] = av.y;
        As[a_col + 2][a_row] = av.z;
        As[a_col + 3][a_row] = av.w;

        float4 bv = *reinterpret_cast<const float4*>(
            B + (size_t)(k0 + b_row) * N + (bn + b_col));
        *reinterpret_cast<float4*>(&Bs[b_row][b_col]) = bv;
        __syncthreads();

#pragma unroll
        for (int kk = 0; kk < 8; kk++) {
            float af[8], bf[8];
            float4 t;
            t = *reinterpret_cast<const float4*>(&As[kk][ty * 8]);
            af[0] = t.x; af[1] = t.y; af[2] = t.z; af[3] = t.w;
            t = *reinterpret_cast<const float4*>(&As[kk][ty * 8 + 4]);
            af[4] = t.x; af[5] = t.y; af[6] = t.z; af[7] = t.w;
            t = *reinterpret_cast<const float4*>(&Bs[kk][tx * 8]);
            bf[0] = t.x; bf[1] = t.y; bf[2] = t.z; bf[3] = t.w;
            t = *reinterpret_cast<const float4*>(&Bs[kk][tx * 8 + 4]);
            bf[4] = t.x; bf[5] = t.y; bf[6] = t.z; bf[7] = t.w;
#pragma unroll
            for (int i = 0; i < 8; i++)
#pragma unroll
                for (int j = 0; j < 8; j++)
                    acc[i][j] += af[i] * bf[j];
        }
        __syncthreads();
    }

#pragma unroll
    for (int i = 0; i < 8; i++) {
        const int row = bm + ty * 8 + i;
        const int col = bn + tx * 8;
#pragma unroll
        for (int j = 0; j < 8; j += 4) {
            float o[4];
#pragma unroll
            for (int t = 0; t < 4; t++) {
                o[t] = acc[i][j + t];
                if (BIAS) o[t] += bias[col + j + t];
            }
            if (SPLIT) {
                float4 h4, l4;
                float* hp = &h4.x;
                float* lp = &l4.x;
#pragma unroll
                for (int t = 0; t < 4; t++) {
                    float h = to_tf32(o[t]);
                    hp[t] = h;
                    lp[t] = to_tf32(o[t] - h);
                }
                *reinterpret_cast<float4*>(C  + (size_t)row * N + col + j) = h4;
                *reinterpret_cast<float4*>(C2 + (size_t)row * N + col + j) = l4;
            } else {
                float4 v4;
                v4.x = o[0]; v4.y = o[1]; v4.z = o[2]; v4.w = o[3];
                *reinterpret_cast<float4*>(C + (size_t)row * N + col + j) = v4;
            }
        }
    }
}

// ---------------- dots_approx = qh @ kh^T via single-pass tf32 mma ----------
// CTA 128x128, 8 warps (4m x 2n) of 32x64, KC=16, 3-stage cp.async pipeline.
__global__ __launch_bounds__(256, 2)
void dots_mma(const float* __restrict__ Ahi, const float* __restrict__ Bhi,
              float* __restrict__ C)
{
    extern __shared__ __align__(16) float smem[];
    const uint32_t sb = smem_u32(smem);

    const int tid = threadIdx.x;
    const int lane = tid & 31;
    const int wid = tid >> 5;
    const int warpM = wid >> 1;       // 0..3 -> 32 rows each
    const int warpN = wid & 1;        // 0..1 -> 64 cols each
    const int bm = blockIdx.x * MT;   // m fastest -> q tiles stay L2 resident
    const int bn = blockIdx.y * NT;

    const int r = lane >> 2;          // 0..7
    const int c4 = lane & 3;          // 0..3

    float acc[2][8][4];
#pragma unroll
    for (int mt = 0; mt < 2; mt++)
#pragma unroll
        for (int nt = 0; nt < 8; nt++)
#pragma unroll
            for (int i = 0; i < 4; i++) acc[mt][nt][i] = 0.0f;

    const int isB = tid >> 7;         // 0: A row, 1: B row
    const int prow = tid & 127;
    const float* gbase = (isB ? Bhi + (size_t)(bn + prow) * DIM
                              : Ahi + (size_t)(bm + prow) * DIM);
    const uint32_t dbase = sb + ((isB ? A_FLOATS : 0) + (uint32_t)prow * LDP) * 4;

    // prefetch K-chunk `it` into stage `s` (4 cp.async16 per thread)
    auto prefetch = [&](int it, int s) {
        const float* g = gbase + it * KC;
        const uint32_t d = dbase + (uint32_t)s * ST_BYTES;
#pragma unroll
        for (int c = 0; c < 4; c++)
            CP_ASYNC16(d + c * 16, g + c * 4);
        CP_COMMIT();
    };

    prefetch(0, 0);
    prefetch(1, 1);

    int aoff[2], boff[8];
#pragma unroll
    for (int mt = 0; mt < 2; mt++)
        aoff[mt] = (warpM * 32 + mt * 16 + r) * LDP + c4;
#pragma unroll
    for (int nt = 0; nt < 8; nt++)
        boff[nt] = A_FLOATS + (warpN * 64 + nt * 8 + r) * LDP + c4;

    int stage = 0;
    for (int it = 0; it < KITERS; it++) {
        if (it + 1 < KITERS)
            asm volatile("cp.async.wait_group %0;" :: "n"(1));
        else
            asm volatile("cp.async.wait_group %0;" :: "n"(0));
        __syncthreads();

        if (it + 2 < KITERS) {
            int ps = stage + 2; if (ps >= NSTAGE) ps -= NSTAGE;
            prefetch(it + 2, ps);
        }

        const float* st = smem + (size_t)stage * ST_FLOATS;

#pragma unroll
        for (int ks = 0; ks < 2; ks++) {
            const int kb = ks * 8;
            uint32_t ah[2][4], bh[8][2];
#pragma unroll
            for (int mt = 0; mt < 2; mt++) {
                const int o = aoff[mt] + kb;
                ah[mt][0] = __float_as_uint(st[o]);
                ah[mt][1] = __float_as_uint(st[o + 8 * LDP]);
                ah[mt][2] = __float_as_uint(st[o + 4]);
                ah[mt][3] = __float_as_uint(st[o + 8 * LDP + 4]);
            }
#pragma unroll
            for (int nt = 0; nt < 8; nt++) {
                const int o = boff[nt] + kb;
                bh[nt][0] = __float_as_uint(st[o]);
                bh[nt][1] = __float_as_uint(st[o + 4]);
            }
#pragma unroll
            for (int mt = 0; mt < 2; mt++)
#pragma unroll
                for (int nt = 0; nt < 8; nt++) {
                    float* a = acc[mt][nt];
                    mma_tf32(a[0], a[1], a[2], a[3],
                             ah[mt][0], ah[mt][1], ah[mt][2], ah[mt][3],
                             bh[nt][0], bh[nt][1]);
                }
        }
        if (++stage == NSTAGE) stage = 0;
    }

    // epilogue: c0,c1 at (row, 2c4), (row, 2c4+1); c2,c3 at row+8
#pragma unroll
    for (int mt = 0; mt < 2; mt++) {
        const int row = bm + warpM * 32 + mt * 16 + r;
#pragma unroll
        for (int nt = 0; nt < 8; nt++) {
            const int col = bn + warpN * 64 + nt * 8 + 2 * c4;
            float2 v0; v0.x = acc[mt][nt][0]; v0.y = acc[mt][nt][1];
            float2 v1; v1.x = acc[mt][nt][2]; v1.y = acc[mt][nt][3];
            *reinterpret_cast<float2*>(C + (size_t)row * VOC + col) = v0;
            *reinterpret_cast<float2*>(C + (size_t)(row + 8) * VOC + col) = v1;
        }
    }
}

// ---------------- per-row: approx select + exact rescore + softmax + A@V ----
__global__ __launch_bounds__(256)
void topk_softmax_gather(const float* __restrict__ dots,
                         const float* __restrict__ Qh, const float* __restrict__ Ql,
                         const float* __restrict__ Kh, const float* __restrict__ Kl,
                         const float* __restrict__ v,
                         float* __restrict__ out)
{
    extern __shared__ unsigned int keys[];            // VOC entries = 128KB
    __shared__ unsigned int hist[256];
    __shared__ unsigned int scanbuf[2][256];
    __shared__ float        f_red[256];
    __shared__ float qrow[DIM];
    __shared__ int   sel_idx[MAXSEL];
    __shared__ float sel_val[MAXSEL];
    __shared__ float sel_w[MAXSEL];
    __shared__ unsigned int s_prefix;
    __shared__ int s_r;

    const int tid = threadIdx.x;
    const int lane = tid & 31;
    const int wid = tid >> 5;
    const int row = blockIdx.x;
    const float* drow = dots + (size_t)row * VOC;

    // ---- phase 1: load approx row as sortable keys; load exact q row ----
    for (int i = tid; i < VOC; i += 256)
        keys[i] = f2k(drow[i]);
    for (int i = tid; i < DIM; i += 256)
        qrow[i] = Qh[(size_t)row * DIM + i] + Ql[(size_t)row * DIM + i];

    // ---- phase 2: radix-select rank-TOPK key on approx values ----
    unsigned int prefix = 0, prefmask = 0;
    int r = TOPK;
    __syncthreads();
    for (int pass = 0; pass < 4; pass++) {
        const int shift = 24 - 8 * pass;
        hist[tid] = 0;
        __syncthreads();
        for (int i = tid; i < VOC; i += 256) {
            unsigned int k = keys[i];
            if ((k & prefmask) == prefix)
                atomicAdd(&hist[(k >> shift) & 255u], 1u);
        }
        __syncthreads();
        scanbuf[0][tid] = hist[tid];
        __syncthreads();
        int src = 0;
        for (int off = 1; off < 256; off <<= 1) {
            unsigned int val = scanbuf[src][tid];
            if (tid + off < 256) val += scanbuf[src][tid + off];
            scanbuf[src ^ 1][tid] = val;
            __syncthreads();
            src ^= 1;
        }
        const unsigned int cumb  = scanbuf[src][tid];
        const unsigned int cumb1 = (tid == 255) ? 0u : scanbuf[src][tid + 1];
        if (cumb >= (unsigned int)r && cumb1 < (unsigned int)r) {
            s_prefix = prefix | ((unsigned int)tid << shift);
            s_r = r - (int)cumb1;
        }
        __syncthreads();
        prefix = s_prefix;
        r = s_r;
        prefmask |= 0xFFu << shift;
        __syncthreads();
    }
    // widen threshold by margin (approx error bound)
    const unsigned int cutkey = f2k(k2f(prefix) - MARGIN);

    // ---- phase 3: deterministic compaction of candidate indices ----
    int c = 0;
    for (int i = tid; i < VOC; i += 256)
        if (keys[i] >= cutkey) c++;
    scanbuf[0][tid] = (unsigned int)c;
    __syncthreads();
    int src = 0;
    for (int off = 1; off < 256; off <<= 1) {
        unsigned int val = scanbuf[src][tid];
        if (tid >= off) val += scanbuf[src][tid - off];
        scanbuf[src ^ 1][tid] = val;
        __syncthreads();
        src ^= 1;
    }
    int pos = (tid == 0) ? 0 : (int)scanbuf[src][tid - 1];
    const int count = min((int)scanbuf[src][255], MAXSEL);

    for (int i = tid; i < VOC; i += 256) {
        if (keys[i] >= cutkey) {
            if (pos < MAXSEL) sel_idx[pos] = i;
            pos++;
        }
    }
    __syncthreads();

    // ---- phase 4: exact fp32 rescore of candidates (one warp per cand) ----
    for (int s = wid; s < count; s += 8) {
        const int idx = sel_idx[s];
        const float4* krh = reinterpret_cast<const float4*>(Kh + (size_t)idx * DIM);
        const float4* krl = reinterpret_cast<const float4*>(Kl + (size_t)idx * DIM);
        float sum = 0.0f;
#pragma unroll
        for (int j = 0; j < 4; j++) {
            const float4 a = krh[lane * 4 + j];
            const float4 b = krl[lane * 4 + j];
            const float4 qv = *reinterpret_cast<const float4*>(&qrow[lane * 16 + j * 4]);
            sum += qv.x * (a.x + b.x) + qv.y * (a.y + b.y)
                 + qv.z * (a.z + b.z) + qv.w * (a.w + b.w);
        }
#pragma unroll
        for (int off = 16; off > 0; off >>= 1)
            sum += __shfl_xor_sync(0xFFFFFFFFu, sum, off);
        if (lane == 0) sel_val[s] = sum;
    }
    __syncthreads();

    // ---- phase 5: exact top-64 rule + softmax weights ----
    float mx = -3.4e38f;
    if (tid < count) mx = sel_val[tid];
    f_red[tid] = mx;
    __syncthreads();
#pragma unroll
    for (int s = 128; s > 0; s >>= 1) {
        if (tid < s) f_red[tid] = fmaxf(f_red[tid], f_red[tid + s]);
        __syncthreads();
    }
    const float m = f_red[0];

    if (tid < count) {
        const float mine = sel_val[tid];
        int greater = 0;
        for (int j = 0; j < count; j++)
            greater += (sel_val[j] > mine);
        sel_w[tid] = (greater < TOPK) ? expf(mine - m) : 0.0f;
    }
    __syncthreads();

    float z = (tid < count) ? sel_w[tid] : 0.0f;
    f_red[tid] = z;
    __syncthreads();
#pragma unroll
    for (int s = 128; s > 0; s >>= 1) {
        if (tid < s) f_red[tid] += f_red[tid + s];
        __syncthreads();
    }
    const float Z = f_red[0];

    // ---- phase 6: out[row] = (1/Z) * sum_s w_s * v[idx_s] ----
    float acc0 = 0.0f, acc1 = 0.0f;
    const int d0 = tid * 2;
    for (int s = 0; s < count; s++) {
        const float w = sel_w[s];
        const float2 vv = *reinterpret_cast<const float2*>(
            v + (size_t)sel_idx[s] * DIM + d0);
        acc0 += w * vv.x;
        acc1 += w * vv.y;
    }
    const float inv = 1.0f / Z;
    float2 o;
    o.x = acc0 * inv;
    o.y = acc1 * inv;
    *reinterpret_cast<float2*>(out + (size_t)row * DIM + d0) = o;
}

// ---------------- launch ----------------------------------------------------
extern "C" void kernel_launch(void* const* d_in, const int* in_sizes, int n_in,
                              void* d_out, int out_size)
{
    const float* x  = (const float*)d_in[0];
    const float* cb = (const float*)d_in[1];
    const float* Wq = (const float*)d_in[2];
    const float* bq = (const float*)d_in[3];
    const float* Wk = (const float*)d_in[4];
    const float* bk = (const float*)d_in[5];
    const float* Wv = (const float*)d_in[6];
    const float* bv = (const float*)d_in[7];
    float* out = (float*)d_out;

    float *v, *qh, *ql, *kh, *kl, *dots;
    cudaGetSymbolAddress((void**)&v,    g_v);
    cudaGetSymbolAddress((void**)&qh,   g_qh);
    cudaGetSymbolAddress((void**)&ql,   g_ql);
    cudaGetSymbolAddress((void**)&kh,   g_kh);
    cudaGetSymbolAddress((void**)&kl,   g_kl);
    cudaGetSymbolAddress((void**)&dots, g_dots);

    cudaFuncSetAttribute(topk_softmax_gather,
                         cudaFuncAttributeMaxDynamicSharedMemorySize,
                         VOC * (int)sizeof(unsigned int));
    cudaFuncSetAttribute(dots_mma,
                         cudaFuncAttributeMaxDynamicSharedMemorySize,
                         NSTAGE * ST_BYTES);

    dim3 blk(256);

    // projections: q,k fused with tf32 split; v plain fp32
    sgemm128<true, true><<<dim3(DIM / 128, BATCH / 128), blk>>>(
        x, Wq, bq, qh, ql, BATCH, DIM, DIM);
    sgemm128<true, true><<<dim3(DIM / 128, VOC / 128), blk>>>(
        cb, Wk, bk, kh, kl, VOC, DIM, DIM);
    sgemm128<true, false><<<dim3(DIM / 128, VOC / 128), blk>>>(
        cb, Wv, bv, v, nullptr, VOC, DIM, DIM);

    // approx dots = qh @ kh^T (single tf32 pass)
    dots_mma<<<dim3(BATCH / MT, VOC / NT), blk, NSTAGE * ST_BYTES>>>(
        qh, kh, dots);

    // approx select (margin) + exact rescore + softmax + sparse gather of v
    topk_softmax_gather<<<BATCH, blk, VOC * (int)sizeof(unsigned int)>>>(
        dots, qh, ql, kh, kl, v, out);
}

// round 8
// speedup vs baseline: 1.4435x; 1.0320x over previous
#include <cuda_runtime.h>
#include <cstdint>

#define VOC   32768
#define DIM   512
#define BATCH 4096
#define TOPK  64
#define MAXSEL 128
#define MARGIN 0.008f

// dots tile config (mma.sync tf32 single-pass): CTA 128x128, 8 warps of 32x64
#define MT 128
#define NT 128
#define KC 16
#define KITERS (DIM / KC)        // 32
#define LDP 20                   // padded floats per smem row (KC + 4)
#define A_FLOATS (MT * LDP)      // 2560
#define B_FLOATS (NT * LDP)      // 2560
#define ST_FLOATS (A_FLOATS + B_FLOATS)          // 5120
#define ST_BYTES  (ST_FLOATS * 4)                // 20480
#define NSTAGE 3

// ---------------- scratch (static device globals; no allocation allowed) ----
__device__ float g_v [(size_t)VOC * DIM];
__device__ float g_qh[(size_t)BATCH * DIM];
__device__ float g_ql[(size_t)BATCH * DIM];
__device__ float g_kh[(size_t)VOC * DIM];
__device__ float g_kl[(size_t)VOC * DIM];
__device__ float g_dots[(size_t)BATCH * VOC];   // 512 MB (approx)

// ---------------- PTX helpers ------------------------------------------------
__device__ __forceinline__ uint32_t smem_u32(const void* p) {
    uint32_t a;
    asm("{ .reg .u64 t; cvta.to.shared.u64 t, %1; cvt.u32.u64 %0, t; }"
        : "=r"(a) : "l"(p));
    return a;
}
#define CP_ASYNC16(dst, src) \
    asm volatile("cp.async.cg.shared.global [%0], [%1], 16;" \
                 :: "r"(dst), "l"(src) : "memory")
#define CP_COMMIT()  asm volatile("cp.async.commit_group;" ::: "memory")

__device__ __forceinline__ void mma_tf32(float& c0, float& c1, float& c2, float& c3,
                                         uint32_t a0, uint32_t a1, uint32_t a2, uint32_t a3,
                                         uint32_t b0, uint32_t b1) {
    asm volatile(
        "mma.sync.aligned.m16n8k8.row.col.f32.tf32.tf32.f32 "
        "{%0,%1,%2,%3}, {%4,%5,%6,%7}, {%8,%9}, {%0,%1,%2,%3};"
        : "+f"(c0), "+f"(c1), "+f"(c2), "+f"(c3)
        : "r"(a0), "r"(a1), "r"(a2), "r"(a3), "r"(b0), "r"(b1));
}

__device__ __forceinline__ void ldsm4(uint32_t& r0, uint32_t& r1,
                                      uint32_t& r2, uint32_t& r3, uint32_t addr) {
    asm volatile("ldmatrix.sync.aligned.m8n8.x4.shared.b16 {%0,%1,%2,%3}, [%4];"
                 : "=r"(r0), "=r"(r1), "=r"(r2), "=r"(r3) : "r"(addr));
}

__device__ __forceinline__ float to_tf32(float a) {
    uint32_t b;
    asm("cvt.rna.tf32.f32 %0, %1;" : "=r"(b) : "f"(a));
    return __uint_as_float(b);
}

// ---------------- misc helpers ----------------------------------------------
__device__ __forceinline__ unsigned int f2k(float f) {
    unsigned int u = __float_as_uint(f);
    return (u & 0x80000000u) ? ~u : (u | 0x80000000u);
}
__device__ __forceinline__ float k2f(unsigned int k) {
    unsigned int u = (k & 0x80000000u) ? (k ^ 0x80000000u) : ~k;
    return __uint_as_float(u);
}

// ---------------- SGEMM (fp32, FFMA) for q/k/v projections -------------------
// SPLIT: write tf32 split (hi -> C, lo -> C2) of acc+bias instead of fp32.
template <bool BIAS, bool SPLIT>
__global__ __launch_bounds__(256)
void sgemm128(const float* __restrict__ A, const float* __restrict__ B,
              const float* __restrict__ bias, float* __restrict__ C,
              float* __restrict__ C2,
              int M, int N, int K)
{
    __shared__ float As[8][128];
    __shared__ float Bs[8][128];

    const int tid = threadIdx.x;
    const int bm = blockIdx.y * 128;
    const int bn = blockIdx.x * 128;

    const int a_row = tid >> 1;
    const int a_col = (tid & 1) * 4;
    const int b_row = tid >> 5;
    const int b_col = (tid & 31) * 4;

    const int tx = tid & 15;
    const int ty = tid >> 4;

    float acc[8][8];
#pragma unroll
    for (int i = 0; i < 8; i++)
#pragma unroll
        for (int j = 0; j < 8; j++) acc[i][j] = 0.0f;

    for (int k0 = 0; k0 < K; k0 += 8) {
        float4 av = *reinterpret_cast<const float4*>(
            A + (size_t)(bm + a_row) * K + (k0 + a_col));
        As[a_col + 0][a_row] = av.x;
        As[a_col + 1][a_row] = av.y;
        As[a_col + 2][a_row] = av.z;
        As[a_col + 3][a_row] = av.w;

        float4 bv = *reinterpret_cast<const float4*>(
            B + (size_t)(k0 + b_row) * N + (bn + b_col));
        *reinterpret_cast<float4*>(&Bs[b_row][b_col]) = bv;
        __syncthreads();

#pragma unroll
        for (int kk = 0; kk < 8; kk++) {
            float af[8], bf[8];
            float4 t;
            t = *reinterpret_cast<const float4*>(&As[kk][ty * 8]);
            af[0] = t.x; af[1] = t.y; af[2] = t.z; af[3] = t.w;
            t = *reinterpret_cast<const float4*>(&As[kk][ty * 8 + 4]);
            af[4] = t.x; af[5] = t.y; af[6] = t.z; af[7] = t.w;
            t = *reinterpret_cast<const float4*>(&Bs[kk][tx * 8]);
            bf[0] = t.x; bf[1] = t.y; bf[2] = t.z; bf[3] = t.w;
            t = *reinterpret_cast<const float4*>(&Bs[kk][tx * 8 + 4]);
            bf[4] = t.x; bf[5] = t.y; bf[6] = t.z; bf[7] = t.w;
#pragma unroll
            for (int i = 0; i < 8; i++)
#pragma unroll
                for (int j = 0; j < 8; j++)
                    acc[i][j] += af[i] * bf[j];
        }
        __syncthreads();
    }

#pragma unroll
    for (int i = 0; i < 8; i++) {
        const int row = bm + ty * 8 + i;
        const int col = bn + tx * 8;
#pragma unroll
        for (int j = 0; j < 8; j += 4) {
            float o[4];
#pragma unroll
            for (int t = 0; t < 4; t++) {
                o[t] = acc[i][j + t];
                if (BIAS) o[t] += bias[col + j + t];
            }
            if (SPLIT) {
                float4 h4, l4;
                float* hp = &h4.x;
                float* lp = &l4.x;
#pragma unroll
                for (int t = 0; t < 4; t++) {
                    float h = to_tf32(o[t]);
                    hp[t] = h;
                    lp[t] = to_tf32(o[t] - h);
                }
                *reinterpret_cast<float4*>(C  + (size_t)row * N + col + j) = h4;
                *reinterpret_cast<float4*>(C2 + (size_t)row * N + col + j) = l4;
            } else {
                float4 v4;
                v4.x = o[0]; v4.y = o[1]; v4.z = o[2]; v4.w = o[3];
                *reinterpret_cast<float4*>(C + (size_t)row * N + col + j) = v4;
            }
        }
    }
}

// ---------------- dots_approx = qh @ kh^T via single-pass tf32 mma ----------
// CTA 128x128, 8 warps (4m x 2n) of 32x64, KC=16, 3-stage cp.async pipeline.
// Fragment loads via ldmatrix.x4 (b16 tiles; an 8x8 tf32 block = two b16 tiles).
__global__ __launch_bounds__(256, 2)
void dots_mma(const float* __restrict__ Ahi, const float* __restrict__ Bhi,
              float* __restrict__ C)
{
    extern __shared__ __align__(16) float smem[];
    const uint32_t sb = smem_u32(smem);

    const int tid = threadIdx.x;
    const int lane = tid & 31;
    const int wid = tid >> 5;
    const int warpM = wid >> 1;       // 0..3 -> 32 rows each
    const int warpN = wid & 1;        // 0..1 -> 64 cols each
    const int bm = blockIdx.x * MT;   // m fastest -> q tiles stay L2 resident
    const int bn = blockIdx.y * NT;

    const int r = lane >> 2;          // 0..7
    const int c4 = lane & 3;          // 0..3

    float acc[2][8][4];
#pragma unroll
    for (int mt = 0; mt < 2; mt++)
#pragma unroll
        for (int nt = 0; nt < 8; nt++)
#pragma unroll
            for (int i = 0; i < 4; i++) acc[mt][nt][i] = 0.0f;

    const int isB = tid >> 7;         // 0: A row, 1: B row
    const int prow = tid & 127;
    const float* gbase = (isB ? Bhi + (size_t)(bn + prow) * DIM
                              : Ahi + (size_t)(bm + prow) * DIM);
    const uint32_t dbase = sb + ((isB ? A_FLOATS : 0) + (uint32_t)prow * LDP) * 4;

    // prefetch K-chunk `it` into stage `s` (4 cp.async16 per thread)
    auto prefetch = [&](int it, int s) {
        const float* g = gbase + it * KC;
        const uint32_t d = dbase + (uint32_t)s * ST_BYTES;
#pragma unroll
        for (int c = 0; c < 4; c++)
            CP_ASYNC16(d + c * 16, g + c * 4);
        CP_COMMIT();
    };

    prefetch(0, 0);
    prefetch(1, 1);

    // ldmatrix per-thread byte offsets within a stage
    // A tile mt (16x8): lanes 0-15 -> rows am+(lane&15), col kb;
    //                   lanes 16-31 -> rows am+(lane&15), col kb+4
    uint32_t aoffb[2];
#pragma unroll
    for (int mt = 0; mt < 2; mt++)
        aoffb[mt] = ((uint32_t)(warpM * 32 + mt * 16 + (lane & 15)) * LDP
                     + ((lane >> 4) << 2)) * 4;
    // B pair p (n-tiles 2p,2p+1): row = n0 + (lane&7) + (lane&16 ? 8 : 0),
    //                             col = kb + (lane&8 ? 4 : 0)
    uint32_t boffb[4];
#pragma unroll
    for (int p = 0; p < 4; p++)
        boffb[p] = ((uint32_t)A_FLOATS
                    + (uint32_t)(warpN * 64 + p * 16 + (lane & 7) + ((lane & 16) >> 1)) * LDP
                    + ((lane & 8) >> 1)) * 4;

    int stage = 0;
    for (int it = 0; it < KITERS; it++) {
        if (it + 1 < KITERS)
            asm volatile("cp.async.wait_group %0;" :: "n"(1));
        else
            asm volatile("cp.async.wait_group %0;" :: "n"(0));
        __syncthreads();

        if (it + 2 < KITERS) {
            int ps = stage + 2; if (ps >= NSTAGE) ps -= NSTAGE;
            prefetch(it + 2, ps);
        }

        const uint32_t stb = sb + (uint32_t)stage * ST_BYTES;

#pragma unroll
        for (int ks = 0; ks < 2; ks++) {
            const uint32_t koff = (uint32_t)ks * 32;   // 8 floats
            uint32_t a[2][4], b[4][4];
#pragma unroll
            for (int mt = 0; mt < 2; mt++)
                ldsm4(a[mt][0], a[mt][1], a[mt][2], a[mt][3],
                      stb + aoffb[mt] + koff);
#pragma unroll
            for (int p = 0; p < 4; p++)
                ldsm4(b[p][0], b[p][1], b[p][2], b[p][3],
                      stb + boffb[p] + koff);
#pragma unroll
            for (int mt = 0; mt < 2; mt++)
#pragma unroll
                for (int p = 0; p < 4; p++) {
                    float* a0 = acc[mt][2 * p];
                    float* a1 = acc[mt][2 * p + 1];
                    mma_tf32(a0[0], a0[1], a0[2], a0[3],
                             a[mt][0], a[mt][1], a[mt][2], a[mt][3],
                             b[p][0], b[p][1]);
                    mma_tf32(a1[0], a1[1], a1[2], a1[3],
                             a[mt][0], a[mt][1], a[mt][2], a[mt][3],
                             b[p][2], b[p][3]);
                }
        }
        if (++stage == NSTAGE) stage = 0;
    }

    // epilogue: c0,c1 at (row, 2c4), (row, 2c4+1); c2,c3 at row+8
#pragma unroll
    for (int mt = 0; mt < 2; mt++) {
        const int row = bm + warpM * 32 + mt * 16 + r;
#pragma unroll
        for (int nt = 0; nt < 8; nt++) {
            const int col = bn + warpN * 64 + nt * 8 + 2 * c4;
            float2 v0; v0.x = acc[mt][nt][0]; v0.y = acc[mt][nt][1];
            float2 v1; v1.x = acc[mt][nt][2]; v1.y = acc[mt][nt][3];
            *reinterpret_cast<float2*>(C + (size_t)row * VOC + col) = v0;
            *reinterpret_cast<float2*>(C + (size_t)(row + 8) * VOC + col) = v1;
        }
    }
}

// ---------------- per-row: approx select + exact rescore + softmax + A@V ----
__global__ __launch_bounds__(256)
void topk_softmax_gather(const float* __restrict__ dots,
                         const float* __restrict__ Qh, const float* __restrict__ Ql,
                         const float* __restrict__ Kh, const float* __restrict__ Kl,
                         const float* __restrict__ v,
                         float* __restrict__ out)
{
    extern __shared__ unsigned int keys[];            // VOC entries = 128KB
    __shared__ unsigned int hist[256];
    __shared__ unsigned int scanbuf[2][256];
    __shared__ float        f_red[256];
    __shared__ float qrow[DIM];
    __shared__ int   sel_idx[MAXSEL];
    __shared__ float sel_val[MAXSEL];
    __shared__ float sel_w[MAXSEL];
    __shared__ unsigned int s_prefix;
    __shared__ int s_r;

    const int tid = threadIdx.x;
    const int lane = tid & 31;
    const int wid = tid >> 5;
    const int row = blockIdx.x;
    const float* drow = dots + (size_t)row * VOC;

    // ---- phase 1: load approx row as sortable keys; load exact q row ----
    for (int i = tid; i < VOC; i += 256)
        keys[i] = f2k(drow[i]);
    for (int i = tid; i < DIM; i += 256)
        qrow[i] = Qh[(size_t)row * DIM + i] + Ql[(size_t)row * DIM + i];

    // ---- phase 2: radix-select rank-TOPK key on approx values ----
    unsigned int prefix = 0, prefmask = 0;
    int r = TOPK;
    __syncthreads();
    for (int pass = 0; pass < 4; pass++) {
        const int shift = 24 - 8 * pass;
        hist[tid] = 0;
        __syncthreads();
        for (int i = tid; i < VOC; i += 256) {
            unsigned int k = keys[i];
            if ((k & prefmask) == prefix)
                atomicAdd(&hist[(k >> shift) & 255u], 1u);
        }
        __syncthreads();
        scanbuf[0][tid] = hist[tid];
        __syncthreads();
        int src = 0;
        for (int off = 1; off < 256; off <<= 1) {
            unsigned int val = scanbuf[src][tid];
            if (tid + off < 256) val += scanbuf[src][tid + off];
            scanbuf[src ^ 1][tid] = val;
            __syncthreads();
            src ^= 1;
        }
        const unsigned int cumb  = scanbuf[src][tid];
        const unsigned int cumb1 = (tid == 255) ? 0u : scanbuf[src][tid + 1];
        if (cumb >= (unsigned int)r && cumb1 < (unsigned int)r) {
            s_prefix = prefix | ((unsigned int)tid << shift);
            s_r = r - (int)cumb1;
        }
        __syncthreads();
        prefix = s_prefix;
        r = s_r;
        prefmask |= 0xFFu << shift;
        __syncthreads();
    }
    // widen threshold by margin (approx error bound)
    const unsigned int cutkey = f2k(k2f(prefix) - MARGIN);

    // ---- phase 3: deterministic compaction of candidate indices ----
    int c = 0;
    for (int i = tid; i < VOC; i += 256)
        if (keys[i] >= cutkey) c++;
    scanbuf[0][tid] = (unsigned int)c;
    __syncthreads();
    int src = 0;
    for (int off = 1; off < 256; off <<= 1) {
        unsigned int val = scanbuf[src][tid];
        if (tid >= off) val += scanbuf[src][tid - off];
        scanbuf[src ^ 1][tid] = val;
        __syncthreads();
        src ^= 1;
    }
    int pos = (tid == 0) ? 0 : (int)scanbuf[src][tid - 1];
    const int count = min((int)scanbuf[src][255], MAXSEL);

    for (int i = tid; i < VOC; i += 256) {
        if (keys[i] >= cutkey) {
            if (pos < MAXSEL) sel_idx[pos] = i;
            pos++;
        }
    }
    __syncthreads();

    // ---- phase 4: exact fp32 rescore of candidates (one warp per cand) ----
    for (int s = wid; s < count; s += 8) {
        const int idx = sel_idx[s];
        const float4* krh = reinterpret_cast<const float4*>(Kh + (size_t)idx * DIM);
        const float4* krl = reinterpret_cast<const float4*>(Kl + (size_t)idx * DIM);
        float sum = 0.0f;
#pragma unroll
        for (int j = 0; j < 4; j++) {
            const float4 a = krh[lane * 4 + j];
            const float4 b = krl[lane * 4 + j];
            const float4 qv = *reinterpret_cast<const float4*>(&qrow[lane * 16 + j * 4]);
            sum += qv.x * (a.x + b.x) + qv.y * (a.y + b.y)
                 + qv.z * (a.z + b.z) + qv.w * (a.w + b.w);
        }
#pragma unroll
        for (int off = 16; off > 0; off >>= 1)
            sum += __shfl_xor_sync(0xFFFFFFFFu, sum, off);
        if (lane == 0) sel_val[s] = sum;
    }
    __syncthreads();

    // ---- phase 5: exact top-64 rule + softmax weights ----
    float mx = -3.4e38f;
    if (tid < count) mx = sel_val[tid];
    f_red[tid] = mx;
    __syncthreads();
#pragma unroll
    for (int s = 128; s > 0; s >>= 1) {
        if (tid < s) f_red[tid] = fmaxf(f_red[tid], f_red[tid + s]);
        __syncthreads();
    }
    const float m = f_red[0];

    if (tid < count) {
        const float mine = sel_val[tid];
        int greater = 0;
        for (int j = 0; j < count; j++)
            greater += (sel_val[j] > mine);
        sel_w[tid] = (greater < TOPK) ? expf(mine - m) : 0.0f;
    }
    __syncthreads();

    float z = (tid < count) ? sel_w[tid] : 0.0f;
    f_red[tid] = z;
    __syncthreads();
#pragma unroll
    for (int s = 128; s > 0; s >>= 1) {
        if (tid < s) f_red[tid] += f_red[tid + s];
        __syncthreads();
    }
    const float Z = f_red[0];

    // ---- phase 6: out[row] = (1/Z) * sum_s w_s * v[idx_s] ----
    float acc0 = 0.0f, acc1 = 0.0f;
    const int d0 = tid * 2;
    for (int s = 0; s < count; s++) {
        const float w = sel_w[s];
        const float2 vv = *reinterpret_cast<const float2*>(
            v + (size_t)sel_idx[s] * DIM + d0);
        acc0 += w * vv.x;
        acc1 += w * vv.y;
    }
    const float inv = 1.0f / Z;
    float2 o;
    o.x = acc0 * inv;
    o.y = acc1 * inv;
    *reinterpret_cast<float2*>(out + (size_t)row * DIM + d0) = o;
}

// ---------------- launch ----------------------------------------------------
extern "C" void kernel_launch(void* const* d_in, const int* in_sizes, int n_in,
                              void* d_out, int out_size)
{
    const float* x  = (const float*)d_in[0];
    const float* cb = (const float*)d_in[1];
    const float* Wq = (const float*)d_in[2];
    const float* bq = (const float*)d_in[3];
    const float* Wk = (const float*)d_in[4];
    const float* bk = (const float*)d_in[5];
    const float* Wv = (const float*)d_in[6];
    const float* bv = (const float*)d_in[7];
    float* out = (float*)d_out;

    float *v, *qh, *ql, *kh, *kl, *dots;
    cudaGetSymbolAddress((void**)&v,    g_v);
    cudaGetSymbolAddress((void**)&qh,   g_qh);
    cudaGetSymbolAddress((void**)&ql,   g_ql);
    cudaGetSymbolAddress((void**)&kh,   g_kh);
    cudaGetSymbolAddress((void**)&kl,   g_kl);
    cudaGetSymbolAddress((void**)&dots, g_dots);

    cudaFuncSetAttribute(topk_softmax_gather,
                         cudaFuncAttributeMaxDynamicSharedMemorySize,
                         VOC * (int)sizeof(unsigned int));
    cudaFuncSetAttribute(dots_mma,
                         cudaFuncAttributeMaxDynamicSharedMemorySize,
                         NSTAGE * ST_BYTES);

    dim3 blk(256);

    // projections: q,k fused with tf32 split; v plain fp32
    sgemm128<true, true><<<dim3(DIM / 128, BATCH / 128), blk>>>(
        x, Wq, bq, qh, ql, BATCH, DIM, DIM);
    sgemm128<true, true><<<dim3(DIM / 128, VOC / 128), blk>>>(
        cb, Wk, bk, kh, kl, VOC, DIM, DIM);
    sgemm128<true, false><<<dim3(DIM / 128, VOC / 128), blk>>>(
        cb, Wv, bv, v, nullptr, VOC, DIM, DIM);

    // approx dots = qh @ kh^T (single tf32 pass, ldmatrix frags)
    dots_mma<<<dim3(BATCH / MT, VOC / NT), blk, NSTAGE * ST_BYTES>>>(
        qh, kh, dots);

    // approx select (margin) + exact rescore + softmax + sparse gather of v
    topk_softmax_gather<<<BATCH, blk, VOC * (int)sizeof(unsigned int)>>>(
        dots, qh, ql, kh, kl, v, out);
}

// round 9
// speedup vs baseline: 2.0896x; 1.4476x over previous
#include <cuda_runtime.h>
#include <cuda_bf16.h>
#include <cstdint>

#define VOC   32768
#define DIM   512
#define BATCH 4096
#define TOPK  64
#define MAXSEL 192
#define MARGIN 0.015f

// dots tile config (mma.sync bf16 m16n8k16): CTA 128x128, 8 warps of 32x64
#define MT 128
#define NT 128
#define KCH 32                   // bf16 elements per K chunk
#define KITERS (DIM / KCH)       // 16
#define LDH 40                   // halves per smem row (KCH + 8 pad)
#define A_HALVES (MT * LDH)      // 5120
#define ST_HALVES (2 * A_HALVES) // 10240
#define ST_BYTES  (ST_HALVES * 2)   // 20480
#define NSTAGE 4

// ---------------- scratch (static device globals; no allocation allowed) ----
__device__ float g_q [(size_t)BATCH * DIM];
__device__ float g_k [(size_t)VOC * DIM];
__device__ float g_v [(size_t)VOC * DIM];
__device__ unsigned short g_qb[(size_t)BATCH * DIM];
__device__ unsigned short g_kb[(size_t)VOC * DIM];
__device__ float g_dots[(size_t)BATCH * VOC];   // 512 MB (approx)

// ---------------- PTX helpers ------------------------------------------------
__device__ __forceinline__ uint32_t smem_u32(const void* p) {
    uint32_t a;
    asm("{ .reg .u64 t; cvta.to.shared.u64 t, %1; cvt.u32.u64 %0, t; }"
        : "=r"(a) : "l"(p));
    return a;
}
#define CP_ASYNC16(dst, src) \
    asm volatile("cp.async.cg.shared.global [%0], [%1], 16;" \
                 :: "r"(dst), "l"(src) : "memory")
#define CP_COMMIT()  asm volatile("cp.async.commit_group;" ::: "memory")

__device__ __forceinline__ void mma_bf16(float& c0, float& c1, float& c2, float& c3,
                                         uint32_t a0, uint32_t a1, uint32_t a2, uint32_t a3,
                                         uint32_t b0, uint32_t b1) {
    asm volatile(
        "mma.sync.aligned.m16n8k16.row.col.f32.bf16.bf16.f32 "
        "{%0,%1,%2,%3}, {%4,%5,%6,%7}, {%8,%9}, {%0,%1,%2,%3};"
        : "+f"(c0), "+f"(c1), "+f"(c2), "+f"(c3)
        : "r"(a0), "r"(a1), "r"(a2), "r"(a3), "r"(b0), "r"(b1));
}

__device__ __forceinline__ void ldsm4(uint32_t& r0, uint32_t& r1,
                                      uint32_t& r2, uint32_t& r3, uint32_t addr) {
    asm volatile("ldmatrix.sync.aligned.m8n8.x4.shared.b16 {%0,%1,%2,%3}, [%4];"
                 : "=r"(r0), "=r"(r1), "=r"(r2), "=r"(r3) : "r"(addr));
}

// ---------------- misc helpers ----------------------------------------------
__device__ __forceinline__ unsigned int f2k(float f) {
    unsigned int u = __float_as_uint(f);
    return (u & 0x80000000u) ? ~u : (u | 0x80000000u);
}
__device__ __forceinline__ float k2f(unsigned int k) {
    unsigned int u = (k & 0x80000000u) ? (k ^ 0x80000000u) : ~k;
    return __uint_as_float(u);
}

// ---------------- SGEMM (fp32, FFMA) for q/k/v projections -------------------
// WB: additionally write bf16 copy of (acc+bias) to Cb.
template <bool WB>
__global__ __launch_bounds__(256)
void sgemm128(const float* __restrict__ A, const float* __restrict__ B,
              const float* __restrict__ bias, float* __restrict__ C,
              unsigned short* __restrict__ Cb,
              int M, int N, int K)
{
    __shared__ float As[8][128];
    __shared__ float Bs[8][128];

    const int tid = threadIdx.x;
    const int bm = blockIdx.y * 128;
    const int bn = blockIdx.x * 128;

    const int a_row = tid >> 1;
    const int a_col = (tid & 1) * 4;
    const int b_row = tid >> 5;
    const int b_col = (tid & 31) * 4;

    const int tx = tid & 15;
    const int ty = tid >> 4;

    float acc[8][8];
#pragma unroll
    for (int i = 0; i < 8; i++)
#pragma unroll
        for (int j = 0; j < 8; j++) acc[i][j] = 0.0f;

    for (int k0 = 0; k0 < K; k0 += 8) {
        float4 av = *reinterpret_cast<const float4*>(
            A + (size_t)(bm + a_row) * K + (k0 + a_col));
        As[a_col + 0][a_row] = av.x;
        As[a_col + 1][a_row] = av.y;
        As[a_col + 2][a_row] = av.z;
        As[a_col + 3][a_row] = av.w;

        float4 bv = *reinterpret_cast<const float4*>(
            B + (size_t)(k0 + b_row) * N + (bn + b_col));
        *reinterpret_cast<float4*>(&Bs[b_row][b_col]) = bv;
        __syncthreads();

#pragma unroll
        for (int kk = 0; kk < 8; kk++) {
            float af[8], bf[8];
            float4 t;
            t = *reinterpret_cast<const float4*>(&As[kk][ty * 8]);
            af[0] = t.x; af[1] = t.y; af[2] = t.z; af[3] = t.w;
            t = *reinterpret_cast<const float4*>(&As[kk][ty * 8 + 4]);
            af[4] = t.x; af[5] = t.y; af[6] = t.z; af[7] = t.w;
            t = *reinterpret_cast<const float4*>(&Bs[kk][tx * 8]);
            bf[0] = t.x; bf[1] = t.y; bf[2] = t.z; bf[3] = t.w;
            t = *reinterpret_cast<const float4*>(&Bs[kk][tx * 8 + 4]);
            bf[4] = t.x; bf[5] = t.y; bf[6] = t.z; bf[7] = t.w;
#pragma unroll
            for (int i = 0; i < 8; i++)
#pragma unroll
                for (int j = 0; j < 8; j++)
                    acc[i][j] += af[i] * bf[j];
        }
        __syncthreads();
    }

#pragma unroll
    for (int i = 0; i < 8; i++) {
        const int row = bm + ty * 8 + i;
        const int col = bn + tx * 8;
#pragma unroll
        for (int j = 0; j < 8; j += 4) {
            float o[4];
#pragma unroll
            for (int t = 0; t < 4; t++) {
                o[t] = acc[i][j + t];
                o[t] += bias[col + j + t];
            }
            float4 v4;
            v4.x = o[0]; v4.y = o[1]; v4.z = o[2]; v4.w = o[3];
            *reinterpret_cast<float4*>(C + (size_t)row * N + col + j) = v4;
            if (WB) {
                ushort4 ub;
                ub.x = __bfloat16_as_ushort(__float2bfloat16(o[0]));
                ub.y = __bfloat16_as_ushort(__float2bfloat16(o[1]));
                ub.z = __bfloat16_as_ushort(__float2bfloat16(o[2]));
                ub.w = __bfloat16_as_ushort(__float2bfloat16(o[3]));
                *reinterpret_cast<ushort4*>(Cb + (size_t)row * N + col + j) = ub;
            }
        }
    }
}

// ---------------- dots_approx = qb @ kb^T via bf16 m16n8k16 mma --------------
// CTA 128x128, 8 warps (4m x 2n) of 32x64, K chunks of 32 bf16, 4-stage pipeline.
__global__ __launch_bounds__(256, 2)
void dots_bf16(const unsigned short* __restrict__ Ab,
               const unsigned short* __restrict__ Bb,
               float* __restrict__ C)
{
    extern __shared__ __align__(16) unsigned short smem[];
    const uint32_t sb = smem_u32(smem);

    const int tid = threadIdx.x;
    const int lane = tid & 31;
    const int wid = tid >> 5;
    const int warpM = wid >> 1;       // 0..3 -> 32 rows each
    const int warpN = wid & 1;        // 0..1 -> 64 cols each
    const int bm = blockIdx.x * MT;   // m fastest -> q tiles stay L2 resident
    const int bn = blockIdx.y * NT;

    const int r = lane >> 2;          // 0..7
    const int c4 = lane & 3;          // 0..3

    float acc[2][8][4];
#pragma unroll
    for (int mt = 0; mt < 2; mt++)
#pragma unroll
        for (int nt = 0; nt < 8; nt++)
#pragma unroll
            for (int i = 0; i < 4; i++) acc[mt][nt][i] = 0.0f;

    const int isB = tid >> 7;         // 0: A row, 1: B row
    const int prow = tid & 127;
    const unsigned short* gbase = (isB ? Bb + (size_t)(bn + prow) * DIM
                                       : Ab + (size_t)(bm + prow) * DIM);
    const uint32_t dbase = sb + ((isB ? A_HALVES : 0) + (uint32_t)prow * LDH) * 2;

    // prefetch K-chunk `it` (32 halves = 64B per row) into stage `s`
    auto prefetch = [&](int it, int s) {
        const unsigned short* g = gbase + it * KCH;
        const uint32_t d = dbase + (uint32_t)s * ST_BYTES;
#pragma unroll
        for (int c = 0; c < 4; c++)
            CP_ASYNC16(d + c * 16, g + c * 8);
        CP_COMMIT();
    };

    prefetch(0, 0);
    prefetch(1, 1);
    prefetch(2, 2);

    // ldmatrix per-thread byte offsets within a stage
    const int l8 = lane & 7;
    const int gq = lane >> 3;         // 0..3 quad group
    uint32_t aoffb[2];
#pragma unroll
    for (int mt = 0; mt < 2; mt++) {
        const int row = warpM * 32 + mt * 16 + l8 + (gq & 1) * 8;
        const int col = (gq >> 1) * 8;
        aoffb[mt] = ((uint32_t)row * LDH + col) * 2;
    }
    uint32_t boffb[4];
#pragma unroll
    for (int p = 0; p < 4; p++) {
        const int row = warpN * 64 + p * 16 + l8 + (gq >> 1) * 8;
        const int col = (gq & 1) * 8;
        boffb[p] = ((uint32_t)A_HALVES + (uint32_t)row * LDH + col) * 2;
    }

    for (int it = 0; it < KITERS; it++) {
        if (it + 2 < KITERS)
            asm volatile("cp.async.wait_group %0;" :: "n"(2));
        else if (it + 1 < KITERS)
            asm volatile("cp.async.wait_group %0;" :: "n"(1));
        else
            asm volatile("cp.async.wait_group %0;" :: "n"(0));
        __syncthreads();

        if (it + 3 < KITERS)
            prefetch(it + 3, (it + 3) & 3);

        const uint32_t stb = sb + (uint32_t)(it & 3) * ST_BYTES;

#pragma unroll
        for (int ks = 0; ks < 2; ks++) {
            const uint32_t koff = (uint32_t)ks * 32;   // 16 halves
            uint32_t a[2][4], b[4][4];
#pragma unroll
            for (int mt = 0; mt < 2; mt++)
                ldsm4(a[mt][0], a[mt][1], a[mt][2], a[mt][3],
                      stb + aoffb[mt] + koff);
#pragma unroll
            for (int p = 0; p < 4; p++)
                ldsm4(b[p][0], b[p][1], b[p][2], b[p][3],
                      stb + boffb[p] + koff);
#pragma unroll
            for (int mt = 0; mt < 2; mt++)
#pragma unroll
                for (int p = 0; p < 4; p++) {
                    float* a0 = acc[mt][2 * p];
                    float* a1 = acc[mt][2 * p + 1];
                    mma_bf16(a0[0], a0[1], a0[2], a0[3],
                             a[mt][0], a[mt][1], a[mt][2], a[mt][3],
                             b[p][0], b[p][1]);
                    mma_bf16(a1[0], a1[1], a1[2], a1[3],
                             a[mt][0], a[mt][1], a[mt][2], a[mt][3],
                             b[p][2], b[p][3]);
                }
        }
    }

    // epilogue: c0,c1 at (row, 2c4), (row, 2c4+1); c2,c3 at row+8
#pragma unroll
    for (int mt = 0; mt < 2; mt++) {
        const int row = bm + warpM * 32 + mt * 16 + r;
#pragma unroll
        for (int nt = 0; nt < 8; nt++) {
            const int col = bn + warpN * 64 + nt * 8 + 2 * c4;
            float2 v0; v0.x = acc[mt][nt][0]; v0.y = acc[mt][nt][1];
            float2 v1; v1.x = acc[mt][nt][2]; v1.y = acc[mt][nt][3];
            *reinterpret_cast<float2*>(C + (size_t)row * VOC + col) = v0;
            *reinterpret_cast<float2*>(C + (size_t)(row + 8) * VOC + col) = v1;
        }
    }
}

// ---------------- per-row: approx select + exact rescore + softmax + A@V ----
#define TT 512
__global__ __launch_bounds__(TT)
void topk_softmax_gather(const float* __restrict__ dots,
                         const float* __restrict__ Q,
                         const float* __restrict__ Kf,
                         const float* __restrict__ v,
                         float* __restrict__ out)
{
    extern __shared__ unsigned int keys[];            // VOC entries = 128KB
    __shared__ unsigned int hist[256];
    __shared__ unsigned int scanbuf[2][256];
    __shared__ unsigned int cscan[2][TT];
    __shared__ float        f_red[TT];
    __shared__ float qrow[DIM];
    __shared__ int   sel_idx[MAXSEL];
    __shared__ float sel_val[MAXSEL];
    __shared__ float sel_w[MAXSEL];
    __shared__ unsigned int s_prefix;
    __shared__ int s_r;

    const int tid = threadIdx.x;
    const int lane = tid & 31;
    const int wid = tid >> 5;
    const int row = blockIdx.x;
    const float* drow = dots + (size_t)row * VOC;

    // ---- phase 1: load approx row as sortable keys; load exact q row ----
    for (int i = tid; i < VOC; i += TT)
        keys[i] = f2k(drow[i]);
    if (tid < DIM)
        qrow[tid] = Q[(size_t)row * DIM + tid];
    __syncthreads();

    // ---- phase 2: radix-select rank-TOPK key on approx values ----
    unsigned int prefix = 0, prefmask = 0;
    int r = TOPK;
    for (int pass = 0; pass < 4; pass++) {
        const int shift = 24 - 8 * pass;
        if (tid < 256) hist[tid] = 0;
        __syncthreads();
        for (int i = tid; i < VOC; i += TT) {
            unsigned int k = keys[i];
            if ((k & prefmask) == prefix)
                atomicAdd(&hist[(k >> shift) & 255u], 1u);
        }
        __syncthreads();
        if (tid < 256) scanbuf[0][tid] = hist[tid];
        __syncthreads();
        int src = 0;
        for (int off = 1; off < 256; off <<= 1) {
            unsigned int val = 0;
            if (tid < 256) {
                val = scanbuf[src][tid];
                if (tid + off < 256) val += scanbuf[src][tid + off];
            }
            __syncthreads();
            if (tid < 256) scanbuf[src ^ 1][tid] = val;
            __syncthreads();
            src ^= 1;
        }
        if (tid < 256) {
            const unsigned int cumb  = scanbuf[src][tid];
            const unsigned int cumb1 = (tid == 255) ? 0u : scanbuf[src][tid + 1];
            if (cumb >= (unsigned int)r && cumb1 < (unsigned int)r) {
                s_prefix = prefix | ((unsigned int)tid << shift);
                s_r = r - (int)cumb1;
            }
        }
        __syncthreads();
        prefix = s_prefix;
        r = s_r;
        prefmask |= 0xFFu << shift;
        __syncthreads();
    }
    // widen threshold by margin (bf16 approx error bound)
    const unsigned int cutkey = f2k(k2f(prefix) - MARGIN);

    // ---- phase 3: deterministic compaction of candidate indices ----
    int c = 0;
    for (int i = tid; i < VOC; i += TT)
        if (keys[i] >= cutkey) c++;
    cscan[0][tid] = (unsigned int)c;
    __syncthreads();
    int src = 0;
    for (int off = 1; off < TT; off <<= 1) {
        unsigned int val = cscan[src][tid];
        if (tid >= off) val += cscan[src][tid - off];
        __syncthreads();
        cscan[src ^ 1][tid] = val;
        __syncthreads();
        src ^= 1;
    }
    int pos = (tid == 0) ? 0 : (int)cscan[src][tid - 1];
    const int count = min((int)cscan[src][TT - 1], MAXSEL);

    for (int i = tid; i < VOC; i += TT) {
        if (keys[i] >= cutkey) {
            if (pos < MAXSEL) sel_idx[pos] = i;
            pos++;
        }
    }
    __syncthreads();

    // ---- phase 4: exact fp32 rescore of candidates (one warp per cand) ----
    for (int s = wid; s < count; s += (TT / 32)) {
        const int idx = sel_idx[s];
        const float4* kr = reinterpret_cast<const float4*>(Kf + (size_t)idx * DIM);
        float sum = 0.0f;
#pragma unroll
        for (int j = 0; j < 4; j++) {
            const float4 a = kr[lane * 4 + j];
            const float4 qv = *reinterpret_cast<const float4*>(&qrow[lane * 16 + j * 4]);
            sum += qv.x * a.x + qv.y * a.y + qv.z * a.z + qv.w * a.w;
        }
#pragma unroll
        for (int off = 16; off > 0; off >>= 1)
            sum += __shfl_xor_sync(0xFFFFFFFFu, sum, off);
        if (lane == 0) sel_val[s] = sum;
    }
    __syncthreads();

    // ---- phase 5: exact top-64 rule + softmax weights ----
    float mx = -3.4e38f;
    if (tid < count) mx = sel_val[tid];
    f_red[tid] = mx;
    __syncthreads();
#pragma unroll
    for (int s = TT / 2; s > 0; s >>= 1) {
        if (tid < s) f_red[tid] = fmaxf(f_red[tid], f_red[tid + s]);
        __syncthreads();
    }
    const float m = f_red[0];

    if (tid < count) {
        const float mine = sel_val[tid];
        int greater = 0;
        for (int j = 0; j < count; j++)
            greater += (sel_val[j] > mine);
        sel_w[tid] = (greater < TOPK) ? expf(mine - m) : 0.0f;
    }
    __syncthreads();

    float z = (tid < count) ? sel_w[tid] : 0.0f;
    f_red[tid] = z;
    __syncthreads();
#pragma unroll
    for (int s = TT / 2; s > 0; s >>= 1) {
        if (tid < s) f_red[tid] += f_red[tid + s];
        __syncthreads();
    }
    const float Z = f_red[0];

    // ---- phase 6: out[row] = (1/Z) * sum_s w_s * v[idx_s] ----
    float acc0 = 0.0f;
    for (int s = 0; s < count; s++)
        acc0 += sel_w[s] * v[(size_t)sel_idx[s] * DIM + tid];
    out[(size_t)row * DIM + tid] = acc0 / Z;
}

// ---------------- launch ----------------------------------------------------
extern "C" void kernel_launch(void* const* d_in, const int* in_sizes, int n_in,
                              void* d_out, int out_size)
{
    const float* x  = (const float*)d_in[0];
    const float* cb = (const float*)d_in[1];
    const float* Wq = (const float*)d_in[2];
    const float* bq = (const float*)d_in[3];
    const float* Wk = (const float*)d_in[4];
    const float* bk = (const float*)d_in[5];
    const float* Wv = (const float*)d_in[6];
    const float* bv = (const float*)d_in[7];
    float* out = (float*)d_out;

    float *q, *k, *v, *dots;
    unsigned short *qb, *kb;
    cudaGetSymbolAddress((void**)&q,    g_q);
    cudaGetSymbolAddress((void**)&k,    g_k);
    cudaGetSymbolAddress((void**)&v,    g_v);
    cudaGetSymbolAddress((void**)&qb,   g_qb);
    cudaGetSymbolAddress((void**)&kb,   g_kb);
    cudaGetSymbolAddress((void**)&dots, g_dots);

    cudaFuncSetAttribute(topk_softmax_gather,
                         cudaFuncAttributeMaxDynamicSharedMemorySize,
                         VOC * (int)sizeof(unsigned int));
    cudaFuncSetAttribute(dots_bf16,
                         cudaFuncAttributeMaxDynamicSharedMemorySize,
                         NSTAGE * ST_BYTES);

    dim3 blk(256);

    // projections: q,k write fp32 + bf16 copies; v plain fp32
    sgemm128<true><<<dim3(DIM / 128, BATCH / 128), blk>>>(
        x, Wq, bq, q, qb, BATCH, DIM, DIM);
    sgemm128<true><<<dim3(DIM / 128, VOC / 128), blk>>>(
        cb, Wk, bk, k, kb, VOC, DIM, DIM);
    sgemm128<false><<<dim3(DIM / 128, VOC / 128), blk>>>(
        cb, Wv, bv, v, nullptr, VOC, DIM, DIM);

    // approx dots = qb @ kb^T (bf16 m16n8k16, ldmatrix frags)
    dots_bf16<<<dim3(BATCH / MT, VOC / NT), blk, NSTAGE * ST_BYTES>>>(
        qb, kb, dots);

    // approx select (margin) + exact rescore + softmax + sparse gather of v
    topk_softmax_gather<<<BATCH, TT, VOC * (int)sizeof(unsigned int)>>>(
        dots, q, k, v, out);
}

// round 10
// speedup vs baseline: 2.5928x; 1.2408x over previous
#include <cuda_runtime.h>
#include <cuda_bf16.h>
#include <cstdint>

#define VOC   32768
#define DIM   512
#define BATCH 4096
#define TOPK  64
#define MAXSEL 192
#define MARGIN 0.02f

// dots tile config (mma.sync bf16 m16n8k16): CTA 128x128, 8 warps of 32x64
#define MT 128
#define NT 128
#define KCH 32                   // bf16 elements per K chunk
#define KITERS (DIM / KCH)       // 16
#define LDH 40                   // halves per smem row (KCH + 8 pad)
#define A_HALVES (MT * LDH)      // 5120
#define ST_HALVES (2 * A_HALVES) // 10240
#define ST_BYTES  (ST_HALVES * 2)   // 20480
#define NSTAGE 4

// ---------------- scratch (static device globals; no allocation allowed) ----
__device__ float g_q [(size_t)BATCH * DIM];
__device__ float g_k [(size_t)VOC * DIM];
__device__ float g_v [(size_t)VOC * DIM];
__device__ unsigned short g_qb[(size_t)BATCH * DIM];
__device__ unsigned short g_kb[(size_t)VOC * DIM];
__device__ unsigned short g_dots16[(size_t)BATCH * VOC];   // 256 MB bf16 approx

// ---------------- PTX helpers ------------------------------------------------
__device__ __forceinline__ uint32_t smem_u32(const void* p) {
    uint32_t a;
    asm("{ .reg .u64 t; cvta.to.shared.u64 t, %1; cvt.u32.u64 %0, t; }"
        : "=r"(a) : "l"(p));
    return a;
}
#define CP_ASYNC16(dst, src) \
    asm volatile("cp.async.cg.shared.global [%0], [%1], 16;" \
                 :: "r"(dst), "l"(src) : "memory")
#define CP_COMMIT()  asm volatile("cp.async.commit_group;" ::: "memory")

__device__ __forceinline__ void mma_bf16(float& c0, float& c1, float& c2, float& c3,
                                         uint32_t a0, uint32_t a1, uint32_t a2, uint32_t a3,
                                         uint32_t b0, uint32_t b1) {
    asm volatile(
        "mma.sync.aligned.m16n8k16.row.col.f32.bf16.bf16.f32 "
        "{%0,%1,%2,%3}, {%4,%5,%6,%7}, {%8,%9}, {%0,%1,%2,%3};"
        : "+f"(c0), "+f"(c1), "+f"(c2), "+f"(c3)
        : "r"(a0), "r"(a1), "r"(a2), "r"(a3), "r"(b0), "r"(b1));
}

__device__ __forceinline__ void ldsm4(uint32_t& r0, uint32_t& r1,
                                      uint32_t& r2, uint32_t& r3, uint32_t addr) {
    asm volatile("ldmatrix.sync.aligned.m8n8.x4.shared.b16 {%0,%1,%2,%3}, [%4];"
                 : "=r"(r0), "=r"(r1), "=r"(r2), "=r"(r3) : "r"(addr));
}

// ---------------- misc helpers ----------------------------------------------
// order-preserving u16 key for bf16 bit patterns
__device__ __forceinline__ unsigned int f2k16(unsigned int b) {
    return (b & 0x8000u) ? ((~b) & 0xFFFFu) : (b | 0x8000u);
}
__device__ __forceinline__ float k16tof(unsigned int k) {
    unsigned int b = (k & 0x8000u) ? (k ^ 0x8000u) : ((~k) & 0xFFFFu);
    unsigned int f = b << 16;
    return __uint_as_float(f);
}
__device__ __forceinline__ unsigned int ftok16(float x) {
    unsigned int b = __bfloat16_as_ushort(__float2bfloat16(x));
    return f2k16(b);
}

// ---------------- SGEMM (fp32, FFMA) for q/k/v projections -------------------
// WB: additionally write bf16 copy of (acc+bias) to Cb.
template <bool WB>
__global__ __launch_bounds__(256)
void sgemm128(const float* __restrict__ A, const float* __restrict__ B,
              const float* __restrict__ bias, float* __restrict__ C,
              unsigned short* __restrict__ Cb,
              int M, int N, int K)
{
    __shared__ float As[8][128];
    __shared__ float Bs[8][128];

    const int tid = threadIdx.x;
    const int bm = blockIdx.y * 128;
    const int bn = blockIdx.x * 128;

    const int a_row = tid >> 1;
    const int a_col = (tid & 1) * 4;
    const int b_row = tid >> 5;
    const int b_col = (tid & 31) * 4;

    const int tx = tid & 15;
    const int ty = tid >> 4;

    float acc[8][8];
#pragma unroll
    for (int i = 0; i < 8; i++)
#pragma unroll
        for (int j = 0; j < 8; j++) acc[i][j] = 0.0f;

    for (int k0 = 0; k0 < K; k0 += 8) {
        float4 av = *reinterpret_cast<const float4*>(
            A + (size_t)(bm + a_row) * K + (k0 + a_col));
        As[a_col + 0][a_row] = av.x;
        As[a_col + 1][a_row] = av.y;
        As[a_col + 2][a_row] = av.z;
        As[a_col + 3][a_row] = av.w;

        float4 bv = *reinterpret_cast<const float4*>(
            B + (size_t)(k0 + b_row) * N + (bn + b_col));
        *reinterpret_cast<float4*>(&Bs[b_row][b_col]) = bv;
        __syncthreads();

#pragma unroll
        for (int kk = 0; kk < 8; kk++) {
            float af[8], bf[8];
            float4 t;
            t = *reinterpret_cast<const float4*>(&As[kk][ty * 8]);
            af[0] = t.x; af[1] = t.y; af[2] = t.z; af[3] = t.w;
            t = *reinterpret_cast<const float4*>(&As[kk][ty * 8 + 4]);
            af[4] = t.x; af[5] = t.y; af[6] = t.z; af[7] = t.w;
            t = *reinterpret_cast<const float4*>(&Bs[kk][tx * 8]);
            bf[0] = t.x; bf[1] = t.y; bf[2] = t.z; bf[3] = t.w;
            t = *reinterpret_cast<const float4*>(&Bs[kk][tx * 8 + 4]);
            bf[4] = t.x; bf[5] = t.y; bf[6] = t.z; bf[7] = t.w;
#pragma unroll
            for (int i = 0; i < 8; i++)
#pragma unroll
                for (int j = 0; j < 8; j++)
                    acc[i][j] += af[i] * bf[j];
        }
        __syncthreads();
    }

#pragma unroll
    for (int i = 0; i < 8; i++) {
        const int row = bm + ty * 8 + i;
        const int col = bn + tx * 8;
#pragma unroll
        for (int j = 0; j < 8; j += 4) {
            float o[4];
#pragma unroll
            for (int t = 0; t < 4; t++) {
                o[t] = acc[i][j + t];
                o[t] += bias[col + j + t];
            }
            float4 v4;
            v4.x = o[0]; v4.y = o[1]; v4.z = o[2]; v4.w = o[3];
            *reinterpret_cast<float4*>(C + (size_t)row * N + col + j) = v4;
            if (WB) {
                ushort4 ub;
                ub.x = __bfloat16_as_ushort(__float2bfloat16(o[0]));
                ub.y = __bfloat16_as_ushort(__float2bfloat16(o[1]));
                ub.z = __bfloat16_as_ushort(__float2bfloat16(o[2]));
                ub.w = __bfloat16_as_ushort(__float2bfloat16(o[3]));
                *reinterpret_cast<ushort4*>(Cb + (size_t)row * N + col + j) = ub;
            }
        }
    }
}

// ---------------- dots_approx = qb @ kb^T via bf16 m16n8k16 mma --------------
// CTA 128x128, 8 warps (4m x 2n) of 32x64, K chunks of 32 bf16, 4-stage pipeline.
// Output written as bf16 (packed pairs).
__global__ __launch_bounds__(256, 2)
void dots_bf16(const unsigned short* __restrict__ Ab,
               const unsigned short* __restrict__ Bb,
               unsigned short* __restrict__ C16)
{
    extern __shared__ __align__(16) unsigned short smem[];
    const uint32_t sb = smem_u32(smem);

    const int tid = threadIdx.x;
    const int lane = tid & 31;
    const int wid = tid >> 5;
    const int warpM = wid >> 1;       // 0..3 -> 32 rows each
    const int warpN = wid & 1;        // 0..1 -> 64 cols each
    const int bm = blockIdx.x * MT;   // m fastest -> q tiles stay L2 resident
    const int bn = blockIdx.y * NT;

    const int r = lane >> 2;          // 0..7
    const int c4 = lane & 3;          // 0..3

    float acc[2][8][4];
#pragma unroll
    for (int mt = 0; mt < 2; mt++)
#pragma unroll
        for (int nt = 0; nt < 8; nt++)
#pragma unroll
            for (int i = 0; i < 4; i++) acc[mt][nt][i] = 0.0f;

    const int isB = tid >> 7;         // 0: A row, 1: B row
    const int prow = tid & 127;
    const unsigned short* gbase = (isB ? Bb + (size_t)(bn + prow) * DIM
                                       : Ab + (size_t)(bm + prow) * DIM);
    const uint32_t dbase = sb + ((isB ? A_HALVES : 0) + (uint32_t)prow * LDH) * 2;

    auto prefetch = [&](int it, int s) {
        const unsigned short* g = gbase + it * KCH;
        const uint32_t d = dbase + (uint32_t)s * ST_BYTES;
#pragma unroll
        for (int c = 0; c < 4; c++)
            CP_ASYNC16(d + c * 16, g + c * 8);
        CP_COMMIT();
    };

    prefetch(0, 0);
    prefetch(1, 1);
    prefetch(2, 2);

    const int l8 = lane & 7;
    const int gq = lane >> 3;         // 0..3 quad group
    uint32_t aoffb[2];
#pragma unroll
    for (int mt = 0; mt < 2; mt++) {
        const int row = warpM * 32 + mt * 16 + l8 + (gq & 1) * 8;
        const int col = (gq >> 1) * 8;
        aoffb[mt] = ((uint32_t)row * LDH + col) * 2;
    }
    uint32_t boffb[4];
#pragma unroll
    for (int p = 0; p < 4; p++) {
        const int row = warpN * 64 + p * 16 + l8 + (gq >> 1) * 8;
        const int col = (gq & 1) * 8;
        boffb[p] = ((uint32_t)A_HALVES + (uint32_t)row * LDH + col) * 2;
    }

    for (int it = 0; it < KITERS; it++) {
        if (it + 2 < KITERS)
            asm volatile("cp.async.wait_group %0;" :: "n"(2));
        else if (it + 1 < KITERS)
            asm volatile("cp.async.wait_group %0;" :: "n"(1));
        else
            asm volatile("cp.async.wait_group %0;" :: "n"(0));
        __syncthreads();

        if (it + 3 < KITERS)
            prefetch(it + 3, (it + 3) & 3);

        const uint32_t stb = sb + (uint32_t)(it & 3) * ST_BYTES;

#pragma unroll
        for (int ks = 0; ks < 2; ks++) {
            const uint32_t koff = (uint32_t)ks * 32;   // 16 halves
            uint32_t a[2][4], b[4][4];
#pragma unroll
            for (int mt = 0; mt < 2; mt++)
                ldsm4(a[mt][0], a[mt][1], a[mt][2], a[mt][3],
                      stb + aoffb[mt] + koff);
#pragma unroll
            for (int p = 0; p < 4; p++)
                ldsm4(b[p][0], b[p][1], b[p][2], b[p][3],
                      stb + boffb[p] + koff);
#pragma unroll
            for (int mt = 0; mt < 2; mt++)
#pragma unroll
                for (int p = 0; p < 4; p++) {
                    float* a0 = acc[mt][2 * p];
                    float* a1 = acc[mt][2 * p + 1];
                    mma_bf16(a0[0], a0[1], a0[2], a0[3],
                             a[mt][0], a[mt][1], a[mt][2], a[mt][3],
                             b[p][0], b[p][1]);
                    mma_bf16(a1[0], a1[1], a1[2], a1[3],
                             a[mt][0], a[mt][1], a[mt][2], a[mt][3],
                             b[p][2], b[p][3]);
                }
        }
    }

    // epilogue: pack bf16 pairs (cols col, col+1), rows r and r+8
#pragma unroll
    for (int mt = 0; mt < 2; mt++) {
        const int row = bm + warpM * 32 + mt * 16 + r;
#pragma unroll
        for (int nt = 0; nt < 8; nt++) {
            const int col = bn + warpN * 64 + nt * 8 + 2 * c4;
            const float* a = acc[mt][nt];
            unsigned int p0 = (unsigned int)__bfloat16_as_ushort(__float2bfloat16(a[0]))
                            | ((unsigned int)__bfloat16_as_ushort(__float2bfloat16(a[1])) << 16);
            unsigned int p1 = (unsigned int)__bfloat16_as_ushort(__float2bfloat16(a[2]))
                            | ((unsigned int)__bfloat16_as_ushort(__float2bfloat16(a[3])) << 16);
            *reinterpret_cast<unsigned int*>(C16 + (size_t)row * VOC + col) = p0;
            *reinterpret_cast<unsigned int*>(C16 + (size_t)(row + 8) * VOC + col) = p1;
        }
    }
}

// ---------------- per-row: approx select + exact rescore + softmax + A@V ----
#define TT 512
__global__ __launch_bounds__(TT, 2)
void topk_softmax_gather(const unsigned short* __restrict__ dots16,
                         const float* __restrict__ Q,
                         const float* __restrict__ Kf,
                         const float* __restrict__ v,
                         float* __restrict__ out)
{
    extern __shared__ unsigned short keys16[];        // VOC u16 = 64KB
    __shared__ unsigned int hist[256];
    __shared__ unsigned int scanbuf[2][256];
    __shared__ unsigned int cscan[2][TT];
    __shared__ float        f_red[TT];
    __shared__ float qrow[DIM];
    __shared__ int   sel_idx[MAXSEL];
    __shared__ float sel_val[MAXSEL];
    __shared__ float sel_w[MAXSEL];
    __shared__ unsigned int s_bucket;
    __shared__ int s_r;
    __shared__ unsigned int s_thresh;

    const int tid = threadIdx.x;
    const int lane = tid & 31;
    const int wid = tid >> 5;
    const int row = blockIdx.x;
    const unsigned int* drow = reinterpret_cast<const unsigned int*>(
        dots16 + (size_t)row * VOC);

    // ---- phase 1: load bf16 row (as u32 pairs), convert to sortable u16 ----
    for (int i = tid; i < VOC / 2; i += TT) {
        const unsigned int w = drow[i];
        const unsigned int k0 = f2k16(w & 0xFFFFu);
        const unsigned int k1 = f2k16(w >> 16);
        reinterpret_cast<unsigned int*>(keys16)[i] = k0 | (k1 << 16);
    }
    if (tid < DIM)
        qrow[tid] = Q[(size_t)row * DIM + tid];
    __syncthreads();

    // ---- phase 2a: radix pass on high byte (warp-aggregated atomics) ----
    if (tid < 256) hist[tid] = 0;
    __syncthreads();
    for (int i = tid; i < VOC; i += TT) {
        const unsigned int bin = (unsigned int)keys16[i] >> 8;
        const unsigned int mask = __match_any_sync(0xFFFFFFFFu, bin);
        if ((__ffs(mask) - 1) == lane)
            atomicAdd(&hist[bin], (unsigned int)__popc(mask));
    }
    __syncthreads();
    {
        if (tid < 256) scanbuf[0][tid] = hist[tid];
        __syncthreads();
        int src = 0;
        for (int off = 1; off < 256; off <<= 1) {
            unsigned int val = 0;
            if (tid < 256) {
                val = scanbuf[src][tid];
                if (tid + off < 256) val += scanbuf[src][tid + off];
            }
            __syncthreads();
            if (tid < 256) scanbuf[src ^ 1][tid] = val;
            __syncthreads();
            src ^= 1;
        }
        if (tid < 256) {
            const unsigned int cumb  = scanbuf[src][tid];
            const unsigned int cumb1 = (tid == 255) ? 0u : scanbuf[src][tid + 1];
            if (cumb >= TOPK && cumb1 < TOPK) {
                s_bucket = (unsigned int)tid;
                s_r = TOPK - (int)cumb1;
            }
        }
        __syncthreads();
    }
    const unsigned int bucket = s_bucket;
    const int r1 = s_r;
    __syncthreads();

    // ---- phase 2b: radix pass on low byte within bucket ----
    if (tid < 256) hist[tid] = 0;
    __syncthreads();
    for (int i = tid; i < VOC; i += TT) {
        const unsigned int k = keys16[i];
        if ((k >> 8) == bucket)
            atomicAdd(&hist[k & 0xFFu], 1u);
    }
    __syncthreads();
    {
        if (tid < 256) scanbuf[0][tid] = hist[tid];
        __syncthreads();
        int src = 0;
        for (int off = 1; off < 256; off <<= 1) {
            unsigned int val = 0;
            if (tid < 256) {
                val = scanbuf[src][tid];
                if (tid + off < 256) val += scanbuf[src][tid + off];
            }
            __syncthreads();
            if (tid < 256) scanbuf[src ^ 1][tid] = val;
            __syncthreads();
            src ^= 1;
        }
        if (tid < 256) {
            const unsigned int cumb  = scanbuf[src][tid];
            const unsigned int cumb1 = (tid == 255) ? 0u : scanbuf[src][tid + 1];
            if (cumb >= (unsigned int)r1 && cumb1 < (unsigned int)r1)
                s_thresh = (bucket << 8) | (unsigned int)tid;
        }
        __syncthreads();
    }
    // widen threshold by margin (bf16 mma + storage quantization bound)
    const unsigned int cut16 = ftok16(k16tof(s_thresh) - MARGIN);

    // ---- phase 3: deterministic compaction of candidate indices ----
    int c = 0;
    for (int i = tid; i < VOC; i += TT)
        if ((unsigned int)keys16[i] >= cut16) c++;
    cscan[0][tid] = (unsigned int)c;
    __syncthreads();
    int src = 0;
    for (int off = 1; off < TT; off <<= 1) {
        unsigned int val = cscan[src][tid];
        if (tid >= off) val += cscan[src][tid - off];
        __syncthreads();
        cscan[src ^ 1][tid] = val;
        __syncthreads();
        src ^= 1;
    }
    int pos = (tid == 0) ? 0 : (int)cscan[src][tid - 1];
    const int count = min((int)cscan[src][TT - 1], MAXSEL);

    for (int i = tid; i < VOC; i += TT) {
        if ((unsigned int)keys16[i] >= cut16) {
            if (pos < MAXSEL) sel_idx[pos] = i;
            pos++;
        }
    }
    __syncthreads();

    // ---- phase 4: exact fp32 rescore of candidates (one warp per cand) ----
    for (int s = wid; s < count; s += (TT / 32)) {
        const int idx = sel_idx[s];
        const float4* kr = reinterpret_cast<const float4*>(Kf + (size_t)idx * DIM);
        float sum = 0.0f;
#pragma unroll
        for (int j = 0; j < 4; j++) {
            const float4 a = kr[lane * 4 + j];
            const float4 qv = *reinterpret_cast<const float4*>(&qrow[lane * 16 + j * 4]);
            sum += qv.x * a.x + qv.y * a.y + qv.z * a.z + qv.w * a.w;
        }
#pragma unroll
        for (int off = 16; off > 0; off >>= 1)
            sum += __shfl_xor_sync(0xFFFFFFFFu, sum, off);
        if (lane == 0) sel_val[s] = sum;
    }
    __syncthreads();

    // ---- phase 5: exact top-64 rule + softmax weights ----
    float mx = -3.4e38f;
    if (tid < count) mx = sel_val[tid];
    f_red[tid] = mx;
    __syncthreads();
#pragma unroll
    for (int s = TT / 2; s > 0; s >>= 1) {
        if (tid < s) f_red[tid] = fmaxf(f_red[tid], f_red[tid + s]);
        __syncthreads();
    }
    const float m = f_red[0];

    if (tid < count) {
        const float mine = sel_val[tid];
        int greater = 0;
        for (int j = 0; j < count; j++)
            greater += (sel_val[j] > mine);
        sel_w[tid] = (greater < TOPK) ? expf(mine - m) : 0.0f;
    }
    __syncthreads();

    float z = (tid < count) ? sel_w[tid] : 0.0f;
    f_red[tid] = z;
    __syncthreads();
#pragma unroll
    for (int s = TT / 2; s > 0; s >>= 1) {
        if (tid < s) f_red[tid] += f_red[tid + s];
        __syncthreads();
    }
    const float Z = f_red[0];

    // ---- phase 6: out[row] = (1/Z) * sum_s w_s * v[idx_s] ----
    float acc0 = 0.0f;
    for (int s = 0; s < count; s++)
        acc0 += sel_w[s] * v[(size_t)sel_idx[s] * DIM + tid];
    out[(size_t)row * DIM + tid] = acc0 / Z;
}

// ---------------- launch ----------------------------------------------------
extern "C" void kernel_launch(void* const* d_in, const int* in_sizes, int n_in,
                              void* d_out, int out_size)
{
    const float* x  = (const float*)d_in[0];
    const float* cb = (const float*)d_in[1];
    const float* Wq = (const float*)d_in[2];
    const float* bq = (const float*)d_in[3];
    const float* Wk = (const float*)d_in[4];
    const float* bk = (const float*)d_in[5];
    const float* Wv = (const float*)d_in[6];
    const float* bv = (const float*)d_in[7];
    float* out = (float*)d_out;

    float *q, *k, *v;
    unsigned short *qb, *kb, *dots16;
    cudaGetSymbolAddress((void**)&q,      g_q);
    cudaGetSymbolAddress((void**)&k,      g_k);
    cudaGetSymbolAddress((void**)&v,      g_v);
    cudaGetSymbolAddress((void**)&qb,     g_qb);
    cudaGetSymbolAddress((void**)&kb,     g_kb);
    cudaGetSymbolAddress((void**)&dots16, g_dots16);

    cudaFuncSetAttribute(topk_softmax_gather,
                         cudaFuncAttributeMaxDynamicSharedMemorySize,
                         VOC * (int)sizeof(unsigned short));
    cudaFuncSetAttribute(dots_bf16,
                         cudaFuncAttributeMaxDynamicSharedMemorySize,
                         NSTAGE * ST_BYTES);

    dim3 blk(256);

    // projections: q,k write fp32 + bf16 copies; v plain fp32
    sgemm128<true><<<dim3(DIM / 128, BATCH / 128), blk>>>(
        x, Wq, bq, q, qb, BATCH, DIM, DIM);
    sgemm128<true><<<dim3(DIM / 128, VOC / 128), blk>>>(
        cb, Wk, bk, k, kb, VOC, DIM, DIM);
    sgemm128<false><<<dim3(DIM / 128, VOC / 128), blk>>>(
        cb, Wv, bv, v, nullptr, VOC, DIM, DIM);

    // approx dots = qb @ kb^T (bf16 m16n8k16), stored as bf16
    dots_bf16<<<dim3(BATCH / MT, VOC / NT), blk, NSTAGE * ST_BYTES>>>(
        qb, kb, dots16);

    // approx select (margin) + exact rescore + softmax + sparse gather of v
    topk_softmax_gather<<<BATCH, TT, VOC * (int)sizeof(unsigned short)>>>(
        dots16, q, k, v, out);
}

// round 12
// speedup vs baseline: 2.6646x; 1.0277x over previous
#include <cuda_runtime.h>
#include <cuda_bf16.h>
#include <cstdint>

#define VOC   32768
#define DIM   512
#define BATCH 4096
#define TOPK  64
#define MAXSEL 192
#define MARGIN 0.02f

// dots tile config (mma.sync bf16 m16n8k16): CTA 128x128, 8 warps of 32x64
#define MT 128
#define NT 128
#define KCH 64                   // bf16 elements per K chunk
#define KITERS (DIM / KCH)       // 8
#define LDH 72                   // halves per smem row (KCH + 8 pad)
#define A_HALVES (MT * LDH)      // 9216
#define ST_HALVES (2 * A_HALVES) // 18432
#define ST_BYTES  (ST_HALVES * 2)   // 36864
#define NSTAGE 2

// ---------------- scratch (static device globals; no allocation allowed) ----
__device__ float g_q [(size_t)BATCH * DIM];
__device__ float g_k [(size_t)VOC * DIM];
__device__ float g_v [(size_t)VOC * DIM];
__device__ unsigned short g_qb[(size_t)BATCH * DIM];
__device__ unsigned short g_kb[(size_t)VOC * DIM];
__device__ unsigned short g_dots16[(size_t)BATCH * VOC];   // 256 MB bf16 approx

// ---------------- PTX helpers ------------------------------------------------
__device__ __forceinline__ uint32_t smem_u32(const void* p) {
    uint32_t a;
    asm("{ .reg .u64 t; cvta.to.shared.u64 t, %1; cvt.u32.u64 %0, t; }"
        : "=r"(a) : "l"(p));
    return a;
}
#define CP_ASYNC16(dst, src) \
    asm volatile("cp.async.cg.shared.global [%0], [%1], 16;" \
                 :: "r"(dst), "l"(src) : "memory")
#define CP_COMMIT()  asm volatile("cp.async.commit_group;" ::: "memory")

__device__ __forceinline__ void mma_bf16(float& c0, float& c1, float& c2, float& c3,
                                         uint32_t a0, uint32_t a1, uint32_t a2, uint32_t a3,
                                         uint32_t b0, uint32_t b1) {
    asm volatile(
        "mma.sync.aligned.m16n8k16.row.col.f32.bf16.bf16.f32 "
        "{%0,%1,%2,%3}, {%4,%5,%6,%7}, {%8,%9}, {%0,%1,%2,%3};"
        : "+f"(c0), "+f"(c1), "+f"(c2), "+f"(c3)
        : "r"(a0), "r"(a1), "r"(a2), "r"(a3), "r"(b0), "r"(b1));
}

__device__ __forceinline__ void ldsm4(uint32_t& r0, uint32_t& r1,
                                      uint32_t& r2, uint32_t& r3, uint32_t addr) {
    asm volatile("ldmatrix.sync.aligned.m8n8.x4.shared.b16 {%0,%1,%2,%3}, [%4];"
                 : "=r"(r0), "=r"(r1), "=r"(r2), "=r"(r3) : "r"(addr));
}

// ---------------- misc helpers ----------------------------------------------
// order-preserving u16 key for bf16 bit patterns
__device__ __forceinline__ unsigned int f2k16(unsigned int b) {
    return (b & 0x8000u) ? ((~b) & 0xFFFFu) : (b | 0x8000u);
}
__device__ __forceinline__ float k16tof(unsigned int k) {
    unsigned int b = (k & 0x8000u) ? (k ^ 0x8000u) : ((~k) & 0xFFFFu);
    unsigned int f = b << 16;
    return __uint_as_float(f);
}
__device__ __forceinline__ unsigned int ftok16(float x) {
    unsigned int b = __bfloat16_as_ushort(__float2bfloat16(x));
    return f2k16(b);
}

// ---------------- SGEMM (fp32, FFMA) for q/k/v projections -------------------
// Register double-buffered: LDG for chunk i+1 overlaps compute of chunk i.
// WB: additionally write bf16 copy of (acc+bias) to Cb.
template <bool WB>
__global__ __launch_bounds__(256)
void sgemm128(const float* __restrict__ A, const float* __restrict__ B,
              const float* __restrict__ bias, float* __restrict__ C,
              unsigned short* __restrict__ Cb,
              int M, int N, int K)
{
    __shared__ float As[8][128];
    __shared__ float Bs[8][128];

    const int tid = threadIdx.x;
    const int bm = blockIdx.y * 128;
    const int bn = blockIdx.x * 128;

    const int a_row = tid >> 1;
    const int a_col = (tid & 1) * 4;
    const int b_row = tid >> 5;
    const int b_col = (tid & 31) * 4;

    const int tx = tid & 15;
    const int ty = tid >> 4;

    float acc[8][8];
#pragma unroll
    for (int i = 0; i < 8; i++)
#pragma unroll
        for (int j = 0; j < 8; j++) acc[i][j] = 0.0f;

    const float* Aptr = A + (size_t)(bm + a_row) * K + a_col;
    const float* Bptr = B + (size_t)b_row * N + (bn + b_col);

    float4 av = *reinterpret_cast<const float4*>(Aptr);
    float4 bv = *reinterpret_cast<const float4*>(Bptr);

    for (int k0 = 0; k0 < K; k0 += 8) {
        // stage current chunk regs -> smem
        As[a_col + 0][a_row] = av.x;
        As[a_col + 1][a_row] = av.y;
        As[a_col + 2][a_row] = av.z;
        As[a_col + 3][a_row] = av.w;
        *reinterpret_cast<float4*>(&Bs[b_row][b_col]) = bv;
        __syncthreads();

        // prefetch next chunk (hidden behind compute)
        if (k0 + 8 < K) {
            av = *reinterpret_cast<const float4*>(Aptr + k0 + 8);
            bv = *reinterpret_cast<const float4*>(Bptr + (size_t)(k0 + 8) * N);
        }

#pragma unroll
        for (int kk = 0; kk < 8; kk++) {
            float af[8], bf[8];
            float4 t;
            t = *reinterpret_cast<const float4*>(&As[kk][ty * 8]);
            af[0] = t.x; af[1] = t.y; af[2] = t.z; af[3] = t.w;
            t = *reinterpret_cast<const float4*>(&As[kk][ty * 8 + 4]);
            af[4] = t.x; af[5] = t.y; af[6] = t.z; af[7] = t.w;
            t = *reinterpret_cast<const float4*>(&Bs[kk][tx * 8]);
            bf[0] = t.x; bf[1] = t.y; bf[2] = t.z; bf[3] = t.w;
            t = *reinterpret_cast<const float4*>(&Bs[kk][tx * 8 + 4]);
            bf[4] = t.x; bf[5] = t.y; bf[6] = t.z; bf[7] = t.w;
#pragma unroll
            for (int i = 0; i < 8; i++)
#pragma unroll
                for (int j = 0; j < 8; j++)
                    acc[i][j] += af[i] * bf[j];
        }
        __syncthreads();
    }

#pragma unroll
    for (int i = 0; i < 8; i++) {
        const int row = bm + ty * 8 + i;
        const int col = bn + tx * 8;
#pragma unroll
        for (int j = 0; j < 8; j += 4) {
            float o[4];
#pragma unroll
            for (int t = 0; t < 4; t++) {
                o[t] = acc[i][j + t];
                o[t] += bias[col + j + t];
            }
            float4 v4;
            v4.x = o[0]; v4.y = o[1]; v4.z = o[2]; v4.w = o[3];
            *reinterpret_cast<float4*>(C + (size_t)row * N + col + j) = v4;
            if (WB) {
                ushort4 ub;
                ub.x = __bfloat16_as_ushort(__float2bfloat16(o[0]));
                ub.y = __bfloat16_as_ushort(__float2bfloat16(o[1]));
                ub.z = __bfloat16_as_ushort(__float2bfloat16(o[2]));
                ub.w = __bfloat16_as_ushort(__float2bfloat16(o[3]));
                *reinterpret_cast<ushort4*>(Cb + (size_t)row * N + col + j) = ub;
            }
        }
    }
}

// ---------------- dots_approx = qb @ kb^T via bf16 m16n8k16 mma --------------
// CTA 128x128, 8 warps (4m x 2n) of 32x64, K chunks of 64 bf16, 2-stage pipeline.
// Prefetch into the current stage happens only AFTER the post-compute barrier
// (2 stages: (it+2)&1 == it&1, so overwriting before that barrier would race).
__global__ __launch_bounds__(256, 2)
void dots_bf16(const unsigned short* __restrict__ Ab,
               const unsigned short* __restrict__ Bb,
               unsigned short* __restrict__ C16)
{
    extern __shared__ __align__(16) unsigned short smem[];
    const uint32_t sb = smem_u32(smem);

    const int tid = threadIdx.x;
    const int lane = tid & 31;
    const int wid = tid >> 5;
    const int warpM = wid >> 1;       // 0..3 -> 32 rows each
    const int warpN = wid & 1;        // 0..1 -> 64 cols each
    const int bm = blockIdx.x * MT;   // m fastest -> q tiles stay L2 resident
    const int bn = blockIdx.y * NT;

    const int r = lane >> 2;          // 0..7
    const int c4 = lane & 3;          // 0..3

    float acc[2][8][4];
#pragma unroll
    for (int mt = 0; mt < 2; mt++)
#pragma unroll
        for (int nt = 0; nt < 8; nt++)
#pragma unroll
            for (int i = 0; i < 4; i++) acc[mt][nt][i] = 0.0f;

    const int isB = tid >> 7;         // 0: A row, 1: B row
    const int prow = tid & 127;
    const unsigned short* gbase = (isB ? Bb + (size_t)(bn + prow) * DIM
                                       : Ab + (size_t)(bm + prow) * DIM);
    const uint32_t dbase = sb + ((isB ? A_HALVES : 0) + (uint32_t)prow * LDH) * 2;

    // prefetch K-chunk `it` (64 halves = 128B per row) into stage `s`
    auto prefetch = [&](int it, int s) {
        const unsigned short* g = gbase + it * KCH;
        const uint32_t d = dbase + (uint32_t)s * ST_BYTES;
#pragma unroll
        for (int c = 0; c < 8; c++)
            CP_ASYNC16(d + c * 16, g + c * 8);
        CP_COMMIT();
    };

    prefetch(0, 0);
    prefetch(1, 1);

    const int l8 = lane & 7;
    const int gq = lane >> 3;         // 0..3 quad group
    uint32_t aoffb[2];
#pragma unroll
    for (int mt = 0; mt < 2; mt++) {
        const int row = warpM * 32 + mt * 16 + l8 + (gq & 1) * 8;
        const int col = (gq >> 1) * 8;
        aoffb[mt] = ((uint32_t)row * LDH + col) * 2;
    }
    uint32_t boffb[4];
#pragma unroll
    for (int p = 0; p < 4; p++) {
        const int row = warpN * 64 + p * 16 + l8 + (gq >> 1) * 8;
        const int col = (gq & 1) * 8;
        boffb[p] = ((uint32_t)A_HALVES + (uint32_t)row * LDH + col) * 2;
    }

    for (int it = 0; it < KITERS; it++) {
        if (it + 1 < KITERS)
            asm volatile("cp.async.wait_group %0;" :: "n"(1));
        else
            asm volatile("cp.async.wait_group %0;" :: "n"(0));
        __syncthreads();

        const uint32_t stb = sb + (uint32_t)(it & 1) * ST_BYTES;

#pragma unroll
        for (int ks = 0; ks < 4; ks++) {
            const uint32_t koff = (uint32_t)ks * 32;   // 16 halves
            uint32_t a[2][4], b[4][4];
#pragma unroll
            for (int mt = 0; mt < 2; mt++)
                ldsm4(a[mt][0], a[mt][1], a[mt][2], a[mt][3],
                      stb + aoffb[mt] + koff);
#pragma unroll
            for (int p = 0; p < 4; p++)
                ldsm4(b[p][0], b[p][1], b[p][2], b[p][3],
                      stb + boffb[p] + koff);
#pragma unroll
            for (int mt = 0; mt < 2; mt++)
#pragma unroll
                for (int p = 0; p < 4; p++) {
                    float* a0 = acc[mt][2 * p];
                    float* a1 = acc[mt][2 * p + 1];
                    mma_bf16(a0[0], a0[1], a0[2], a0[3],
                             a[mt][0], a[mt][1], a[mt][2], a[mt][3],
                             b[p][0], b[p][1]);
                    mma_bf16(a1[0], a1[1], a1[2], a1[3],
                             a[mt][0], a[mt][1], a[mt][2], a[mt][3],
                             b[p][2], b[p][3]);
                }
        }

        // overwrite of stage (it&1) is only safe after ALL warps finished
        // reading it; the in-flight group for stage (it+1)&1 still overlaps.
        if (it + 2 < KITERS) {
            __syncthreads();
            prefetch(it + 2, it & 1);
        }
    }

    // epilogue: pack bf16 pairs (cols col, col+1), rows r and r+8
#pragma unroll
    for (int mt = 0; mt < 2; mt++) {
        const int row = bm + warpM * 32 + mt * 16 + r;
#pragma unroll
        for (int nt = 0; nt < 8; nt++) {
            const int col = bn + warpN * 64 + nt * 8 + 2 * c4;
            const float* a = acc[mt][nt];
            unsigned int p0 = (unsigned int)__bfloat16_as_ushort(__float2bfloat16(a[0]))
                            | ((unsigned int)__bfloat16_as_ushort(__float2bfloat16(a[1])) << 16);
            unsigned int p1 = (unsigned int)__bfloat16_as_ushort(__float2bfloat16(a[2]))
                            | ((unsigned int)__bfloat16_as_ushort(__float2bfloat16(a[3])) << 16);
            *reinterpret_cast<unsigned int*>(C16 + (size_t)row * VOC + col) = p0;
            *reinterpret_cast<unsigned int*>(C16 + (size_t)(row + 8) * VOC + col) = p1;
        }
    }
}

// ---------------- per-row: approx select + exact rescore + softmax + A@V ----
#define TT 512
__global__ __launch_bounds__(TT, 2)
void topk_softmax_gather(const unsigned short* __restrict__ dots16,
                         const float* __restrict__ Q,
                         const float* __restrict__ Kf,
                         const float* __restrict__ v,
                         float* __restrict__ out)
{
    extern __shared__ unsigned short keys16[];        // VOC u16 = 64KB
    __shared__ unsigned int hist[256];
    __shared__ unsigned int scanbuf[2][256];
    __shared__ unsigned int cscan[2][TT];
    __shared__ float        f_red[TT];
    __shared__ float qrow[DIM];
    __shared__ int   sel_idx[MAXSEL];
    __shared__ float sel_val[MAXSEL];
    __shared__ float sel_w[MAXSEL];
    __shared__ unsigned int s_bucket;
    __shared__ int s_r;
    __shared__ unsigned int s_thresh;

    const int tid = threadIdx.x;
    const int lane = tid & 31;
    const int wid = tid >> 5;
    const int row = blockIdx.x;
    const unsigned int* drow = reinterpret_cast<const unsigned int*>(
        dots16 + (size_t)row * VOC);

    // ---- phase 1: load bf16 row (as u32 pairs), convert to sortable u16 ----
    for (int i = tid; i < VOC / 2; i += TT) {
        const unsigned int w = drow[i];
        const unsigned int k0 = f2k16(w & 0xFFFFu);
        const unsigned int k1 = f2k16(w >> 16);
        reinterpret_cast<unsigned int*>(keys16)[i] = k0 | (k1 << 16);
    }
    if (tid < DIM)
        qrow[tid] = Q[(size_t)row * DIM + tid];
    __syncthreads();

    // ---- phase 2a: radix pass on high byte (warp-aggregated atomics) ----
    if (tid < 256) hist[tid] = 0;
    __syncthreads();
    for (int i = tid; i < VOC; i += TT) {
        const unsigned int bin = (unsigned int)keys16[i] >> 8;
        const unsigned int mask = __match_any_sync(0xFFFFFFFFu, bin);
        if ((__ffs(mask) - 1) == lane)
            atomicAdd(&hist[bin], (unsigned int)__popc(mask));
    }
    __syncthreads();
    {
        if (tid < 256) scanbuf[0][tid] = hist[tid];
        __syncthreads();
        int src = 0;
        for (int off = 1; off < 256; off <<= 1) {
            unsigned int val = 0;
            if (tid < 256) {
                val = scanbuf[src][tid];
                if (tid + off < 256) val += scanbuf[src][tid + off];
            }
            __syncthreads();
            if (tid < 256) scanbuf[src ^ 1][tid] = val;
            __syncthreads();
            src ^= 1;
        }
        if (tid < 256) {
            const unsigned int cumb  = scanbuf[src][tid];
            const unsigned int cumb1 = (tid == 255) ? 0u : scanbuf[src][tid + 1];
            if (cumb >= TOPK && cumb1 < TOPK) {
                s_bucket = (unsigned int)tid;
                s_r = TOPK - (int)cumb1;
            }
        }
        __syncthreads();
    }
    const unsigned int bucket = s_bucket;
    const int r1 = s_r;
    __syncthreads();

    // ---- phase 2b: radix pass on low byte within bucket ----
    if (tid < 256) hist[tid] = 0;
    __syncthreads();
    for (int i = tid; i < VOC; i += TT) {
        const unsigned int k = keys16[i];
        if ((k >> 8) == bucket)
            atomicAdd(&hist[k & 0xFFu], 1u);
    }
    __syncthreads();
    {
        if (tid < 256) scanbuf[0][tid] = hist[tid];
        __syncthreads();
        int src = 0;
        for (int off = 1; off < 256; off <<= 1) {
            unsigned int val = 0;
            if (tid < 256) {
                val = scanbuf[src][tid];
                if (tid + off < 256) val += scanbuf[src][tid + off];
            }
            __syncthreads();
            if (tid < 256) scanbuf[src ^ 1][tid] = val;
            __syncthreads();
            src ^= 1;
        }
        if (tid < 256) {
            const unsigned int cumb  = scanbuf[src][tid];
            const unsigned int cumb1 = (tid == 255) ? 0u : scanbuf[src][tid + 1];
            if (cumb >= (unsigned int)r1 && cumb1 < (unsigned int)r1)
                s_thresh = (bucket << 8) | (unsigned int)tid;
        }
        __syncthreads();
    }
    // widen threshold by margin (bf16 mma + storage quantization bound)
    const unsigned int cut16 = ftok16(k16tof(s_thresh) - MARGIN);

    // ---- phase 3: deterministic compaction of candidate indices ----
    int c = 0;
    for (int i = tid; i < VOC; i += TT)
        if ((unsigned int)keys16[i] >= cut16) c++;
    cscan[0][tid] = (unsigned int)c;
    __syncthreads();
    int src = 0;
    for (int off = 1; off < TT; off <<= 1) {
        unsigned int val = cscan[src][tid];
        if (tid >= off) val += cscan[src][tid - off];
        __syncthreads();
        cscan[src ^ 1][tid] = val;
        __syncthreads();
        src ^= 1;
    }
    int pos = (tid == 0) ? 0 : (int)cscan[src][tid - 1];
    const int count = min((int)cscan[src][TT - 1], MAXSEL);

    for (int i = tid; i < VOC; i += TT) {
        if ((unsigned int)keys16[i] >= cut16) {
            if (pos < MAXSEL) sel_idx[pos] = i;
            pos++;
        }
    }
    __syncthreads();

    // ---- phase 4: exact fp32 rescore of candidates (one warp per cand) ----
    for (int s = wid; s < count; s += (TT / 32)) {
        const int idx = sel_idx[s];
        const float4* kr = reinterpret_cast<const float4*>(Kf + (size_t)idx * DIM);
        float sum = 0.0f;
#pragma unroll
        for (int j = 0; j < 4; j++) {
            const float4 a = kr[lane * 4 + j];
            const float4 qv = *reinterpret_cast<const float4*>(&qrow[lane * 16 + j * 4]);
            sum += qv.x * a.x + qv.y * a.y + qv.z * a.z + qv.w * a.w;
        }
#pragma unroll
        for (int off = 16; off > 0; off >>= 1)
            sum += __shfl_xor_sync(0xFFFFFFFFu, sum, off);
        if (lane == 0) sel_val[s] = sum;
    }
    __syncthreads();

    // ---- phase 5: exact top-64 rule + softmax weights ----
    float mx = -3.4e38f;
    if (tid < count) mx = sel_val[tid];
    f_red[tid] = mx;
    __syncthreads();
#pragma unroll
    for (int s = TT / 2; s > 0; s >>= 1) {
        if (tid < s) f_red[tid] = fmaxf(f_red[tid], f_red[tid + s]);
        __syncthreads();
    }
    const float m = f_red[0];

    if (tid < count) {
        const float mine = sel_val[tid];
        int greater = 0;
        for (int j = 0; j < count; j++)
            greater += (sel_val[j] > mine);
        sel_w[tid] = (greater < TOPK) ? expf(mine - m) : 0.0f;
    }
    __syncthreads();

    float z = (tid < count) ? sel_w[tid] : 0.0f;
    f_red[tid] = z;
    __syncthreads();
#pragma unroll
    for (int s = TT / 2; s > 0; s >>= 1) {
        if (tid < s) f_red[tid] += f_red[tid + s];
        __syncthreads();
    }
    const float Z = f_red[0];

    // ---- phase 6: out[row] = (1/Z) * sum_s w_s * v[idx_s] ----
    float acc0 = 0.0f;
    for (int s = 0; s < count; s++)
        acc0 += sel_w[s] * v[(size_t)sel_idx[s] * DIM + tid];
    out[(size_t)row * DIM + tid] = acc0 / Z;
}

// ---------------- launch ----------------------------------------------------
extern "C" void kernel_launch(void* const* d_in, const int* in_sizes, int n_in,
                              void* d_out, int out_size)
{
    const float* x  = (const float*)d_in[0];
    const float* cb = (const float*)d_in[1];
    const float* Wq = (const float*)d_in[2];
    const float* bq = (const float*)d_in[3];
    const float* Wk = (const float*)d_in[4];
    const float* bk = (const float*)d_in[5];
    const float* Wv = (const float*)d_in[6];
    const float* bv = (const float*)d_in[7];
    float* out = (float*)d_out;

    float *q, *k, *v;
    unsigned short *qb, *kb, *dots16;
    cudaGetSymbolAddress((void**)&q,      g_q);
    cudaGetSymbolAddress((void**)&k,      g_k);
    cudaGetSymbolAddress((void**)&v,      g_v);
    cudaGetSymbolAddress((void**)&qb,     g_qb);
    cudaGetSymbolAddress((void**)&kb,     g_kb);
    cudaGetSymbolAddress((void**)&dots16, g_dots16);

    cudaFuncSetAttribute(topk_softmax_gather,
                         cudaFuncAttributeMaxDynamicSharedMemorySize,
                         VOC * (int)sizeof(unsigned short));
    cudaFuncSetAttribute(dots_bf16,
                         cudaFuncAttributeMaxDynamicSharedMemorySize,
                         NSTAGE * ST_BYTES);

    dim3 blk(256);

    // projections: q,k write fp32 + bf16 copies; v plain fp32
    sgemm128<true><<<dim3(DIM / 128, BATCH / 128), blk>>>(
        x, Wq, bq, q, qb, BATCH, DIM, DIM);
    sgemm128<true><<<dim3(DIM / 128, VOC / 128), blk>>>(
        cb, Wk, bk, k, kb, VOC, DIM, DIM);
    sgemm128<false><<<dim3(DIM / 128, VOC / 128), blk>>>(
        cb, Wv, bv, v, nullptr, VOC, DIM, DIM);

    // approx dots = qb @ kb^T (bf16 m16n8k16), stored as bf16
    dots_bf16<<<dim3(BATCH / MT, VOC / NT), blk, NSTAGE * ST_BYTES>>>(
        qb, kb, dots16);

    // approx select (margin) + exact rescore + softmax + sparse gather of v
    topk_softmax_gather<<<BATCH, TT, VOC * (int)sizeof(unsigned short)>>>(
        dots16, q, k, v, out);
}

// round 14
// speedup vs baseline: 2.8124x; 1.0555x over previous
#include <cuda_runtime.h>
#include <cuda_bf16.h>
#include <cstdint>

#define VOC   32768
#define DIM   512
#define BATCH 4096
#define TOPK  64
#define MAXSEL 192
#define MARGIN 0.02f

// persistent-A dots config: CTA 128m x 1024n, A resident in smem, B streamed
#define MT 128
#define NSUB 8                    // n-subtiles of 128 -> 1024 cols per CTA
#define KCH 64                    // bf16 per K chunk
#define KITERS (DIM / KCH)        // 8 per subtile
#define GITERS (NSUB * KITERS)    // 64
#define LDHA 520                  // A halves per smem row (512 + 8 pad)
#define LDHB 72                   // B halves per smem row (64 + 8 pad)
#define A_BYTES (MT * LDHA * 2)       // 133120
#define BST_BYTES (128 * LDHB * 2)    // 18432
#define BSTAGES 3
#define DOTS_SMEM (A_BYTES + BSTAGES * BST_BYTES)   // 188416

// ---------------- scratch (static device globals; no allocation allowed) ----
__device__ float g_q [(size_t)BATCH * DIM];
__device__ float g_k [(size_t)VOC * DIM];
__device__ float g_v [(size_t)VOC * DIM];
__device__ unsigned short g_qb[(size_t)BATCH * DIM];
__device__ unsigned short g_kb[(size_t)VOC * DIM];
__device__ unsigned short g_dots16[(size_t)BATCH * VOC];   // 256 MB bf16 approx

// ---------------- PTX helpers ------------------------------------------------
__device__ __forceinline__ uint32_t smem_u32(const void* p) {
    uint32_t a;
    asm("{ .reg .u64 t; cvta.to.shared.u64 t, %1; cvt.u32.u64 %0, t; }"
        : "=r"(a) : "l"(p));
    return a;
}
#define CP_ASYNC16(dst, src) \
    asm volatile("cp.async.cg.shared.global [%0], [%1], 16;" \
                 :: "r"(dst), "l"(src) : "memory")
#define CP_COMMIT()  asm volatile("cp.async.commit_group;" ::: "memory")

__device__ __forceinline__ void mma_bf16(float& c0, float& c1, float& c2, float& c3,
                                         uint32_t a0, uint32_t a1, uint32_t a2, uint32_t a3,
                                         uint32_t b0, uint32_t b1) {
    asm volatile(
        "mma.sync.aligned.m16n8k16.row.col.f32.bf16.bf16.f32 "
        "{%0,%1,%2,%3}, {%4,%5,%6,%7}, {%8,%9}, {%0,%1,%2,%3};"
        : "+f"(c0), "+f"(c1), "+f"(c2), "+f"(c3)
        : "r"(a0), "r"(a1), "r"(a2), "r"(a3), "r"(b0), "r"(b1));
}

__device__ __forceinline__ void ldsm4(uint32_t& r0, uint32_t& r1,
                                      uint32_t& r2, uint32_t& r3, uint32_t addr) {
    asm volatile("ldmatrix.sync.aligned.m8n8.x4.shared.b16 {%0,%1,%2,%3}, [%4];"
                 : "=r"(r0), "=r"(r1), "=r"(r2), "=r"(r3) : "r"(addr));
}

// ---------------- misc helpers ----------------------------------------------
// order-preserving u16 key for bf16 bit patterns
__device__ __forceinline__ unsigned int f2k16(unsigned int b) {
    return (b & 0x8000u) ? ((~b) & 0xFFFFu) : (b | 0x8000u);
}
__device__ __forceinline__ float k16tof(unsigned int k) {
    unsigned int b = (k & 0x8000u) ? (k ^ 0x8000u) : ((~k) & 0xFFFFu);
    unsigned int f = b << 16;
    return __uint_as_float(f);
}
__device__ __forceinline__ unsigned int ftok16(float x) {
    unsigned int b = __bfloat16_as_ushort(__float2bfloat16(x));
    return f2k16(b);
}

// ---------------- SGEMM (fp32, FFMA) for q/k/v projections -------------------
// Register double-buffered: LDG for chunk i+1 overlaps compute of chunk i.
// WB: additionally write bf16 copy of (acc+bias) to Cb.
template <bool WB>
__global__ __launch_bounds__(256)
void sgemm128(const float* __restrict__ A, const float* __restrict__ B,
              const float* __restrict__ bias, float* __restrict__ C,
              unsigned short* __restrict__ Cb,
              int M, int N, int K)
{
    __shared__ float As[8][128];
    __shared__ float Bs[8][128];

    const int tid = threadIdx.x;
    const int bm = blockIdx.y * 128;
    const int bn = blockIdx.x * 128;

    const int a_row = tid >> 1;
    const int a_col = (tid & 1) * 4;
    const int b_row = tid >> 5;
    const int b_col = (tid & 31) * 4;

    const int tx = tid & 15;
    const int ty = tid >> 4;

    float acc[8][8];
#pragma unroll
    for (int i = 0; i < 8; i++)
#pragma unroll
        for (int j = 0; j < 8; j++) acc[i][j] = 0.0f;

    const float* Aptr = A + (size_t)(bm + a_row) * K + a_col;
    const float* Bptr = B + (size_t)b_row * N + (bn + b_col);

    float4 av = *reinterpret_cast<const float4*>(Aptr);
    float4 bv = *reinterpret_cast<const float4*>(Bptr);

    for (int k0 = 0; k0 < K; k0 += 8) {
        As[a_col + 0][a_row] = av.x;
        As[a_col + 1][a_row] = av.y;
        As[a_col + 2][a_row] = av.z;
        As[a_col + 3][a_row] = av.w;
        *reinterpret_cast<float4*>(&Bs[b_row][b_col]) = bv;
        __syncthreads();

        if (k0 + 8 < K) {
            av = *reinterpret_cast<const float4*>(Aptr + k0 + 8);
            bv = *reinterpret_cast<const float4*>(Bptr + (size_t)(k0 + 8) * N);
        }

#pragma unroll
        for (int kk = 0; kk < 8; kk++) {
            float af[8], bf[8];
            float4 t;
            t = *reinterpret_cast<const float4*>(&As[kk][ty * 8]);
            af[0] = t.x; af[1] = t.y; af[2] = t.z; af[3] = t.w;
            t = *reinterpret_cast<const float4*>(&As[kk][ty * 8 + 4]);
            af[4] = t.x; af[5] = t.y; af[6] = t.z; af[7] = t.w;
            t = *reinterpret_cast<const float4*>(&Bs[kk][tx * 8]);
            bf[0] = t.x; bf[1] = t.y; bf[2] = t.z; bf[3] = t.w;
            t = *reinterpret_cast<const float4*>(&Bs[kk][tx * 8 + 4]);
            bf[4] = t.x; bf[5] = t.y; bf[6] = t.z; bf[7] = t.w;
#pragma unroll
            for (int i = 0; i < 8; i++)
#pragma unroll
                for (int j = 0; j < 8; j++)
                    acc[i][j] += af[i] * bf[j];
        }
        __syncthreads();
    }

#pragma unroll
    for (int i = 0; i < 8; i++) {
        const int row = bm + ty * 8 + i;
        const int col = bn + tx * 8;
#pragma unroll
        for (int j = 0; j < 8; j += 4) {
            float o[4];
#pragma unroll
            for (int t = 0; t < 4; t++) {
                o[t] = acc[i][j + t];
                o[t] += bias[col + j + t];
            }
            float4 v4;
            v4.x = o[0]; v4.y = o[1]; v4.z = o[2]; v4.w = o[3];
            *reinterpret_cast<float4*>(C + (size_t)row * N + col + j) = v4;
            if (WB) {
                ushort4 ub;
                ub.x = __bfloat16_as_ushort(__float2bfloat16(o[0]));
                ub.y = __bfloat16_as_ushort(__float2bfloat16(o[1]));
                ub.z = __bfloat16_as_ushort(__float2bfloat16(o[2]));
                ub.w = __bfloat16_as_ushort(__float2bfloat16(o[3]));
                *reinterpret_cast<ushort4*>(Cb + (size_t)row * N + col + j) = ub;
            }
        }
    }
}

// ---------------- dots_approx = qb @ kb^T, persistent-A bf16 mma -------------
// CTA 128m x 1024n. A (128x512 bf16) loaded to smem ONCE; B streamed per
// 64-wide K chunk through a 3-stage cp.async ring (64 chunks total).
__global__ __launch_bounds__(256, 1)
void dots_bf16(const unsigned short* __restrict__ Ab,
               const unsigned short* __restrict__ Bb,
               unsigned short* __restrict__ C16)
{
    extern __shared__ __align__(16) unsigned short smem[];
    const uint32_t sb = smem_u32(smem);

    const int tid = threadIdx.x;
    const int lane = tid & 31;
    const int wid = tid >> 5;
    const int warpM = wid >> 1;       // 0..3 -> 32 rows each
    const int warpN = wid & 1;        // 0..1 -> 64 cols each (within 128 subtile)
    const int bm = blockIdx.x * MT;   // m fastest
    const int bn0 = blockIdx.y * (NSUB * 128);

    const int r = lane >> 2;          // 0..7
    const int c4 = lane & 3;          // 0..3

    // ---- one-time A load: 128 rows x 512 halves (each thread 32 x 16B) ----
    {
        const int row = tid >> 1;
        const int half = tid & 1;
        const unsigned short* g = Ab + (size_t)(bm + row) * DIM + half * 256;
        const uint32_t d = sb + ((uint32_t)row * LDHA + half * 256) * 2;
#pragma unroll
        for (int c = 0; c < 32; c++)
            CP_ASYNC16(d + c * 16, g + c * 8);
        CP_COMMIT();
    }

    // ---- B chunk prefetch: chunk g covers rows bn0+(g>>3)*128, cols (g&7)*64
    auto prefetchB = [&](int g, int s) {
        const int row = tid >> 1;
        const int seg = tid & 1;
        const unsigned short* gp = Bb
            + (size_t)(bn0 + (g >> 3) * 128 + row) * DIM + (g & 7) * KCH + seg * 32;
        const uint32_t d = sb + A_BYTES + (uint32_t)s * BST_BYTES
                         + ((uint32_t)row * LDHB + seg * 32) * 2;
#pragma unroll
        for (int c = 0; c < 4; c++)
            CP_ASYNC16(d + c * 16, gp + c * 8);
        CP_COMMIT();
    };

    prefetchB(0, 0);
    prefetchB(1, 1);

    // ldmatrix per-thread byte offsets
    const int l8 = lane & 7;
    const int gq = lane >> 3;         // 0..3 quad group
    uint32_t aoffb[2];                // into persistent A region
#pragma unroll
    for (int mt = 0; mt < 2; mt++) {
        const int row = warpM * 32 + mt * 16 + l8 + (gq & 1) * 8;
        const int col = (gq >> 1) * 8;
        aoffb[mt] = ((uint32_t)row * LDHA + col) * 2;
    }
    uint32_t boffb[4];                // relative to B stage base
#pragma unroll
    for (int p = 0; p < 4; p++) {
        const int row = warpN * 64 + p * 16 + l8 + (gq >> 1) * 8;
        const int col = (gq & 1) * 8;
        boffb[p] = ((uint32_t)row * LDHB + col) * 2;
    }

    float acc[2][8][4];

    int stage = 0;
    for (int g = 0; g < GITERS; g++) {
        const int it = g & 7;
        if (it == 0) {
#pragma unroll
            for (int mt = 0; mt < 2; mt++)
#pragma unroll
                for (int nt = 0; nt < 8; nt++)
#pragma unroll
                    for (int i = 0; i < 4; i++) acc[mt][nt][i] = 0.0f;
        }

        if (g + 1 < GITERS)
            asm volatile("cp.async.wait_group %0;" :: "n"(1));
        else
            asm volatile("cp.async.wait_group %0;" :: "n"(0));
        __syncthreads();

        // stage (g+2)%3 == (g-1)%3: all warps finished reading it (barrier above)
        if (g + 2 < GITERS) {
            int ps = stage + 2; if (ps >= BSTAGES) ps -= BSTAGES;
            prefetchB(g + 2, ps);
        }

        const uint32_t stb = sb + A_BYTES + (uint32_t)stage * BST_BYTES;
        const uint32_t akoff = (uint32_t)it * KCH * 2;   // byte offset into A cols

#pragma unroll
        for (int ks = 0; ks < 4; ks++) {
            const uint32_t koff = (uint32_t)ks * 32;     // 16 halves
            uint32_t a[2][4], b[4][4];
#pragma unroll
            for (int mt = 0; mt < 2; mt++)
                ldsm4(a[mt][0], a[mt][1], a[mt][2], a[mt][3],
                      sb + aoffb[mt] + akoff + koff);
#pragma unroll
            for (int p = 0; p < 4; p++)
                ldsm4(b[p][0], b[p][1], b[p][2], b[p][3],
                      stb + boffb[p] + koff);
#pragma unroll
            for (int mt = 0; mt < 2; mt++)
#pragma unroll
                for (int p = 0; p < 4; p++) {
                    float* a0 = acc[mt][2 * p];
                    float* a1 = acc[mt][2 * p + 1];
                    mma_bf16(a0[0], a0[1], a0[2], a0[3],
                             a[mt][0], a[mt][1], a[mt][2], a[mt][3],
                             b[p][0], b[p][1]);
                    mma_bf16(a1[0], a1[1], a1[2], a1[3],
                             a[mt][0], a[mt][1], a[mt][2], a[mt][3],
                             b[p][2], b[p][3]);
                }
        }

        if (it == 7) {
            // epilogue for this n-subtile: pack bf16 pairs
            const int bn = bn0 + (g >> 3) * 128;
#pragma unroll
            for (int mt = 0; mt < 2; mt++) {
                const int row = bm + warpM * 32 + mt * 16 + r;
#pragma unroll
                for (int nt = 0; nt < 8; nt++) {
                    const int col = bn + warpN * 64 + nt * 8 + 2 * c4;
                    const float* a = acc[mt][nt];
                    unsigned int p0 =
                        (unsigned int)__bfloat16_as_ushort(__float2bfloat16(a[0]))
                        | ((unsigned int)__bfloat16_as_ushort(__float2bfloat16(a[1])) << 16);
                    unsigned int p1 =
                        (unsigned int)__bfloat16_as_ushort(__float2bfloat16(a[2]))
                        | ((unsigned int)__bfloat16_as_ushort(__float2bfloat16(a[3])) << 16);
                    *reinterpret_cast<unsigned int*>(C16 + (size_t)row * VOC + col) = p0;
                    *reinterpret_cast<unsigned int*>(C16 + (size_t)(row + 8) * VOC + col) = p1;
                }
            }
        }

        if (++stage == BSTAGES) stage = 0;
    }
}

// ---------------- per-row: approx select + exact rescore + softmax + A@V ----
#define TT 512
__global__ __launch_bounds__(TT, 2)
void topk_softmax_gather(const unsigned short* __restrict__ dots16,
                         const float* __restrict__ Q,
                         const float* __restrict__ Kf,
                         const float* __restrict__ v,
                         float* __restrict__ out)
{
    extern __shared__ unsigned short keys16[];        // VOC u16 = 64KB
    __shared__ unsigned int hist[256];
    __shared__ unsigned int scanbuf[2][256];
    __shared__ unsigned int cscan[2][TT];
    __shared__ float        f_red[TT];
    __shared__ float qrow[DIM];
    __shared__ int   sel_idx[MAXSEL];
    __shared__ float sel_val[MAXSEL];
    __shared__ float sel_w[MAXSEL];
    __shared__ unsigned int s_bucket;
    __shared__ int s_r;
    __shared__ unsigned int s_thresh;

    const int tid = threadIdx.x;
    const int lane = tid & 31;
    const int wid = tid >> 5;
    const int row = blockIdx.x;
    const unsigned int* drow = reinterpret_cast<const unsigned int*>(
        dots16 + (size_t)row * VOC);

    // ---- phase 1: load bf16 row (as u32 pairs), convert to sortable u16 ----
    for (int i = tid; i < VOC / 2; i += TT) {
        const unsigned int w = drow[i];
        const unsigned int k0 = f2k16(w & 0xFFFFu);
        const unsigned int k1 = f2k16(w >> 16);
        reinterpret_cast<unsigned int*>(keys16)[i] = k0 | (k1 << 16);
    }
    if (tid < DIM)
        qrow[tid] = Q[(size_t)row * DIM + tid];
    __syncthreads();

    // ---- phase 2a: radix pass on high byte (warp-aggregated atomics) ----
    if (tid < 256) hist[tid] = 0;
    __syncthreads();
    for (int i = tid; i < VOC; i += TT) {
        const unsigned int bin = (unsigned int)keys16[i] >> 8;
        const unsigned int mask = __match_any_sync(0xFFFFFFFFu, bin);
        if ((__ffs(mask) - 1) == lane)
            atomicAdd(&hist[bin], (unsigned int)__popc(mask));
    }
    __syncthreads();
    {
        if (tid < 256) scanbuf[0][tid] = hist[tid];
        __syncthreads();
        int src = 0;
        for (int off = 1; off < 256; off <<= 1) {
            unsigned int val = 0;
            if (tid < 256) {
                val = scanbuf[src][tid];
                if (tid + off < 256) val += scanbuf[src][tid + off];
            }
            __syncthreads();
            if (tid < 256) scanbuf[src ^ 1][tid] = val;
            __syncthreads();
            src ^= 1;
        }
        if (tid < 256) {
            const unsigned int cumb  = scanbuf[src][tid];
            const unsigned int cumb1 = (tid == 255) ? 0u : scanbuf[src][tid + 1];
            if (cumb >= TOPK && cumb1 < TOPK) {
                s_bucket = (unsigned int)tid;
                s_r = TOPK - (int)cumb1;
            }
        }
        __syncthreads();
    }
    const unsigned int bucket = s_bucket;
    const int r1 = s_r;
    __syncthreads();

    // ---- phase 2b: radix pass on low byte within bucket ----
    if (tid < 256) hist[tid] = 0;
    __syncthreads();
    for (int i = tid; i < VOC; i += TT) {
        const unsigned int k = keys16[i];
        if ((k >> 8) == bucket)
            atomicAdd(&hist[k & 0xFFu], 1u);
    }
    __syncthreads();
    {
        if (tid < 256) scanbuf[0][tid] = hist[tid];
        __syncthreads();
        int src = 0;
        for (int off = 1; off < 256; off <<= 1) {
            unsigned int val = 0;
            if (tid < 256) {
                val = scanbuf[src][tid];
                if (tid + off < 256) val += scanbuf[src][tid + off];
            }
            __syncthreads();
            if (tid < 256) scanbuf[src ^ 1][tid] = val;
            __syncthreads();
            src ^= 1;
        }
        if (tid < 256) {
            const unsigned int cumb  = scanbuf[src][tid];
            const unsigned int cumb1 = (tid == 255) ? 0u : scanbuf[src][tid + 1];
            if (cumb >= (unsigned int)r1 && cumb1 < (unsigned int)r1)
                s_thresh = (bucket << 8) | (unsigned int)tid;
        }
        __syncthreads();
    }
    // widen threshold by margin (bf16 mma + storage quantization bound)
    const unsigned int cut16 = ftok16(k16tof(s_thresh) - MARGIN);

    // ---- phase 3: deterministic compaction of candidate indices ----
    int c = 0;
    for (int i = tid; i < VOC; i += TT)
        if ((unsigned int)keys16[i] >= cut16) c++;
    cscan[0][tid] = (unsigned int)c;
    __syncthreads();
    int src = 0;
    for (int off = 1; off < TT; off <<= 1) {
        unsigned int val = cscan[src][tid];
        if (tid >= off) val += cscan[src][tid - off];
        __syncthreads();
        cscan[src ^ 1][tid] = val;
        __syncthreads();
        src ^= 1;
    }
    int pos = (tid == 0) ? 0 : (int)cscan[src][tid - 1];
    const int count = min((int)cscan[src][TT - 1], MAXSEL);

    for (int i = tid; i < VOC; i += TT) {
        if ((unsigned int)keys16[i] >= cut16) {
            if (pos < MAXSEL) sel_idx[pos] = i;
            pos++;
        }
    }
    __syncthreads();

    // ---- phase 4: exact fp32 rescore of candidates (one warp per cand) ----
    for (int s = wid; s < count; s += (TT / 32)) {
        const int idx = sel_idx[s];
        const float4* kr = reinterpret_cast<const float4*>(Kf + (size_t)idx * DIM);
        float sum = 0.0f;
#pragma unroll
        for (int j = 0; j < 4; j++) {
            const float4 a = kr[lane * 4 + j];
            const float4 qv = *reinterpret_cast<const float4*>(&qrow[lane * 16 + j * 4]);
            sum += qv.x * a.x + qv.y * a.y + qv.z * a.z + qv.w * a.w;
        }
#pragma unroll
        for (int off = 16; off > 0; off >>= 1)
            sum += __shfl_xor_sync(0xFFFFFFFFu, sum, off);
        if (lane == 0) sel_val[s] = sum;
    }
    __syncthreads();

    // ---- phase 5: exact top-64 rule + softmax weights ----
    float mx = -3.4e38f;
    if (tid < count) mx = sel_val[tid];
    f_red[tid] = mx;
    __syncthreads();
#pragma unroll
    for (int s = TT / 2; s > 0; s >>= 1) {
        if (tid < s) f_red[tid] = fmaxf(f_red[tid], f_red[tid + s]);
        __syncthreads();
    }
    const float m = f_red[0];

    if (tid < count) {
        const float mine = sel_val[tid];
        int greater = 0;
        for (int j = 0; j < count; j++)
            greater += (sel_val[j] > mine);
        sel_w[tid] = (greater < TOPK) ? expf(mine - m) : 0.0f;
    }
    __syncthreads();

    float z = (tid < count) ? sel_w[tid] : 0.0f;
    f_red[tid] = z;
    __syncthreads();
#pragma unroll
    for (int s = TT / 2; s > 0; s >>= 1) {
        if (tid < s) f_red[tid] += f_red[tid + s];
        __syncthreads();
    }
    const float Z = f_red[0];

    // ---- phase 6: out[row] = (1/Z) * sum_s w_s * v[idx_s] ----
    float acc0 = 0.0f;
    for (int s = 0; s < count; s++)
        acc0 += sel_w[s] * v[(size_t)sel_idx[s] * DIM + tid];
    out[(size_t)row * DIM + tid] = acc0 / Z;
}

// ---------------- launch ----------------------------------------------------
extern "C" void kernel_launch(void* const* d_in, const int* in_sizes, int n_in,
                              void* d_out, int out_size)
{
    const float* x  = (const float*)d_in[0];
    const float* cb = (const float*)d_in[1];
    const float* Wq = (const float*)d_in[2];
    const float* bq = (const float*)d_in[3];
    const float* Wk = (const float*)d_in[4];
    const float* bk = (const float*)d_in[5];
    const float* Wv = (const float*)d_in[6];
    const float* bv = (const float*)d_in[7];
    float* out = (float*)d_out;

    float *q, *k, *v;
    unsigned short *qb, *kb, *dots16;
    cudaGetSymbolAddress((void**)&q,      g_q);
    cudaGetSymbolAddress((void**)&k,      g_k);
    cudaGetSymbolAddress((void**)&v,      g_v);
    cudaGetSymbolAddress((void**)&qb,     g_qb);
    cudaGetSymbolAddress((void**)&kb,     g_kb);
    cudaGetSymbolAddress((void**)&dots16, g_dots16);

    cudaFuncSetAttribute(topk_softmax_gather,
                         cudaFuncAttributeMaxDynamicSharedMemorySize,
                         VOC * (int)sizeof(unsigned short));
    cudaFuncSetAttribute(dots_bf16,
                         cudaFuncAttributeMaxDynamicSharedMemorySize,
                         DOTS_SMEM);

    dim3 blk(256);

    // projections: q,k write fp32 + bf16 copies; v plain fp32
    sgemm128<true><<<dim3(DIM / 128, BATCH / 128), blk>>>(
        x, Wq, bq, q, qb, BATCH, DIM, DIM);
    sgemm128<true><<<dim3(DIM / 128, VOC / 128), blk>>>(
        cb, Wk, bk, k, kb, VOC, DIM, DIM);
    sgemm128<false><<<dim3(DIM / 128, VOC / 128), blk>>>(
        cb, Wv, bv, v, nullptr, VOC, DIM, DIM);

    // approx dots = qb @ kb^T (persistent-A bf16 m16n8k16), stored as bf16
    dots_bf16<<<dim3(BATCH / MT, VOC / (NSUB * 128)), blk, DOTS_SMEM>>>(
        qb, kb, dots16);

    // approx select (margin) + exact rescore + softmax + sparse gather of v
    topk_softmax_gather<<<BATCH, TT, VOC * (int)sizeof(unsigned short)>>>(
        dots16, q, k, v, out);
}

// round 15
// speedup vs baseline: 3.4165x; 1.2148x over previous
#include <cuda_runtime.h>
#include <cuda_bf16.h>
#include <cstdint>

#define VOC   32768
#define DIM   512
#define BATCH 4096
#define TOPK  64
#define MAXSEL 192
#define MARGIN 0.02f

// ---- persistent-A dots config: CTA 128m x 1024n ----
#define MT 128
#define NSUB 8
#define KCH 64
#define KITERS (DIM / KCH)        // 8 per subtile
#define GITERS (NSUB * KITERS)    // 64
#define LDHA 520
#define LDHB 72
#define A_BYTES (MT * LDHA * 2)       // 133120
#define BST_BYTES (128 * LDHB * 2)    // 18432
#define BSTAGES 3
#define DOTS_SMEM (A_BYTES + BSTAGES * BST_BYTES)

// ---- bf16x3 projection gemm config: CTA 128x128, KCH 32, 2 stages ----
#define PKCH 32
#define PKITERS (DIM / PKCH)      // 16
#define PLDH 40
#define P_AH (128 * PLDH)         // 5120 halves per plane
#define PST_HALVES (4 * P_AH)     // A hi/lo + B hi/lo
#define PST_BYTES (PST_HALVES * 2)   // 40960
#define PROJ_SMEM (2 * PST_BYTES)    // 81920

// ---------------- scratch (static device globals) ----------------------------
__device__ float g_q [(size_t)BATCH * DIM];
__device__ float g_k [(size_t)VOC * DIM];
__device__ float g_v [(size_t)VOC * DIM];
__device__ unsigned short g_qb[(size_t)BATCH * DIM];
__device__ unsigned short g_kb[(size_t)VOC * DIM];
__device__ unsigned short g_xh[(size_t)BATCH * DIM];
__device__ unsigned short g_xl[(size_t)BATCH * DIM];
__device__ unsigned short g_ch[(size_t)VOC * DIM];
__device__ unsigned short g_cl[(size_t)VOC * DIM];
__device__ unsigned short g_wh[3 * DIM * DIM];
__device__ unsigned short g_wl[3 * DIM * DIM];
__device__ unsigned short g_dots16[(size_t)BATCH * VOC];

// ---------------- PTX helpers ------------------------------------------------
__device__ __forceinline__ uint32_t smem_u32(const void* p) {
    uint32_t a;
    asm("{ .reg .u64 t; cvta.to.shared.u64 t, %1; cvt.u32.u64 %0, t; }"
        : "=r"(a) : "l"(p));
    return a;
}
#define CP_ASYNC16(dst, src) \
    asm volatile("cp.async.cg.shared.global [%0], [%1], 16;" \
                 :: "r"(dst), "l"(src) : "memory")
#define CP_COMMIT()  asm volatile("cp.async.commit_group;" ::: "memory")

__device__ __forceinline__ void mma_bf16(float& c0, float& c1, float& c2, float& c3,
                                         uint32_t a0, uint32_t a1, uint32_t a2, uint32_t a3,
                                         uint32_t b0, uint32_t b1) {
    asm volatile(
        "mma.sync.aligned.m16n8k16.row.col.f32.bf16.bf16.f32 "
        "{%0,%1,%2,%3}, {%4,%5,%6,%7}, {%8,%9}, {%0,%1,%2,%3};"
        : "+f"(c0), "+f"(c1), "+f"(c2), "+f"(c3)
        : "r"(a0), "r"(a1), "r"(a2), "r"(a3), "r"(b0), "r"(b1));
}

__device__ __forceinline__ void ldsm4(uint32_t& r0, uint32_t& r1,
                                      uint32_t& r2, uint32_t& r3, uint32_t addr) {
    asm volatile("ldmatrix.sync.aligned.m8n8.x4.shared.b16 {%0,%1,%2,%3}, [%4];"
                 : "=r"(r0), "=r"(r1), "=r"(r2), "=r"(r3) : "r"(addr));
}

// ---------------- misc helpers ----------------------------------------------
__device__ __forceinline__ unsigned int f2k16(unsigned int b) {
    return (b & 0x8000u) ? ((~b) & 0xFFFFu) : (b | 0x8000u);
}
__device__ __forceinline__ float k16tof(unsigned int k) {
    unsigned int b = (k & 0x8000u) ? (k ^ 0x8000u) : ((~k) & 0xFFFFu);
    return __uint_as_float(b << 16);
}
__device__ __forceinline__ unsigned int ftok16(float x) {
    return f2k16(__bfloat16_as_ushort(__float2bfloat16(x)));
}
__device__ __forceinline__ void bf16split(float a, unsigned short& h, unsigned short& l) {
    __nv_bfloat16 hb = __float2bfloat16(a);
    float hf = __bfloat162float(hb);
    __nv_bfloat16 lb = __float2bfloat16(a - hf);
    h = __bfloat16_as_ushort(hb);
    l = __bfloat16_as_ushort(lb);
}

// ---------------- prep: elementwise bf16 split -------------------------------
__global__ __launch_bounds__(256)
void split_bf16(const float* __restrict__ in, unsigned short* __restrict__ hi,
                unsigned short* __restrict__ lo, int n)
{
    int i = blockIdx.x * 256 + threadIdx.x;
    if (i >= n) return;
    unsigned short h, l;
    bf16split(in[i], h, l);
    hi[i] = h;
    lo[i] = l;
}

// ---------------- prep: W [K,N] -> Wt [N,K] with bf16 split ------------------
__global__ __launch_bounds__(256)
void transpose_split_w(const float* __restrict__ W,
                       unsigned short* __restrict__ Th,
                       unsigned short* __restrict__ Tl)
{
    int idx = blockIdx.x * 256 + threadIdx.x;   // n*DIM + kk
    if (idx >= DIM * DIM) return;
    int n = idx >> 9, kk = idx & (DIM - 1);
    unsigned short h, l;
    bf16split(W[kk * DIM + n], h, l);
    Th[idx] = h;
    Tl[idx] = l;
}

// ---------------- projection GEMM: C = (Ah+Al)(Bh+Bl)^T + bias ---------------
// bf16x3 emulation (hi*hi + lo*hi + hi*lo), fp32 accum. Writes fp32 C and
// (if WB) bf16 Cb. CTA 128x128, 8 warps of 32x64, KCH=32, 2-stage (R12 pattern).
template <bool WB>
__global__ __launch_bounds__(256, 2)
void gemm_bf16x3(const unsigned short* __restrict__ Ah,
                 const unsigned short* __restrict__ Al,
                 const unsigned short* __restrict__ Bh,
                 const unsigned short* __restrict__ Bl,
                 const float* __restrict__ bias,
                 float* __restrict__ C, unsigned short* __restrict__ Cb)
{
    extern __shared__ __align__(16) unsigned short smem[];
    const uint32_t sb = smem_u32(smem);

    const int tid = threadIdx.x;
    const int lane = tid & 31;
    const int wid = tid >> 5;
    const int warpM = wid >> 1;
    const int warpN = wid & 1;
    const int bm = blockIdx.x * 128;
    const int bn = blockIdx.y * 128;

    const int r = lane >> 2;
    const int c4 = lane & 3;

    float acc[2][8][4];
#pragma unroll
    for (int mt = 0; mt < 2; mt++)
#pragma unroll
        for (int nt = 0; nt < 8; nt++)
#pragma unroll
            for (int i = 0; i < 4; i++) acc[mt][nt][i] = 0.0f;

    const int plane = tid >> 7;       // 0: hi, 1: lo
    const int prow = tid & 127;
    const unsigned short* gaBase = (plane ? Al : Ah) + (size_t)(bm + prow) * DIM;
    const unsigned short* gbBase = (plane ? Bl : Bh) + (size_t)(bn + prow) * DIM;
    const uint32_t daBase = sb + ((uint32_t)plane * P_AH + (uint32_t)prow * PLDH) * 2;
    const uint32_t dbBase = sb + ((uint32_t)(2 + plane) * P_AH + (uint32_t)prow * PLDH) * 2;

    auto prefetch = [&](int it, int s) {
        const unsigned short* ga = gaBase + it * PKCH;
        const unsigned short* gb = gbBase + it * PKCH;
        const uint32_t da = daBase + (uint32_t)s * PST_BYTES;
        const uint32_t db = dbBase + (uint32_t)s * PST_BYTES;
#pragma unroll
        for (int c = 0; c < 4; c++) {
            CP_ASYNC16(da + c * 16, ga + c * 8);
            CP_ASYNC16(db + c * 16, gb + c * 8);
        }
        CP_COMMIT();
    };

    prefetch(0, 0);
    prefetch(1, 1);

    const int l8 = lane & 7;
    const int gq = lane >> 3;
    uint32_t aoffb[2];
#pragma unroll
    for (int mt = 0; mt < 2; mt++) {
        const int row = warpM * 32 + mt * 16 + l8 + (gq & 1) * 8;
        const int col = (gq >> 1) * 8;
        aoffb[mt] = ((uint32_t)row * PLDH + col) * 2;
    }
    uint32_t boffb[4];
#pragma unroll
    for (int p = 0; p < 4; p++) {
        const int row = warpN * 64 + p * 16 + l8 + (gq >> 1) * 8;
        const int col = (gq & 1) * 8;
        boffb[p] = ((uint32_t)(2 * P_AH) + (uint32_t)row * PLDH + col) * 2;
    }
    const uint32_t LO_A = (uint32_t)P_AH * 2;   // byte offset hi->lo plane

    for (int it = 0; it < PKITERS; it++) {
        if (it + 1 < PKITERS)
            asm volatile("cp.async.wait_group %0;" :: "n"(1));
        else
            asm volatile("cp.async.wait_group %0;" :: "n"(0));
        __syncthreads();

        const uint32_t stb = sb + (uint32_t)(it & 1) * PST_BYTES;

#pragma unroll
        for (int ks = 0; ks < 2; ks++) {
            const uint32_t koff = (uint32_t)ks * 32;   // 16 halves
            uint32_t ah[2][4], al[2][4], bh[4][4], bl[4][4];
#pragma unroll
            for (int mt = 0; mt < 2; mt++) {
                ldsm4(ah[mt][0], ah[mt][1], ah[mt][2], ah[mt][3],
                      stb + aoffb[mt] + koff);
                ldsm4(al[mt][0], al[mt][1], al[mt][2], al[mt][3],
                      stb + aoffb[mt] + LO_A + koff);
            }
#pragma unroll
            for (int p = 0; p < 4; p++) {
                ldsm4(bh[p][0], bh[p][1], bh[p][2], bh[p][3],
                      stb + boffb[p] + koff);
                ldsm4(bl[p][0], bl[p][1], bl[p][2], bl[p][3],
                      stb + boffb[p] + LO_A + koff);
            }
#pragma unroll
            for (int mt = 0; mt < 2; mt++)
#pragma unroll
                for (int p = 0; p < 4; p++) {
                    float* a0 = acc[mt][2 * p];
                    float* a1 = acc[mt][2 * p + 1];
                    mma_bf16(a0[0], a0[1], a0[2], a0[3],
                             ah[mt][0], ah[mt][1], ah[mt][2], ah[mt][3],
                             bh[p][0], bh[p][1]);
                    mma_bf16(a0[0], a0[1], a0[2], a0[3],
                             al[mt][0], al[mt][1], al[mt][2], al[mt][3],
                             bh[p][0], bh[p][1]);
                    mma_bf16(a0[0], a0[1], a0[2], a0[3],
                             ah[mt][0], ah[mt][1], ah[mt][2], ah[mt][3],
                             bl[p][0], bl[p][1]);
                    mma_bf16(a1[0], a1[1], a1[2], a1[3],
                             ah[mt][0], ah[mt][1], ah[mt][2], ah[mt][3],
                             bh[p][2], bh[p][3]);
                    mma_bf16(a1[0], a1[1], a1[2], a1[3],
                             al[mt][0], al[mt][1], al[mt][2], al[mt][3],
                             bh[p][2], bh[p][3]);
                    mma_bf16(a1[0], a1[1], a1[2], a1[3],
                             ah[mt][0], ah[mt][1], ah[mt][2], ah[mt][3],
                             bl[p][2], bl[p][3]);
                }
        }

        if (it + 2 < PKITERS) {
            __syncthreads();
            prefetch(it + 2, it & 1);
        }
    }

    // epilogue: add bias, write fp32 (and bf16 if WB)
#pragma unroll
    for (int mt = 0; mt < 2; mt++) {
        const int row = bm + warpM * 32 + mt * 16 + r;
#pragma unroll
        for (int nt = 0; nt < 8; nt++) {
            const int col = bn + warpN * 64 + nt * 8 + 2 * c4;
            const float b0 = bias[col];
            const float b1 = bias[col + 1];
            float* a = acc[mt][nt];
            float2 v0; v0.x = a[0] + b0; v0.y = a[1] + b1;
            float2 v1; v1.x = a[2] + b0; v1.y = a[3] + b1;
            *reinterpret_cast<float2*>(C + (size_t)row * DIM + col) = v0;
            *reinterpret_cast<float2*>(C + (size_t)(row + 8) * DIM + col) = v1;
            if (WB) {
                unsigned int p0 =
                    (unsigned int)__bfloat16_as_ushort(__float2bfloat16(v0.x))
                    | ((unsigned int)__bfloat16_as_ushort(__float2bfloat16(v0.y)) << 16);
                unsigned int p1 =
                    (unsigned int)__bfloat16_as_ushort(__float2bfloat16(v1.x))
                    | ((unsigned int)__bfloat16_as_ushort(__float2bfloat16(v1.y)) << 16);
                *reinterpret_cast<unsigned int*>(Cb + (size_t)row * DIM + col) = p0;
                *reinterpret_cast<unsigned int*>(Cb + (size_t)(row + 8) * DIM + col) = p1;
            }
        }
    }
}

// ---------------- dots_approx = qb @ kb^T, persistent-A bf16 mma -------------
__global__ __launch_bounds__(256, 1)
void dots_bf16(const unsigned short* __restrict__ Ab,
               const unsigned short* __restrict__ Bb,
               unsigned short* __restrict__ C16)
{
    extern __shared__ __align__(16) unsigned short smem[];
    const uint32_t sb = smem_u32(smem);

    const int tid = threadIdx.x;
    const int lane = tid & 31;
    const int wid = tid >> 5;
    const int warpM = wid >> 1;
    const int warpN = wid & 1;
    const int bm = blockIdx.x * MT;
    const int bn0 = blockIdx.y * (NSUB * 128);

    const int r = lane >> 2;
    const int c4 = lane & 3;

    {
        const int row = tid >> 1;
        const int half = tid & 1;
        const unsigned short* g = Ab + (size_t)(bm + row) * DIM + half * 256;
        const uint32_t d = sb + ((uint32_t)row * LDHA + half * 256) * 2;
#pragma unroll
        for (int c = 0; c < 32; c++)
            CP_ASYNC16(d + c * 16, g + c * 8);
        CP_COMMIT();
    }

    auto prefetchB = [&](int g, int s) {
        const int row = tid >> 1;
        const int seg = tid & 1;
        const unsigned short* gp = Bb
            + (size_t)(bn0 + (g >> 3) * 128 + row) * DIM + (g & 7) * KCH + seg * 32;
        const uint32_t d = sb + A_BYTES + (uint32_t)s * BST_BYTES
                         + ((uint32_t)row * LDHB + seg * 32) * 2;
#pragma unroll
        for (int c = 0; c < 4; c++)
            CP_ASYNC16(d + c * 16, gp + c * 8);
        CP_COMMIT();
    };

    prefetchB(0, 0);
    prefetchB(1, 1);

    const int l8 = lane & 7;
    const int gq = lane >> 3;
    uint32_t aoffb[2];
#pragma unroll
    for (int mt = 0; mt < 2; mt++) {
        const int row = warpM * 32 + mt * 16 + l8 + (gq & 1) * 8;
        const int col = (gq >> 1) * 8;
        aoffb[mt] = ((uint32_t)row * LDHA + col) * 2;
    }
    uint32_t boffb[4];
#pragma unroll
    for (int p = 0; p < 4; p++) {
        const int row = warpN * 64 + p * 16 + l8 + (gq >> 1) * 8;
        const int col = (gq & 1) * 8;
        boffb[p] = ((uint32_t)row * LDHB + col) * 2;
    }

    float acc[2][8][4];

    int stage = 0;
    for (int g = 0; g < GITERS; g++) {
        const int it = g & 7;
        if (it == 0) {
#pragma unroll
            for (int mt = 0; mt < 2; mt++)
#pragma unroll
                for (int nt = 0; nt < 8; nt++)
#pragma unroll
                    for (int i = 0; i < 4; i++) acc[mt][nt][i] = 0.0f;
        }

        if (g + 1 < GITERS)
            asm volatile("cp.async.wait_group %0;" :: "n"(1));
        else
            asm volatile("cp.async.wait_group %0;" :: "n"(0));
        __syncthreads();

        if (g + 2 < GITERS) {
            int ps = stage + 2; if (ps >= BSTAGES) ps -= BSTAGES;
            prefetchB(g + 2, ps);
        }

        const uint32_t stb = sb + A_BYTES + (uint32_t)stage * BST_BYTES;
        const uint32_t akoff = (uint32_t)it * KCH * 2;

#pragma unroll
        for (int ks = 0; ks < 4; ks++) {
            const uint32_t koff = (uint32_t)ks * 32;
            uint32_t a[2][4], b[4][4];
#pragma unroll
            for (int mt = 0; mt < 2; mt++)
                ldsm4(a[mt][0], a[mt][1], a[mt][2], a[mt][3],
                      sb + aoffb[mt] + akoff + koff);
#pragma unroll
            for (int p = 0; p < 4; p++)
                ldsm4(b[p][0], b[p][1], b[p][2], b[p][3],
                      stb + boffb[p] + koff);
#pragma unroll
            for (int mt = 0; mt < 2; mt++)
#pragma unroll
                for (int p = 0; p < 4; p++) {
                    float* a0 = acc[mt][2 * p];
                    float* a1 = acc[mt][2 * p + 1];
                    mma_bf16(a0[0], a0[1], a0[2], a0[3],
                             a[mt][0], a[mt][1], a[mt][2], a[mt][3],
                             b[p][0], b[p][1]);
                    mma_bf16(a1[0], a1[1], a1[2], a1[3],
                             a[mt][0], a[mt][1], a[mt][2], a[mt][3],
                             b[p][2], b[p][3]);
                }
        }

        if (it == 7) {
            const int bn = bn0 + (g >> 3) * 128;
#pragma unroll
            for (int mt = 0; mt < 2; mt++) {
                const int row = bm + warpM * 32 + mt * 16 + r;
#pragma unroll
                for (int nt = 0; nt < 8; nt++) {
                    const int col = bn + warpN * 64 + nt * 8 + 2 * c4;
                    const float* a = acc[mt][nt];
                    unsigned int p0 =
                        (unsigned int)__bfloat16_as_ushort(__float2bfloat16(a[0]))
                        | ((unsigned int)__bfloat16_as_ushort(__float2bfloat16(a[1])) << 16);
                    unsigned int p1 =
                        (unsigned int)__bfloat16_as_ushort(__float2bfloat16(a[2]))
                        | ((unsigned int)__bfloat16_as_ushort(__float2bfloat16(a[3])) << 16);
                    *reinterpret_cast<unsigned int*>(C16 + (size_t)row * VOC + col) = p0;
                    *reinterpret_cast<unsigned int*>(C16 + (size_t)(row + 8) * VOC + col) = p1;
                }
            }
        }

        if (++stage == BSTAGES) stage = 0;
    }
}

// ---------------- per-row: approx select + exact rescore + softmax + A@V ----
#define TT 512
__global__ __launch_bounds__(TT, 2)
void topk_softmax_gather(const unsigned short* __restrict__ dots16,
                         const float* __restrict__ Q,
                         const float* __restrict__ Kf,
                         const float* __restrict__ v,
                         float* __restrict__ out)
{
    extern __shared__ unsigned short keys16[];
    __shared__ unsigned int hist[256];
    __shared__ unsigned int scanbuf[2][256];
    __shared__ unsigned int cscan[2][TT];
    __shared__ float        f_red[TT];
    __shared__ float qrow[DIM];
    __shared__ int   sel_idx[MAXSEL];
    __shared__ float sel_val[MAXSEL];
    __shared__ float sel_w[MAXSEL];
    __shared__ unsigned int s_bucket;
    __shared__ int s_r;
    __shared__ unsigned int s_thresh;

    const int tid = threadIdx.x;
    const int lane = tid & 31;
    const int wid = tid >> 5;
    const int row = blockIdx.x;
    const unsigned int* drow = reinterpret_cast<const unsigned int*>(
        dots16 + (size_t)row * VOC);

    for (int i = tid; i < VOC / 2; i += TT) {
        const unsigned int w = drow[i];
        const unsigned int k0 = f2k16(w & 0xFFFFu);
        const unsigned int k1 = f2k16(w >> 16);
        reinterpret_cast<unsigned int*>(keys16)[i] = k0 | (k1 << 16);
    }
    if (tid < DIM)
        qrow[tid] = Q[(size_t)row * DIM + tid];
    __syncthreads();

    if (tid < 256) hist[tid] = 0;
    __syncthreads();
    for (int i = tid; i < VOC; i += TT) {
        const unsigned int bin = (unsigned int)keys16[i] >> 8;
        const unsigned int mask = __match_any_sync(0xFFFFFFFFu, bin);
        if ((__ffs(mask) - 1) == lane)
            atomicAdd(&hist[bin], (unsigned int)__popc(mask));
    }
    __syncthreads();
    {
        if (tid < 256) scanbuf[0][tid] = hist[tid];
        __syncthreads();
        int src = 0;
        for (int off = 1; off < 256; off <<= 1) {
            unsigned int val = 0;
            if (tid < 256) {
                val = scanbuf[src][tid];
                if (tid + off < 256) val += scanbuf[src][tid + off];
            }
            __syncthreads();
            if (tid < 256) scanbuf[src ^ 1][tid] = val;
            __syncthreads();
            src ^= 1;
        }
        if (tid < 256) {
            const unsigned int cumb  = scanbuf[src][tid];
            const unsigned int cumb1 = (tid == 255) ? 0u : scanbuf[src][tid + 1];
            if (cumb >= TOPK && cumb1 < TOPK) {
                s_bucket = (unsigned int)tid;
                s_r = TOPK - (int)cumb1;
            }
        }
        __syncthreads();
    }
    const unsigned int bucket = s_bucket;
    const int r1 = s_r;
    __syncthreads();

    if (tid < 256) hist[tid] = 0;
    __syncthreads();
    for (int i = tid; i < VOC; i += TT) {
        const unsigned int k = keys16[i];
        if ((k >> 8) == bucket)
            atomicAdd(&hist[k & 0xFFu], 1u);
    }
    __syncthreads();
    {
        if (tid < 256) scanbuf[0][tid] = hist[tid];
        __syncthreads();
        int src = 0;
        for (int off = 1; off < 256; off <<= 1) {
            unsigned int val = 0;
            if (tid < 256) {
                val = scanbuf[src][tid];
                if (tid + off < 256) val += scanbuf[src][tid + off];
            }
            __syncthreads();
            if (tid < 256) scanbuf[src ^ 1][tid] = val;
            __syncthreads();
            src ^= 1;
        }
        if (tid < 256) {
            const unsigned int cumb  = scanbuf[src][tid];
            const unsigned int cumb1 = (tid == 255) ? 0u : scanbuf[src][tid + 1];
            if (cumb >= (unsigned int)r1 && cumb1 < (unsigned int)r1)
                s_thresh = (bucket << 8) | (unsigned int)tid;
        }
        __syncthreads();
    }
    const unsigned int cut16 = ftok16(k16tof(s_thresh) - MARGIN);

    int c = 0;
    for (int i = tid; i < VOC; i += TT)
        if ((unsigned int)keys16[i] >= cut16) c++;
    cscan[0][tid] = (unsigned int)c;
    __syncthreads();
    int src = 0;
    for (int off = 1; off < TT; off <<= 1) {
        unsigned int val = cscan[src][tid];
        if (tid >= off) val += cscan[src][tid - off];
        __syncthreads();
        cscan[src ^ 1][tid] = val;
        __syncthreads();
        src ^= 1;
    }
    int pos = (tid == 0) ? 0 : (int)cscan[src][tid - 1];
    const int count = min((int)cscan[src][TT - 1], MAXSEL);

    for (int i = tid; i < VOC; i += TT) {
        if ((unsigned int)keys16[i] >= cut16) {
            if (pos < MAXSEL) sel_idx[pos] = i;
            pos++;
        }
    }
    __syncthreads();

    for (int s = wid; s < count; s += (TT / 32)) {
        const int idx = sel_idx[s];
        const float4* kr = reinterpret_cast<const float4*>(Kf + (size_t)idx * DIM);
        float sum = 0.0f;
#pragma unroll
        for (int j = 0; j < 4; j++) {
            const float4 a = kr[lane * 4 + j];
            const float4 qv = *reinterpret_cast<const float4*>(&qrow[lane * 16 + j * 4]);
            sum += qv.x * a.x + qv.y * a.y + qv.z * a.z + qv.w * a.w;
        }
#pragma unroll
        for (int off = 16; off > 0; off >>= 1)
            sum += __shfl_xor_sync(0xFFFFFFFFu, sum, off);
        if (lane == 0) sel_val[s] = sum;
    }
    __syncthreads();

    float mx = -3.4e38f;
    if (tid < count) mx = sel_val[tid];
    f_red[tid] = mx;
    __syncthreads();
#pragma unroll
    for (int s = TT / 2; s > 0; s >>= 1) {
        if (tid < s) f_red[tid] = fmaxf(f_red[tid], f_red[tid + s]);
        __syncthreads();
    }
    const float m = f_red[0];

    if (tid < count) {
        const float mine = sel_val[tid];
        int greater = 0;
        for (int j = 0; j < count; j++)
            greater += (sel_val[j] > mine);
        sel_w[tid] = (greater < TOPK) ? expf(mine - m) : 0.0f;
    }
    __syncthreads();

    float z = (tid < count) ? sel_w[tid] : 0.0f;
    f_red[tid] = z;
    __syncthreads();
#pragma unroll
    for (int s = TT / 2; s > 0; s >>= 1) {
        if (tid < s) f_red[tid] += f_red[tid + s];
        __syncthreads();
    }
    const float Z = f_red[0];

    float acc0 = 0.0f;
    for (int s = 0; s < count; s++)
        acc0 += sel_w[s] * v[(size_t)sel_idx[s] * DIM + tid];
    out[(size_t)row * DIM + tid] = acc0 / Z;
}

// ---------------- launch ----------------------------------------------------
extern "C" void kernel_launch(void* const* d_in, const int* in_sizes, int n_in,
                              void* d_out, int out_size)
{
    const float* x  = (const float*)d_in[0];
    const float* cb = (const float*)d_in[1];
    const float* Wq = (const float*)d_in[2];
    const float* bq = (const float*)d_in[3];
    const float* Wk = (const float*)d_in[4];
    const float* bk = (const float*)d_in[5];
    const float* Wv = (const float*)d_in[6];
    const float* bv = (const float*)d_in[7];
    float* out = (float*)d_out;

    float *q, *k, *v;
    unsigned short *qb, *kb, *xh, *xl, *ch, *cl, *wh, *wl, *dots16;
    cudaGetSymbolAddress((void**)&q,      g_q);
    cudaGetSymbolAddress((void**)&k,      g_k);
    cudaGetSymbolAddress((void**)&v,      g_v);
    cudaGetSymbolAddress((void**)&qb,     g_qb);
    cudaGetSymbolAddress((void**)&kb,     g_kb);
    cudaGetSymbolAddress((void**)&xh,     g_xh);
    cudaGetSymbolAddress((void**)&xl,     g_xl);
    cudaGetSymbolAddress((void**)&ch,     g_ch);
    cudaGetSymbolAddress((void**)&cl,     g_cl);
    cudaGetSymbolAddress((void**)&wh,     g_wh);
    cudaGetSymbolAddress((void**)&wl,     g_wl);
    cudaGetSymbolAddress((void**)&dots16, g_dots16);

    cudaFuncSetAttribute(topk_softmax_gather,
                         cudaFuncAttributeMaxDynamicSharedMemorySize,
                         VOC * (int)sizeof(unsigned short));
    cudaFuncSetAttribute(dots_bf16,
                         cudaFuncAttributeMaxDynamicSharedMemorySize, DOTS_SMEM);
    cudaFuncSetAttribute(gemm_bf16x3<true>,
                         cudaFuncAttributeMaxDynamicSharedMemorySize, PROJ_SMEM);
    cudaFuncSetAttribute(gemm_bf16x3<false>,
                         cudaFuncAttributeMaxDynamicSharedMemorySize, PROJ_SMEM);

    dim3 blk(256);
    const int WN = DIM * DIM;   // 262144

    // prep: splits + W transposes
    split_bf16<<<(BATCH * DIM + 255) / 256, blk>>>(x, xh, xl, BATCH * DIM);
    split_bf16<<<(VOC * DIM + 255) / 256, blk>>>(cb, ch, cl, VOC * DIM);
    transpose_split_w<<<(WN + 255) / 256, blk>>>(Wq, wh + 0 * WN, wl + 0 * WN);
    transpose_split_w<<<(WN + 255) / 256, blk>>>(Wk, wh + 1 * WN, wl + 1 * WN);
    transpose_split_w<<<(WN + 255) / 256, blk>>>(Wv, wh + 2 * WN, wl + 2 * WN);

    // projections via bf16x3 MMA
    gemm_bf16x3<true><<<dim3(BATCH / 128, DIM / 128), blk, PROJ_SMEM>>>(
        xh, xl, wh + 0 * WN, wl + 0 * WN, bq, q, qb);
    gemm_bf16x3<true><<<dim3(VOC / 128, DIM / 128), blk, PROJ_SMEM>>>(
        ch, cl, wh + 1 * WN, wl + 1 * WN, bk, k, kb);
    gemm_bf16x3<false><<<dim3(VOC / 128, DIM / 128), blk, PROJ_SMEM>>>(
        ch, cl, wh + 2 * WN, wl + 2 * WN, bv, v, nullptr);

    // approx dots = qb @ kb^T (persistent-A), stored as bf16
    dots_bf16<<<dim3(BATCH / MT, VOC / (NSUB * 128)), blk, DOTS_SMEM>>>(
        qb, kb, dots16);

    // approx select + exact rescore + softmax + sparse gather of v
    topk_softmax_gather<<<BATCH, TT, VOC * (int)sizeof(unsigned short)>>>(
        dots16, q, k, v, out);
}

// round 16
// speedup vs baseline: 3.6313x; 1.0629x over previous
#include <cuda_runtime.h>
#include <cuda_bf16.h>
#include <cstdint>

#define VOC   32768
#define DIM   512
#define BATCH 4096
#define TOPK  64
#define MAXSEL 192
#define MARGIN 0.02f

// ---- persistent-A dots config: CTA 128m x 1024n ----
#define MT 128
#define NSUB 8
#define KCH 64
#define KITERS (DIM / KCH)        // 8 per subtile
#define GITERS (NSUB * KITERS)    // 64
#define LDHA 520
#define LDHB 72
#define A_BYTES (MT * LDHA * 2)       // 133120
#define BST_BYTES (128 * LDHB * 2)    // 18432
#define BSTAGES 3
#define DOTS_SMEM (A_BYTES + BSTAGES * BST_BYTES)

// ---- bf16x3 projection gemm config: CTA 128x128, KCH 32, 2 stages ----
#define PKCH 32
#define PKITERS (DIM / PKCH)      // 16
#define PLDH 40
#define P_AH (128 * PLDH)         // 5120 halves per plane
#define PST_HALVES (4 * P_AH)     // A hi/lo + B hi/lo
#define PST_BYTES (PST_HALVES * 2)   // 40960
#define PROJ_SMEM (2 * PST_BYTES)    // 81920

// ---------------- scratch (static device globals) ----------------------------
__device__ float g_q [(size_t)BATCH * DIM];
__device__ float g_k [(size_t)VOC * DIM];
__device__ float g_v [(size_t)VOC * DIM];
__device__ unsigned short g_qb[(size_t)BATCH * DIM];
__device__ unsigned short g_kb[(size_t)VOC * DIM];
__device__ unsigned short g_xh[(size_t)BATCH * DIM];
__device__ unsigned short g_xl[(size_t)BATCH * DIM];
__device__ unsigned short g_ch[(size_t)VOC * DIM];
__device__ unsigned short g_cl[(size_t)VOC * DIM];
__device__ unsigned short g_wh[3 * DIM * DIM];
__device__ unsigned short g_wl[3 * DIM * DIM];
__device__ unsigned short g_dots16[(size_t)BATCH * VOC];

// ---------------- PTX helpers ------------------------------------------------
__device__ __forceinline__ uint32_t smem_u32(const void* p) {
    uint32_t a;
    asm("{ .reg .u64 t; cvta.to.shared.u64 t, %1; cvt.u32.u64 %0, t; }"
        : "=r"(a) : "l"(p));
    return a;
}
#define CP_ASYNC16(dst, src) \
    asm volatile("cp.async.cg.shared.global [%0], [%1], 16;" \
                 :: "r"(dst), "l"(src) : "memory")
#define CP_COMMIT()  asm volatile("cp.async.commit_group;" ::: "memory")

__device__ __forceinline__ void mma_bf16(float& c0, float& c1, float& c2, float& c3,
                                         uint32_t a0, uint32_t a1, uint32_t a2, uint32_t a3,
                                         uint32_t b0, uint32_t b1) {
    asm volatile(
        "mma.sync.aligned.m16n8k16.row.col.f32.bf16.bf16.f32 "
        "{%0,%1,%2,%3}, {%4,%5,%6,%7}, {%8,%9}, {%0,%1,%2,%3};"
        : "+f"(c0), "+f"(c1), "+f"(c2), "+f"(c3)
        : "r"(a0), "r"(a1), "r"(a2), "r"(a3), "r"(b0), "r"(b1));
}

__device__ __forceinline__ void ldsm4(uint32_t& r0, uint32_t& r1,
                                      uint32_t& r2, uint32_t& r3, uint32_t addr) {
    asm volatile("ldmatrix.sync.aligned.m8n8.x4.shared.b16 {%0,%1,%2,%3}, [%4];"
                 : "=r"(r0), "=r"(r1), "=r"(r2), "=r"(r3) : "r"(addr));
}

// ---------------- misc helpers ----------------------------------------------
__device__ __forceinline__ unsigned int f2k16(unsigned int b) {
    return (b & 0x8000u) ? ((~b) & 0xFFFFu) : (b | 0x8000u);
}
__device__ __forceinline__ float k16tof(unsigned int k) {
    unsigned int b = (k & 0x8000u) ? (k ^ 0x8000u) : ((~k) & 0xFFFFu);
    return __uint_as_float(b << 16);
}
__device__ __forceinline__ unsigned int ftok16(float x) {
    return f2k16(__bfloat16_as_ushort(__float2bfloat16(x)));
}
__device__ __forceinline__ void bf16split(float a, unsigned short& h, unsigned short& l) {
    __nv_bfloat16 hb = __float2bfloat16(a);
    float hf = __bfloat162float(hb);
    __nv_bfloat16 lb = __float2bfloat16(a - hf);
    h = __bfloat16_as_ushort(hb);
    l = __bfloat16_as_ushort(lb);
}

// ---------------- prep: elementwise bf16 split -------------------------------
__global__ __launch_bounds__(256)
void split_bf16(const float* __restrict__ in, unsigned short* __restrict__ hi,
                unsigned short* __restrict__ lo, int n)
{
    int i = blockIdx.x * 256 + threadIdx.x;
    if (i >= n) return;
    unsigned short h, l;
    bf16split(in[i], h, l);
    hi[i] = h;
    lo[i] = l;
}

// ---------------- prep: W [K,N] -> Wt [N,K] with bf16 split ------------------
__global__ __launch_bounds__(256)
void transpose_split_w(const float* __restrict__ W,
                       unsigned short* __restrict__ Th,
                       unsigned short* __restrict__ Tl)
{
    int idx = blockIdx.x * 256 + threadIdx.x;   // n*DIM + kk
    if (idx >= DIM * DIM) return;
    int n = idx >> 9, kk = idx & (DIM - 1);
    unsigned short h, l;
    bf16split(W[kk * DIM + n], h, l);
    Th[idx] = h;
    Tl[idx] = l;
}

// ---------------- projection GEMM: C = (Ah+Al)(Bh+Bl)^T + bias ---------------
// PASSES==3: bf16x3 emulation (hi*hi + lo*hi + hi*lo), fp32 accum.
// PASSES==1: single-pass bf16 (hi*hi only) — for precision-insensitive v.
template <bool WB, int PASSES>
__global__ __launch_bounds__(256, 2)
void gemm_bf16x3(const unsigned short* __restrict__ Ah,
                 const unsigned short* __restrict__ Al,
                 const unsigned short* __restrict__ Bh,
                 const unsigned short* __restrict__ Bl,
                 const float* __restrict__ bias,
                 float* __restrict__ C, unsigned short* __restrict__ Cb)
{
    extern __shared__ __align__(16) unsigned short smem[];
    const uint32_t sb = smem_u32(smem);

    const int tid = threadIdx.x;
    const int lane = tid & 31;
    const int wid = tid >> 5;
    const int warpM = wid >> 1;
    const int warpN = wid & 1;
    const int bm = blockIdx.x * 128;
    const int bn = blockIdx.y * 128;

    const int r = lane >> 2;
    const int c4 = lane & 3;

    float acc[2][8][4];
#pragma unroll
    for (int mt = 0; mt < 2; mt++)
#pragma unroll
        for (int nt = 0; nt < 8; nt++)
#pragma unroll
            for (int i = 0; i < 4; i++) acc[mt][nt][i] = 0.0f;

    const int plane = tid >> 7;       // 0: hi, 1: lo
    const int prow = tid & 127;
    const unsigned short* gaBase = (plane ? Al : Ah) + (size_t)(bm + prow) * DIM;
    const unsigned short* gbBase = (plane ? Bl : Bh) + (size_t)(bn + prow) * DIM;
    const uint32_t daBase = sb + ((uint32_t)plane * P_AH + (uint32_t)prow * PLDH) * 2;
    const uint32_t dbBase = sb + ((uint32_t)(2 + plane) * P_AH + (uint32_t)prow * PLDH) * 2;

    auto prefetch = [&](int it, int s) {
        if (PASSES == 3 || plane == 0) {
            const unsigned short* ga = gaBase + it * PKCH;
            const unsigned short* gb = gbBase + it * PKCH;
            const uint32_t da = daBase + (uint32_t)s * PST_BYTES;
            const uint32_t db = dbBase + (uint32_t)s * PST_BYTES;
#pragma unroll
            for (int c = 0; c < 4; c++) {
                CP_ASYNC16(da + c * 16, ga + c * 8);
                CP_ASYNC16(db + c * 16, gb + c * 8);
            }
        }
        CP_COMMIT();
    };

    prefetch(0, 0);
    prefetch(1, 1);

    const int l8 = lane & 7;
    const int gq = lane >> 3;
    uint32_t aoffb[2];
#pragma unroll
    for (int mt = 0; mt < 2; mt++) {
        const int row = warpM * 32 + mt * 16 + l8 + (gq & 1) * 8;
        const int col = (gq >> 1) * 8;
        aoffb[mt] = ((uint32_t)row * PLDH + col) * 2;
    }
    uint32_t boffb[4];
#pragma unroll
    for (int p = 0; p < 4; p++) {
        const int row = warpN * 64 + p * 16 + l8 + (gq >> 1) * 8;
        const int col = (gq & 1) * 8;
        boffb[p] = ((uint32_t)(2 * P_AH) + (uint32_t)row * PLDH + col) * 2;
    }
    const uint32_t LO_A = (uint32_t)P_AH * 2;

    for (int it = 0; it < PKITERS; it++) {
        if (it + 1 < PKITERS)
            asm volatile("cp.async.wait_group %0;" :: "n"(1));
        else
            asm volatile("cp.async.wait_group %0;" :: "n"(0));
        __syncthreads();

        const uint32_t stb = sb + (uint32_t)(it & 1) * PST_BYTES;

#pragma unroll
        for (int ks = 0; ks < 2; ks++) {
            const uint32_t koff = (uint32_t)ks * 32;
            uint32_t ah[2][4], al[2][4], bh[4][4], bl[4][4];
#pragma unroll
            for (int mt = 0; mt < 2; mt++) {
                ldsm4(ah[mt][0], ah[mt][1], ah[mt][2], ah[mt][3],
                      stb + aoffb[mt] + koff);
                if (PASSES == 3)
                    ldsm4(al[mt][0], al[mt][1], al[mt][2], al[mt][3],
                          stb + aoffb[mt] + LO_A + koff);
            }
#pragma unroll
            for (int p = 0; p < 4; p++) {
                ldsm4(bh[p][0], bh[p][1], bh[p][2], bh[p][3],
                      stb + boffb[p] + koff);
                if (PASSES == 3)
                    ldsm4(bl[p][0], bl[p][1], bl[p][2], bl[p][3],
                          stb + boffb[p] + LO_A + koff);
            }
#pragma unroll
            for (int mt = 0; mt < 2; mt++)
#pragma unroll
                for (int p = 0; p < 4; p++) {
                    float* a0 = acc[mt][2 * p];
                    float* a1 = acc[mt][2 * p + 1];
                    mma_bf16(a0[0], a0[1], a0[2], a0[3],
                             ah[mt][0], ah[mt][1], ah[mt][2], ah[mt][3],
                             bh[p][0], bh[p][1]);
                    mma_bf16(a1[0], a1[1], a1[2], a1[3],
                             ah[mt][0], ah[mt][1], ah[mt][2], ah[mt][3],
                             bh[p][2], bh[p][3]);
                    if (PASSES == 3) {
                        mma_bf16(a0[0], a0[1], a0[2], a0[3],
                                 al[mt][0], al[mt][1], al[mt][2], al[mt][3],
                                 bh[p][0], bh[p][1]);
                        mma_bf16(a0[0], a0[1], a0[2], a0[3],
                                 ah[mt][0], ah[mt][1], ah[mt][2], ah[mt][3],
                                 bl[p][0], bl[p][1]);
                        mma_bf16(a1[0], a1[1], a1[2], a1[3],
                                 al[mt][0], al[mt][1], al[mt][2], al[mt][3],
                                 bh[p][2], bh[p][3]);
                        mma_bf16(a1[0], a1[1], a1[2], a1[3],
                                 ah[mt][0], ah[mt][1], ah[mt][2], ah[mt][3],
                                 bl[p][2], bl[p][3]);
                    }
                }
        }

        if (it + 2 < PKITERS) {
            __syncthreads();
            prefetch(it + 2, it & 1);
        }
    }

    // epilogue: add bias, write fp32 (and bf16 if WB)
#pragma unroll
    for (int mt = 0; mt < 2; mt++) {
        const int row = bm + warpM * 32 + mt * 16 + r;
#pragma unroll
        for (int nt = 0; nt < 8; nt++) {
            const int col = bn + warpN * 64 + nt * 8 + 2 * c4;
            const float b0 = bias[col];
            const float b1 = bias[col + 1];
            float* a = acc[mt][nt];
            float2 v0; v0.x = a[0] + b0; v0.y = a[1] + b1;
            float2 v1; v1.x = a[2] + b0; v1.y = a[3] + b1;
            *reinterpret_cast<float2*>(C + (size_t)row * DIM + col) = v0;
            *reinterpret_cast<float2*>(C + (size_t)(row + 8) * DIM + col) = v1;
            if (WB) {
                unsigned int p0 =
                    (unsigned int)__bfloat16_as_ushort(__float2bfloat16(v0.x))
                    | ((unsigned int)__bfloat16_as_ushort(__float2bfloat16(v0.y)) << 16);
                unsigned int p1 =
                    (unsigned int)__bfloat16_as_ushort(__float2bfloat16(v1.x))
                    | ((unsigned int)__bfloat16_as_ushort(__float2bfloat16(v1.y)) << 16);
                *reinterpret_cast<unsigned int*>(Cb + (size_t)row * DIM + col) = p0;
                *reinterpret_cast<unsigned int*>(Cb + (size_t)(row + 8) * DIM + col) = p1;
            }
        }
    }
}

// ---------------- dots_approx = qb @ kb^T, persistent-A bf16 mma -------------
__global__ __launch_bounds__(256, 1)
void dots_bf16(const unsigned short* __restrict__ Ab,
               const unsigned short* __restrict__ Bb,
               unsigned short* __restrict__ C16)
{
    extern __shared__ __align__(16) unsigned short smem[];
    const uint32_t sb = smem_u32(smem);

    const int tid = threadIdx.x;
    const int lane = tid & 31;
    const int wid = tid >> 5;
    const int warpM = wid >> 1;
    const int warpN = wid & 1;
    const int bm = blockIdx.x * MT;
    const int bn0 = blockIdx.y * (NSUB * 128);

    const int r = lane >> 2;
    const int c4 = lane & 3;

    {
        const int row = tid >> 1;
        const int half = tid & 1;
        const unsigned short* g = Ab + (size_t)(bm + row) * DIM + half * 256;
        const uint32_t d = sb + ((uint32_t)row * LDHA + half * 256) * 2;
#pragma unroll
        for (int c = 0; c < 32; c++)
            CP_ASYNC16(d + c * 16, g + c * 8);
        CP_COMMIT();
    }

    auto prefetchB = [&](int g, int s) {
        const int row = tid >> 1;
        const int seg = tid & 1;
        const unsigned short* gp = Bb
            + (size_t)(bn0 + (g >> 3) * 128 + row) * DIM + (g & 7) * KCH + seg * 32;
        const uint32_t d = sb + A_BYTES + (uint32_t)s * BST_BYTES
                         + ((uint32_t)row * LDHB + seg * 32) * 2;
#pragma unroll
        for (int c = 0; c < 4; c++)
            CP_ASYNC16(d + c * 16, gp + c * 8);
        CP_COMMIT();
    };

    prefetchB(0, 0);
    prefetchB(1, 1);

    const int l8 = lane & 7;
    const int gq = lane >> 3;
    uint32_t aoffb[2];
#pragma unroll
    for (int mt = 0; mt < 2; mt++) {
        const int row = warpM * 32 + mt * 16 + l8 + (gq & 1) * 8;
        const int col = (gq >> 1) * 8;
        aoffb[mt] = ((uint32_t)row * LDHA + col) * 2;
    }
    uint32_t boffb[4];
#pragma unroll
    for (int p = 0; p < 4; p++) {
        const int row = warpN * 64 + p * 16 + l8 + (gq >> 1) * 8;
        const int col = (gq & 1) * 8;
        boffb[p] = ((uint32_t)row * LDHB + col) * 2;
    }

    float acc[2][8][4];

    int stage = 0;
    for (int g = 0; g < GITERS; g++) {
        const int it = g & 7;
        if (it == 0) {
#pragma unroll
            for (int mt = 0; mt < 2; mt++)
#pragma unroll
                for (int nt = 0; nt < 8; nt++)
#pragma unroll
                    for (int i = 0; i < 4; i++) acc[mt][nt][i] = 0.0f;
        }

        if (g + 1 < GITERS)
            asm volatile("cp.async.wait_group %0;" :: "n"(1));
        else
            asm volatile("cp.async.wait_group %0;" :: "n"(0));
        __syncthreads();

        if (g + 2 < GITERS) {
            int ps = stage + 2; if (ps >= BSTAGES) ps -= BSTAGES;
            prefetchB(g + 2, ps);
        }

        const uint32_t stb = sb + A_BYTES + (uint32_t)stage * BST_BYTES;
        const uint32_t akoff = (uint32_t)it * KCH * 2;

#pragma unroll
        for (int ks = 0; ks < 4; ks++) {
            const uint32_t koff = (uint32_t)ks * 32;
            uint32_t a[2][4], b[4][4];
#pragma unroll
            for (int mt = 0; mt < 2; mt++)
                ldsm4(a[mt][0], a[mt][1], a[mt][2], a[mt][3],
                      sb + aoffb[mt] + akoff + koff);
#pragma unroll
            for (int p = 0; p < 4; p++)
                ldsm4(b[p][0], b[p][1], b[p][2], b[p][3],
                      stb + boffb[p] + koff);
#pragma unroll
            for (int mt = 0; mt < 2; mt++)
#pragma unroll
                for (int p = 0; p < 4; p++) {
                    float* a0 = acc[mt][2 * p];
                    float* a1 = acc[mt][2 * p + 1];
                    mma_bf16(a0[0], a0[1], a0[2], a0[3],
                             a[mt][0], a[mt][1], a[mt][2], a[mt][3],
                             b[p][0], b[p][1]);
                    mma_bf16(a1[0], a1[1], a1[2], a1[3],
                             a[mt][0], a[mt][1], a[mt][2], a[mt][3],
                             b[p][2], b[p][3]);
                }
        }

        if (it == 7) {
            const int bn = bn0 + (g >> 3) * 128;
#pragma unroll
            for (int mt = 0; mt < 2; mt++) {
                const int row = bm + warpM * 32 + mt * 16 + r;
#pragma unroll
                for (int nt = 0; nt < 8; nt++) {
                    const int col = bn + warpN * 64 + nt * 8 + 2 * c4;
                    const float* a = acc[mt][nt];
                    unsigned int p0 =
                        (unsigned int)__bfloat16_as_ushort(__float2bfloat16(a[0]))
                        | ((unsigned int)__bfloat16_as_ushort(__float2bfloat16(a[1])) << 16);
                    unsigned int p1 =
                        (unsigned int)__bfloat16_as_ushort(__float2bfloat16(a[2]))
                        | ((unsigned int)__bfloat16_as_ushort(__float2bfloat16(a[3])) << 16);
                    *reinterpret_cast<unsigned int*>(C16 + (size_t)row * VOC + col) = p0;
                    *reinterpret_cast<unsigned int*>(C16 + (size_t)(row + 8) * VOC + col) = p1;
                }
            }
        }

        if (++stage == BSTAGES) stage = 0;
    }
}

// ---------------- per-row: approx select + exact rescore + softmax + A@V ----
#define TT 512
__global__ __launch_bounds__(TT, 2)
void topk_softmax_gather(const unsigned short* __restrict__ dots16,
                         const float* __restrict__ Q,
                         const float* __restrict__ Kf,
                         const float* __restrict__ v,
                         float* __restrict__ out)
{
    extern __shared__ unsigned short keys16[];
    __shared__ unsigned int hist[256];
    __shared__ unsigned int scanbuf[2][256];
    __shared__ unsigned int cscan[2][TT];
    __shared__ float        f_red[TT];
    __shared__ float qrow[DIM];
    __shared__ int   sel_idx[MAXSEL];
    __shared__ float sel_val[MAXSEL];
    __shared__ float sel_w[MAXSEL];
    __shared__ unsigned int s_bucket;
    __shared__ int s_r;
    __shared__ unsigned int s_thresh;

    const int tid = threadIdx.x;
    const int lane = tid & 31;
    const int wid = tid >> 5;
    const int row = blockIdx.x;
    const unsigned int* drow = reinterpret_cast<const unsigned int*>(
        dots16 + (size_t)row * VOC);

    for (int i = tid; i < VOC / 2; i += TT) {
        const unsigned int w = drow[i];
        const unsigned int k0 = f2k16(w & 0xFFFFu);
        const unsigned int k1 = f2k16(w >> 16);
        reinterpret_cast<unsigned int*>(keys16)[i] = k0 | (k1 << 16);
    }
    if (tid < DIM)
        qrow[tid] = Q[(size_t)row * DIM + tid];
    __syncthreads();

    if (tid < 256) hist[tid] = 0;
    __syncthreads();
    for (int i = tid; i < VOC; i += TT) {
        const unsigned int bin = (unsigned int)keys16[i] >> 8;
        const unsigned int mask = __match_any_sync(0xFFFFFFFFu, bin);
        if ((__ffs(mask) - 1) == lane)
            atomicAdd(&hist[bin], (unsigned int)__popc(mask));
    }
    __syncthreads();
    {
        if (tid < 256) scanbuf[0][tid] = hist[tid];
        __syncthreads();
        int src = 0;
        for (int off = 1; off < 256; off <<= 1) {
            unsigned int val = 0;
            if (tid < 256) {
                val = scanbuf[src][tid];
                if (tid + off < 256) val += scanbuf[src][tid + off];
            }
            __syncthreads();
            if (tid < 256) scanbuf[src ^ 1][tid] = val;
            __syncthreads();
            src ^= 1;
        }
        if (tid < 256) {
            const unsigned int cumb  = scanbuf[src][tid];
            const unsigned int cumb1 = (tid == 255) ? 0u : scanbuf[src][tid + 1];
            if (cumb >= TOPK && cumb1 < TOPK) {
                s_bucket = (unsigned int)tid;
                s_r = TOPK - (int)cumb1;
            }
        }
        __syncthreads();
    }
    const unsigned int bucket = s_bucket;
    const int r1 = s_r;
    __syncthreads();

    if (tid < 256) hist[tid] = 0;
    __syncthreads();
    for (int i = tid; i < VOC; i += TT) {
        const unsigned int k = keys16[i];
        if ((k >> 8) == bucket)
            atomicAdd(&hist[k & 0xFFu], 1u);
    }
    __syncthreads();
    {
        if (tid < 256) scanbuf[0][tid] = hist[tid];
        __syncthreads();
        int src = 0;
        for (int off = 1; off < 256; off <<= 1) {
            unsigned int val = 0;
            if (tid < 256) {
                val = scanbuf[src][tid];
                if (tid + off < 256) val += scanbuf[src][tid + off];
            }
            __syncthreads();
            if (tid < 256) scanbuf[src ^ 1][tid] = val;
            __syncthreads();
            src ^= 1;
        }
        if (tid < 256) {
            const unsigned int cumb  = scanbuf[src][tid];
            const unsigned int cumb1 = (tid == 255) ? 0u : scanbuf[src][tid + 1];
            if (cumb >= (unsigned int)r1 && cumb1 < (unsigned int)r1)
                s_thresh = (bucket << 8) | (unsigned int)tid;
        }
        __syncthreads();
    }
    const unsigned int cut16 = ftok16(k16tof(s_thresh) - MARGIN);

    int c = 0;
    for (int i = tid; i < VOC; i += TT)
        if ((unsigned int)keys16[i] >= cut16) c++;
    cscan[0][tid] = (unsigned int)c;
    __syncthreads();
    int src = 0;
    for (int off = 1; off < TT; off <<= 1) {
        unsigned int val = cscan[src][tid];
        if (tid >= off) val += cscan[src][tid - off];
        __syncthreads();
        cscan[src ^ 1][tid] = val;
        __syncthreads();
        src ^= 1;
    }
    int pos = (tid == 0) ? 0 : (int)cscan[src][tid - 1];
    const int count = min((int)cscan[src][TT - 1], MAXSEL);

    for (int i = tid; i < VOC; i += TT) {
        if ((unsigned int)keys16[i] >= cut16) {
            if (pos < MAXSEL) sel_idx[pos] = i;
            pos++;
        }
    }
    __syncthreads();

    for (int s = wid; s < count; s += (TT / 32)) {
        const int idx = sel_idx[s];
        const float4* kr = reinterpret_cast<const float4*>(Kf + (size_t)idx * DIM);
        float sum = 0.0f;
#pragma unroll
        for (int j = 0; j < 4; j++) {
            const float4 a = kr[lane * 4 + j];
            const float4 qv = *reinterpret_cast<const float4*>(&qrow[lane * 16 + j * 4]);
            sum += qv.x * a.x + qv.y * a.y + qv.z * a.z + qv.w * a.w;
        }
#pragma unroll
        for (int off = 16; off > 0; off >>= 1)
            sum += __shfl_xor_sync(0xFFFFFFFFu, sum, off);
        if (lane == 0) sel_val[s] = sum;
    }
    __syncthreads();

    float mx = -3.4e38f;
    if (tid < count) mx = sel_val[tid];
    f_red[tid] = mx;
    __syncthreads();
#pragma unroll
    for (int s = TT / 2; s > 0; s >>= 1) {
        if (tid < s) f_red[tid] = fmaxf(f_red[tid], f_red[tid + s]);
        __syncthreads();
    }
    const float m = f_red[0];

    if (tid < count) {
        const float mine = sel_val[tid];
        int greater = 0;
        for (int j = 0; j < count; j++)
            greater += (sel_val[j] > mine);
        sel_w[tid] = (greater < TOPK) ? expf(mine - m) : 0.0f;
    }
    __syncthreads();

    float z = (tid < count) ? sel_w[tid] : 0.0f;
    f_red[tid] = z;
    __syncthreads();
#pragma unroll
    for (int s = TT / 2; s > 0; s >>= 1) {
        if (tid < s) f_red[tid] += f_red[tid + s];
        __syncthreads();
    }
    const float Z = f_red[0];

    float acc0 = 0.0f;
    for (int s = 0; s < count; s++)
        acc0 += sel_w[s] * v[(size_t)sel_idx[s] * DIM + tid];
    out[(size_t)row * DIM + tid] = acc0 / Z;
}

// ---------------- launch ----------------------------------------------------
extern "C" void kernel_launch(void* const* d_in, const int* in_sizes, int n_in,
                              void* d_out, int out_size)
{
    const float* x  = (const float*)d_in[0];
    const float* cb = (const float*)d_in[1];
    const float* Wq = (const float*)d_in[2];
    const float* bq = (const float*)d_in[3];
    const float* Wk = (const float*)d_in[4];
    const float* bk = (const float*)d_in[5];
    const float* Wv = (const float*)d_in[6];
    const float* bv = (const float*)d_in[7];
    float* out = (float*)d_out;

    float *q, *k, *v;
    unsigned short *qb, *kb, *xh, *xl, *ch, *cl, *wh, *wl, *dots16;
    cudaGetSymbolAddress((void**)&q,      g_q);
    cudaGetSymbolAddress((void**)&k,      g_k);
    cudaGetSymbolAddress((void**)&v,      g_v);
    cudaGetSymbolAddress((void**)&qb,     g_qb);
    cudaGetSymbolAddress((void**)&kb,     g_kb);
    cudaGetSymbolAddress((void**)&xh,     g_xh);
    cudaGetSymbolAddress((void**)&xl,     g_xl);
    cudaGetSymbolAddress((void**)&ch,     g_ch);
    cudaGetSymbolAddress((void**)&cl,     g_cl);
    cudaGetSymbolAddress((void**)&wh,     g_wh);
    cudaGetSymbolAddress((void**)&wl,     g_wl);
    cudaGetSymbolAddress((void**)&dots16, g_dots16);

    cudaFuncSetAttribute(topk_softmax_gather,
                         cudaFuncAttributeMaxDynamicSharedMemorySize,
                         VOC * (int)sizeof(unsigned short));
    cudaFuncSetAttribute(dots_bf16,
                         cudaFuncAttributeMaxDynamicSharedMemorySize, DOTS_SMEM);
    cudaFuncSetAttribute((const void*)gemm_bf16x3<true, 3>,
                         cudaFuncAttributeMaxDynamicSharedMemorySize, PROJ_SMEM);
    cudaFuncSetAttribute((const void*)gemm_bf16x3<false, 1>,
                         cudaFuncAttributeMaxDynamicSharedMemorySize, PROJ_SMEM);

    dim3 blk(256);
    const int WN = DIM * DIM;   // 262144

    // prep: splits + W transposes
    split_bf16<<<(BATCH * DIM + 255) / 256, blk>>>(x, xh, xl, BATCH * DIM);
    split_bf16<<<(VOC * DIM + 255) / 256, blk>>>(cb, ch, cl, VOC * DIM);
    transpose_split_w<<<(WN + 255) / 256, blk>>>(Wq, wh + 0 * WN, wl + 0 * WN);
    transpose_split_w<<<(WN + 255) / 256, blk>>>(Wk, wh + 1 * WN, wl + 1 * WN);
    transpose_split_w<<<(WN + 255) / 256, blk>>>(Wv, wh + 2 * WN, wl + 2 * WN);

    // projections via bf16 MMA: q,k x3 (selection-grade), v x1 (non-selective)
    gemm_bf16x3<true, 3><<<dim3(BATCH / 128, DIM / 128), blk, PROJ_SMEM>>>(
        xh, xl, wh + 0 * WN, wl + 0 * WN, bq, q, qb);
    gemm_bf16x3<true, 3><<<dim3(VOC / 128, DIM / 128), blk, PROJ_SMEM>>>(
        ch, cl, wh + 1 * WN, wl + 1 * WN, bk, k, kb);
    gemm_bf16x3<false, 1><<<dim3(VOC / 128, DIM / 128), blk, PROJ_SMEM>>>(
        ch, cl, wh + 2 * WN, wl + 2 * WN, bv, v, nullptr);

    // approx dots = qb @ kb^T (persistent-A), stored as bf16
    dots_bf16<<<dim3(BATCH / MT, VOC / (NSUB * 128)), blk, DOTS_SMEM>>>(
        qb, kb, dots16);

    // approx select + exact rescore + softmax + sparse gather of v
    topk_softmax_gather<<<BATCH, TT, VOC * (int)sizeof(unsigned short)>>>(
        dots16, q, k, v, out);
}

// round 17
// speedup vs baseline: 3.6688x; 1.0103x over previous
#include <cuda_runtime.h>
#include <cuda_bf16.h>
#include <cstdint>

#define VOC   32768
#define DIM   512
#define BATCH 4096
#define TOPK  64
#define MAXSEL 192
#define MARGIN 0.02f

// ---- persistent-A dots config: CTA 128m x 1024n, 512 threads (16 warps) ----
#define MT 128
#define NSUB 8
#define KCH 64
#define KITERS (DIM / KCH)        // 8 per subtile
#define GITERS (NSUB * KITERS)    // 64
#define LDHA 520
#define LDHB 72
#define A_BYTES (MT * LDHA * 2)       // 133120
#define BST_BYTES (128 * LDHB * 2)    // 18432
#define BSTAGES 3
#define DOTS_SMEM (A_BYTES + BSTAGES * BST_BYTES)
#define DT 512

// ---- bf16x3 projection gemm config: CTA 128x128, KCH 32, 2 stages ----
#define PKCH 32
#define PKITERS (DIM / PKCH)      // 16
#define PLDH 40
#define P_AH (128 * PLDH)         // 5120 halves per plane
#define PST_HALVES (4 * P_AH)
#define PST_BYTES (PST_HALVES * 2)   // 40960
#define PROJ_SMEM (2 * PST_BYTES)    // 81920

// ---------------- scratch (static device globals) ----------------------------
__device__ float g_q [(size_t)BATCH * DIM];
__device__ float g_k [(size_t)VOC * DIM];
__device__ float g_v [(size_t)VOC * DIM];
__device__ unsigned short g_qb[(size_t)BATCH * DIM];
__device__ unsigned short g_kb[(size_t)VOC * DIM];
__device__ unsigned short g_xh[(size_t)BATCH * DIM];
__device__ unsigned short g_xl[(size_t)BATCH * DIM];
__device__ unsigned short g_ch[(size_t)VOC * DIM];
__device__ unsigned short g_cl[(size_t)VOC * DIM];
__device__ unsigned short g_wh[3 * DIM * DIM];
__device__ unsigned short g_wl[3 * DIM * DIM];
__device__ unsigned short g_dots16[(size_t)BATCH * VOC];

// ---------------- PTX helpers ------------------------------------------------
__device__ __forceinline__ uint32_t smem_u32(const void* p) {
    uint32_t a;
    asm("{ .reg .u64 t; cvta.to.shared.u64 t, %1; cvt.u32.u64 %0, t; }"
        : "=r"(a) : "l"(p));
    return a;
}
#define CP_ASYNC16(dst, src) \
    asm volatile("cp.async.cg.shared.global [%0], [%1], 16;" \
                 :: "r"(dst), "l"(src) : "memory")
#define CP_COMMIT()  asm volatile("cp.async.commit_group;" ::: "memory")

__device__ __forceinline__ void mma_bf16(float& c0, float& c1, float& c2, float& c3,
                                         uint32_t a0, uint32_t a1, uint32_t a2, uint32_t a3,
                                         uint32_t b0, uint32_t b1) {
    asm volatile(
        "mma.sync.aligned.m16n8k16.row.col.f32.bf16.bf16.f32 "
        "{%0,%1,%2,%3}, {%4,%5,%6,%7}, {%8,%9}, {%0,%1,%2,%3};"
        : "+f"(c0), "+f"(c1), "+f"(c2), "+f"(c3)
        : "r"(a0), "r"(a1), "r"(a2), "r"(a3), "r"(b0), "r"(b1));
}

__device__ __forceinline__ void ldsm4(uint32_t& r0, uint32_t& r1,
                                      uint32_t& r2, uint32_t& r3, uint32_t addr) {
    asm volatile("ldmatrix.sync.aligned.m8n8.x4.shared.b16 {%0,%1,%2,%3}, [%4];"
                 : "=r"(r0), "=r"(r1), "=r"(r2), "=r"(r3) : "r"(addr));
}

// ---------------- misc helpers ----------------------------------------------
__device__ __forceinline__ unsigned int f2k16(unsigned int b) {
    return (b & 0x8000u) ? ((~b) & 0xFFFFu) : (b | 0x8000u);
}
__device__ __forceinline__ float k16tof(unsigned int k) {
    unsigned int b = (k & 0x8000u) ? (k ^ 0x8000u) : ((~k) & 0xFFFFu);
    return __uint_as_float(b << 16);
}
__device__ __forceinline__ unsigned int ftok16(float x) {
    return f2k16(__bfloat16_as_ushort(__float2bfloat16(x)));
}
__device__ __forceinline__ void bf16split(float a, unsigned short& h, unsigned short& l) {
    __nv_bfloat16 hb = __float2bfloat16(a);
    float hf = __bfloat162float(hb);
    __nv_bfloat16 lb = __float2bfloat16(a - hf);
    h = __bfloat16_as_ushort(hb);
    l = __bfloat16_as_ushort(lb);
}

// ---------------- prep: elementwise bf16 split -------------------------------
__global__ __launch_bounds__(256)
void split_bf16(const float* __restrict__ in, unsigned short* __restrict__ hi,
                unsigned short* __restrict__ lo, int n)
{
    int i = blockIdx.x * 256 + threadIdx.x;
    if (i >= n) return;
    unsigned short h, l;
    bf16split(in[i], h, l);
    hi[i] = h;
    lo[i] = l;
}

// ---------------- prep: W [K,N] -> Wt [N,K] with bf16 split ------------------
__global__ __launch_bounds__(256)
void transpose_split_w(const float* __restrict__ W,
                       unsigned short* __restrict__ Th,
                       unsigned short* __restrict__ Tl)
{
    int idx = blockIdx.x * 256 + threadIdx.x;
    if (idx >= DIM * DIM) return;
    int n = idx >> 9, kk = idx & (DIM - 1);
    unsigned short h, l;
    bf16split(W[kk * DIM + n], h, l);
    Th[idx] = h;
    Tl[idx] = l;
}

// ---------------- projection GEMM: C = (Ah+Al)(Bh+Bl)^T + bias ---------------
template <bool WB, int PASSES>
__global__ __launch_bounds__(256, 2)
void gemm_bf16x3(const unsigned short* __restrict__ Ah,
                 const unsigned short* __restrict__ Al,
                 const unsigned short* __restrict__ Bh,
                 const unsigned short* __restrict__ Bl,
                 const float* __restrict__ bias,
                 float* __restrict__ C, unsigned short* __restrict__ Cb)
{
    extern __shared__ __align__(16) unsigned short smem[];
    const uint32_t sb = smem_u32(smem);

    const int tid = threadIdx.x;
    const int lane = tid & 31;
    const int wid = tid >> 5;
    const int warpM = wid >> 1;
    const int warpN = wid & 1;
    const int bm = blockIdx.x * 128;
    const int bn = blockIdx.y * 128;

    const int r = lane >> 2;
    const int c4 = lane & 3;

    float acc[2][8][4];
#pragma unroll
    for (int mt = 0; mt < 2; mt++)
#pragma unroll
        for (int nt = 0; nt < 8; nt++)
#pragma unroll
            for (int i = 0; i < 4; i++) acc[mt][nt][i] = 0.0f;

    const int plane = tid >> 7;
    const int prow = tid & 127;
    const unsigned short* gaBase = (plane ? Al : Ah) + (size_t)(bm + prow) * DIM;
    const unsigned short* gbBase = (plane ? Bl : Bh) + (size_t)(bn + prow) * DIM;
    const uint32_t daBase = sb + ((uint32_t)plane * P_AH + (uint32_t)prow * PLDH) * 2;
    const uint32_t dbBase = sb + ((uint32_t)(2 + plane) * P_AH + (uint32_t)prow * PLDH) * 2;

    auto prefetch = [&](int it, int s) {
        if (PASSES == 3 || plane == 0) {
            const unsigned short* ga = gaBase + it * PKCH;
            const unsigned short* gb = gbBase + it * PKCH;
            const uint32_t da = daBase + (uint32_t)s * PST_BYTES;
            const uint32_t db = dbBase + (uint32_t)s * PST_BYTES;
#pragma unroll
            for (int c = 0; c < 4; c++) {
                CP_ASYNC16(da + c * 16, ga + c * 8);
                CP_ASYNC16(db + c * 16, gb + c * 8);
            }
        }
        CP_COMMIT();
    };

    prefetch(0, 0);
    prefetch(1, 1);

    const int l8 = lane & 7;
    const int gq = lane >> 3;
    uint32_t aoffb[2];
#pragma unroll
    for (int mt = 0; mt < 2; mt++) {
        const int row = warpM * 32 + mt * 16 + l8 + (gq & 1) * 8;
        const int col = (gq >> 1) * 8;
        aoffb[mt] = ((uint32_t)row * PLDH + col) * 2;
    }
    uint32_t boffb[4];
#pragma unroll
    for (int p = 0; p < 4; p++) {
        const int row = warpN * 64 + p * 16 + l8 + (gq >> 1) * 8;
        const int col = (gq & 1) * 8;
        boffb[p] = ((uint32_t)(2 * P_AH) + (uint32_t)row * PLDH + col) * 2;
    }
    const uint32_t LO_A = (uint32_t)P_AH * 2;

    for (int it = 0; it < PKITERS; it++) {
        if (it + 1 < PKITERS)
            asm volatile("cp.async.wait_group %0;" :: "n"(1));
        else
            asm volatile("cp.async.wait_group %0;" :: "n"(0));
        __syncthreads();

        const uint32_t stb = sb + (uint32_t)(it & 1) * PST_BYTES;

#pragma unroll
        for (int ks = 0; ks < 2; ks++) {
            const uint32_t koff = (uint32_t)ks * 32;
            uint32_t ah[2][4], al[2][4], bh[4][4], bl[4][4];
#pragma unroll
            for (int mt = 0; mt < 2; mt++) {
                ldsm4(ah[mt][0], ah[mt][1], ah[mt][2], ah[mt][3],
                      stb + aoffb[mt] + koff);
                if (PASSES == 3)
                    ldsm4(al[mt][0], al[mt][1], al[mt][2], al[mt][3],
                          stb + aoffb[mt] + LO_A + koff);
            }
#pragma unroll
            for (int p = 0; p < 4; p++) {
                ldsm4(bh[p][0], bh[p][1], bh[p][2], bh[p][3],
                      stb + boffb[p] + koff);
                if (PASSES == 3)
                    ldsm4(bl[p][0], bl[p][1], bl[p][2], bl[p][3],
                          stb + boffb[p] + LO_A + koff);
            }
#pragma unroll
            for (int mt = 0; mt < 2; mt++)
#pragma unroll
                for (int p = 0; p < 4; p++) {
                    float* a0 = acc[mt][2 * p];
                    float* a1 = acc[mt][2 * p + 1];
                    mma_bf16(a0[0], a0[1], a0[2], a0[3],
                             ah[mt][0], ah[mt][1], ah[mt][2], ah[mt][3],
                             bh[p][0], bh[p][1]);
                    mma_bf16(a1[0], a1[1], a1[2], a1[3],
                             ah[mt][0], ah[mt][1], ah[mt][2], ah[mt][3],
                             bh[p][2], bh[p][3]);
                    if (PASSES == 3) {
                        mma_bf16(a0[0], a0[1], a0[2], a0[3],
                                 al[mt][0], al[mt][1], al[mt][2], al[mt][3],
                                 bh[p][0], bh[p][1]);
                        mma_bf16(a0[0], a0[1], a0[2], a0[3],
                                 ah[mt][0], ah[mt][1], ah[mt][2], ah[mt][3],
                                 bl[p][0], bl[p][1]);
                        mma_bf16(a1[0], a1[1], a1[2], a1[3],
                                 al[mt][0], al[mt][1], al[mt][2], al[mt][3],
                                 bh[p][2], bh[p][3]);
                        mma_bf16(a1[0], a1[1], a1[2], a1[3],
                                 ah[mt][0], ah[mt][1], ah[mt][2], ah[mt][3],
                                 bl[p][2], bl[p][3]);
                    }
                }
        }

        if (it + 2 < PKITERS) {
            __syncthreads();
            prefetch(it + 2, it & 1);
        }
    }

#pragma unroll
    for (int mt = 0; mt < 2; mt++) {
        const int row = bm + warpM * 32 + mt * 16 + r;
#pragma unroll
        for (int nt = 0; nt < 8; nt++) {
            const int col = bn + warpN * 64 + nt * 8 + 2 * c4;
            const float b0 = bias[col];
            const float b1 = bias[col + 1];
            float* a = acc[mt][nt];
            float2 v0; v0.x = a[0] + b0; v0.y = a[1] + b1;
            float2 v1; v1.x = a[2] + b0; v1.y = a[3] + b1;
            *reinterpret_cast<float2*>(C + (size_t)row * DIM + col) = v0;
            *reinterpret_cast<float2*>(C + (size_t)(row + 8) * DIM + col) = v1;
            if (WB) {
                unsigned int p0 =
                    (unsigned int)__bfloat16_as_ushort(__float2bfloat16(v0.x))
                    | ((unsigned int)__bfloat16_as_ushort(__float2bfloat16(v0.y)) << 16);
                unsigned int p1 =
                    (unsigned int)__bfloat16_as_ushort(__float2bfloat16(v1.x))
                    | ((unsigned int)__bfloat16_as_ushort(__float2bfloat16(v1.y)) << 16);
                *reinterpret_cast<unsigned int*>(Cb + (size_t)row * DIM + col) = p0;
                *reinterpret_cast<unsigned int*>(Cb + (size_t)(row + 8) * DIM + col) = p1;
            }
        }
    }
}

// ---------------- dots_approx = qb @ kb^T, persistent-A, 512 threads ---------
// CTA 128m x 1024n, 16 warps of 16x64. A resident; B 3-stage ring.
__global__ __launch_bounds__(DT, 1)
void dots_bf16(const unsigned short* __restrict__ Ab,
               const unsigned short* __restrict__ Bb,
               unsigned short* __restrict__ C16)
{
    extern __shared__ __align__(16) unsigned short smem[];
    const uint32_t sb = smem_u32(smem);

    const int tid = threadIdx.x;
    const int lane = tid & 31;
    const int wid = tid >> 5;        // 0..15
    const int warpM = wid >> 1;      // 0..7 -> 16 rows each
    const int warpN = wid & 1;       // 0..1 -> 64 cols
    const int bm = blockIdx.x * MT;
    const int bn0 = blockIdx.y * (NSUB * 128);

    const int r = lane >> 2;
    const int c4 = lane & 3;

    // ---- one-time A load: 4 threads/row, 128 halves each (16 x 16B) ----
    {
        const int row = tid >> 2;
        const int q4 = tid & 3;
        const unsigned short* g = Ab + (size_t)(bm + row) * DIM + q4 * 128;
        const uint32_t d = sb + ((uint32_t)row * LDHA + q4 * 128) * 2;
#pragma unroll
        for (int c = 0; c < 16; c++)
            CP_ASYNC16(d + c * 16, g + c * 8);
        CP_COMMIT();
    }

    // ---- B chunk prefetch: 4 threads/row, 16 halves each (2 x 16B) ----
    auto prefetchB = [&](int g, int s) {
        const int row = tid >> 2;
        const int seg = tid & 3;
        const unsigned short* gp = Bb
            + (size_t)(bn0 + (g >> 3) * 128 + row) * DIM + (g & 7) * KCH + seg * 16;
        const uint32_t d = sb + A_BYTES + (uint32_t)s * BST_BYTES
                         + ((uint32_t)row * LDHB + seg * 16) * 2;
        CP_ASYNC16(d, gp);
        CP_ASYNC16(d + 16, gp + 8);
        CP_COMMIT();
    };

    prefetchB(0, 0);
    prefetchB(1, 1);

    const int l8 = lane & 7;
    const int gq = lane >> 3;
    const uint32_t aoffb = (((uint32_t)(warpM * 16 + l8 + (gq & 1) * 8)) * LDHA
                            + (gq >> 1) * 8) * 2;
    uint32_t boffb[4];
#pragma unroll
    for (int p = 0; p < 4; p++) {
        const int row = warpN * 64 + p * 16 + l8 + (gq >> 1) * 8;
        const int col = (gq & 1) * 8;
        boffb[p] = ((uint32_t)row * LDHB + col) * 2;
    }

    float acc[8][4];

    int stage = 0;
    for (int g = 0; g < GITERS; g++) {
        const int it = g & 7;
        if (it == 0) {
#pragma unroll
            for (int nt = 0; nt < 8; nt++)
#pragma unroll
                for (int i = 0; i < 4; i++) acc[nt][i] = 0.0f;
        }

        if (g + 1 < GITERS)
            asm volatile("cp.async.wait_group %0;" :: "n"(1));
        else
            asm volatile("cp.async.wait_group %0;" :: "n"(0));
        __syncthreads();

        if (g + 2 < GITERS) {
            int ps = stage + 2; if (ps >= BSTAGES) ps -= BSTAGES;
            prefetchB(g + 2, ps);
        }

        const uint32_t stb = sb + A_BYTES + (uint32_t)stage * BST_BYTES;
        const uint32_t akoff = (uint32_t)it * KCH * 2;

#pragma unroll
        for (int ks = 0; ks < 4; ks++) {
            const uint32_t koff = (uint32_t)ks * 32;
            uint32_t a[4], b[4][4];
            ldsm4(a[0], a[1], a[2], a[3], sb + aoffb + akoff + koff);
#pragma unroll
            for (int p = 0; p < 4; p++)
                ldsm4(b[p][0], b[p][1], b[p][2], b[p][3],
                      stb + boffb[p] + koff);
#pragma unroll
            for (int p = 0; p < 4; p++) {
                float* a0 = acc[2 * p];
                float* a1 = acc[2 * p + 1];
                mma_bf16(a0[0], a0[1], a0[2], a0[3],
                         a[0], a[1], a[2], a[3], b[p][0], b[p][1]);
                mma_bf16(a1[0], a1[1], a1[2], a1[3],
                         a[0], a[1], a[2], a[3], b[p][2], b[p][3]);
            }
        }

        if (it == 7) {
            const int bn = bn0 + (g >> 3) * 128;
            const int row = bm + warpM * 16 + r;
#pragma unroll
            for (int nt = 0; nt < 8; nt++) {
                const int col = bn + warpN * 64 + nt * 8 + 2 * c4;
                const float* a = acc[nt];
                unsigned int p0 =
                    (unsigned int)__bfloat16_as_ushort(__float2bfloat16(a[0]))
                    | ((unsigned int)__bfloat16_as_ushort(__float2bfloat16(a[1])) << 16);
                unsigned int p1 =
                    (unsigned int)__bfloat16_as_ushort(__float2bfloat16(a[2]))
                    | ((unsigned int)__bfloat16_as_ushort(__float2bfloat16(a[3])) << 16);
                *reinterpret_cast<unsigned int*>(C16 + (size_t)row * VOC + col) = p0;
                *reinterpret_cast<unsigned int*>(C16 + (size_t)(row + 8) * VOC + col) = p1;
            }
        }

        if (++stage == BSTAGES) stage = 0;
    }
}

// ---------------- per-row: approx select + exact rescore + softmax + A@V ----
#define TT 512
__global__ __launch_bounds__(TT, 2)
void topk_softmax_gather(const unsigned short* __restrict__ dots16,
                         const float* __restrict__ Q,
                         const float* __restrict__ Kf,
                         const float* __restrict__ v,
                         float* __restrict__ out)
{
    extern __shared__ unsigned short keys16[];
    __shared__ unsigned int hist[256];
    __shared__ unsigned int scanbuf[2][256];
    __shared__ unsigned int cscan[2][TT];
    __shared__ float        f_red[TT];
    __shared__ float qrow[DIM];
    __shared__ int   sel_idx[MAXSEL];
    __shared__ float sel_val[MAXSEL];
    __shared__ float sel_w[MAXSEL];
    __shared__ unsigned int s_bucket;
    __shared__ int s_r;
    __shared__ unsigned int s_thresh;

    const int tid = threadIdx.x;
    const int lane = tid & 31;
    const int wid = tid >> 5;
    const int row = blockIdx.x;
    const unsigned int* drow = reinterpret_cast<const unsigned int*>(
        dots16 + (size_t)row * VOC);

    for (int i = tid; i < VOC / 2; i += TT) {
        const unsigned int w = drow[i];
        const unsigned int k0 = f2k16(w & 0xFFFFu);
        const unsigned int k1 = f2k16(w >> 16);
        reinterpret_cast<unsigned int*>(keys16)[i] = k0 | (k1 << 16);
    }
    if (tid < DIM)
        qrow[tid] = Q[(size_t)row * DIM + tid];
    __syncthreads();

    if (tid < 256) hist[tid] = 0;
    __syncthreads();
    for (int i = tid; i < VOC; i += TT) {
        const unsigned int bin = (unsigned int)keys16[i] >> 8;
        const unsigned int mask = __match_any_sync(0xFFFFFFFFu, bin);
        if ((__ffs(mask) - 1) == lane)
            atomicAdd(&hist[bin], (unsigned int)__popc(mask));
    }
    __syncthreads();
    {
        if (tid < 256) scanbuf[0][tid] = hist[tid];
        __syncthreads();
        int src = 0;
        for (int off = 1; off < 256; off <<= 1) {
            unsigned int val = 0;
            if (tid < 256) {
                val = scanbuf[src][tid];
                if (tid + off < 256) val += scanbuf[src][tid + off];
            }
            __syncthreads();
            if (tid < 256) scanbuf[src ^ 1][tid] = val;
            __syncthreads();
            src ^= 1;
        }
        if (tid < 256) {
            const unsigned int cumb  = scanbuf[src][tid];
            const unsigned int cumb1 = (tid == 255) ? 0u : scanbuf[src][tid + 1];
            if (cumb >= TOPK && cumb1 < TOPK) {
                s_bucket = (unsigned int)tid;
                s_r = TOPK - (int)cumb1;
            }
        }
        __syncthreads();
    }
    const unsigned int bucket = s_bucket;
    const int r1 = s_r;
    __syncthreads();

    if (tid < 256) hist[tid] = 0;
    __syncthreads();
    for (int i = tid; i < VOC; i += TT) {
        const unsigned int k = keys16[i];
        if ((k >> 8) == bucket)
            atomicAdd(&hist[k & 0xFFu], 1u);
    }
    __syncthreads();
    {
        if (tid < 256) scanbuf[0][tid] = hist[tid];
        __syncthreads();
        int src = 0;
        for (int off = 1; off < 256; off <<= 1) {
            unsigned int val = 0;
            if (tid < 256) {
                val = scanbuf[src][tid];
                if (tid + off < 256) val += scanbuf[src][tid + off];
            }
            __syncthreads();
            if (tid < 256) scanbuf[src ^ 1][tid] = val;
            __syncthreads();
            src ^= 1;
        }
        if (tid < 256) {
            const unsigned int cumb  = scanbuf[src][tid];
            const unsigned int cumb1 = (tid == 255) ? 0u : scanbuf[src][tid + 1];
            if (cumb >= (unsigned int)r1 && cumb1 < (unsigned int)r1)
                s_thresh = (bucket << 8) | (unsigned int)tid;
        }
        __syncthreads();
    }
    const unsigned int cut16 = ftok16(k16tof(s_thresh) - MARGIN);

    int c = 0;
    for (int i = tid; i < VOC; i += TT)
        if ((unsigned int)keys16[i] >= cut16) c++;
    cscan[0][tid] = (unsigned int)c;
    __syncthreads();
    int src = 0;
    for (int off = 1; off < TT; off <<= 1) {
        unsigned int val = cscan[src][tid];
        if (tid >= off) val += cscan[src][tid - off];
        __syncthreads();
        cscan[src ^ 1][tid] = val;
        __syncthreads();
        src ^= 1;
    }
    int pos = (tid == 0) ? 0 : (int)cscan[src][tid - 1];
    const int count = min((int)cscan[src][TT - 1], MAXSEL);

    for (int i = tid; i < VOC; i += TT) {
        if ((unsigned int)keys16[i] >= cut16) {
            if (pos < MAXSEL) sel_idx[pos] = i;
            pos++;
        }
    }
    __syncthreads();

    for (int s = wid; s < count; s += (TT / 32)) {
        const int idx = sel_idx[s];
        const float4* kr = reinterpret_cast<const float4*>(Kf + (size_t)idx * DIM);
        float sum = 0.0f;
#pragma unroll
        for (int j = 0; j < 4; j++) {
            const float4 a = kr[lane * 4 + j];
            const float4 qv = *reinterpret_cast<const float4*>(&qrow[lane * 16 + j * 4]);
            sum += qv.x * a.x + qv.y * a.y + qv.z * a.z + qv.w * a.w;
        }
#pragma unroll
        for (int off = 16; off > 0; off >>= 1)
            sum += __shfl_xor_sync(0xFFFFFFFFu, sum, off);
        if (lane == 0) sel_val[s] = sum;
    }
    __syncthreads();

    float mx = -3.4e38f;
    if (tid < count) mx = sel_val[tid];
    f_red[tid] = mx;
    __syncthreads();
#pragma unroll
    for (int s = TT / 2; s > 0; s >>= 1) {
        if (tid < s) f_red[tid] = fmaxf(f_red[tid], f_red[tid + s]);
        __syncthreads();
    }
    const float m = f_red[0];

    if (tid < count) {
        const float mine = sel_val[tid];
        int greater = 0;
        for (int j = 0; j < count; j++)
            greater += (sel_val[j] > mine);
        sel_w[tid] = (greater < TOPK) ? expf(mine - m) : 0.0f;
    }
    __syncthreads();

    float z = (tid < count) ? sel_w[tid] : 0.0f;
    f_red[tid] = z;
    __syncthreads();
#pragma unroll
    for (int s = TT / 2; s > 0; s >>= 1) {
        if (tid < s) f_red[tid] += f_red[tid + s];
        __syncthreads();
    }
    const float Z = f_red[0];

    float acc0 = 0.0f;
    for (int s = 0; s < count; s++)
        acc0 += sel_w[s] * v[(size_t)sel_idx[s] * DIM + tid];
    out[(size_t)row * DIM + tid] = acc0 / Z;
}

// ---------------- launch ----------------------------------------------------
extern "C" void kernel_launch(void* const* d_in, const int* in_sizes, int n_in,
                              void* d_out, int out_size)
{
    const float* x  = (const float*)d_in[0];
    const float* cb = (const float*)d_in[1];
    const float* Wq = (const float*)d_in[2];
    const float* bq = (const float*)d_in[3];
    const float* Wk = (const float*)d_in[4];
    const float* bk = (const float*)d_in[5];
    const float* Wv = (const float*)d_in[6];
    const float* bv = (const float*)d_in[7];
    float* out = (float*)d_out;

    float *q, *k, *v;
    unsigned short *qb, *kb, *xh, *xl, *ch, *cl, *wh, *wl, *dots16;
    cudaGetSymbolAddress((void**)&q,      g_q);
    cudaGetSymbolAddress((void**)&k,      g_k);
    cudaGetSymbolAddress((void**)&v,      g_v);
    cudaGetSymbolAddress((void**)&qb,     g_qb);
    cudaGetSymbolAddress((void**)&kb,     g_kb);
    cudaGetSymbolAddress((void**)&xh,     g_xh);
    cudaGetSymbolAddress((void**)&xl,     g_xl);
    cudaGetSymbolAddress((void**)&ch,     g_ch);
    cudaGetSymbolAddress((void**)&cl,     g_cl);
    cudaGetSymbolAddress((void**)&wh,     g_wh);
    cudaGetSymbolAddress((void**)&wl,     g_wl);
    cudaGetSymbolAddress((void**)&dots16, g_dots16);

    cudaFuncSetAttribute(topk_softmax_gather,
                         cudaFuncAttributeMaxDynamicSharedMemorySize,
                         VOC * (int)sizeof(unsigned short));
    cudaFuncSetAttribute(dots_bf16,
                         cudaFuncAttributeMaxDynamicSharedMemorySize, DOTS_SMEM);
    cudaFuncSetAttribute((const void*)gemm_bf16x3<true, 3>,
                         cudaFuncAttributeMaxDynamicSharedMemorySize, PROJ_SMEM);
    cudaFuncSetAttribute((const void*)gemm_bf16x3<false, 1>,
                         cudaFuncAttributeMaxDynamicSharedMemorySize, PROJ_SMEM);

    dim3 blk(256);
    const int WN = DIM * DIM;

    split_bf16<<<(BATCH * DIM + 255) / 256, blk>>>(x, xh, xl, BATCH * DIM);
    split_bf16<<<(VOC * DIM + 255) / 256, blk>>>(cb, ch, cl, VOC * DIM);
    transpose_split_w<<<(WN + 255) / 256, blk>>>(Wq, wh + 0 * WN, wl + 0 * WN);
    transpose_split_w<<<(WN + 255) / 256, blk>>>(Wk, wh + 1 * WN, wl + 1 * WN);
    transpose_split_w<<<(WN + 255) / 256, blk>>>(Wv, wh + 2 * WN, wl + 2 * WN);

    gemm_bf16x3<true, 3><<<dim3(BATCH / 128, DIM / 128), blk, PROJ_SMEM>>>(
        xh, xl, wh + 0 * WN, wl + 0 * WN, bq, q, qb);
    gemm_bf16x3<true, 3><<<dim3(VOC / 128, DIM / 128), blk, PROJ_SMEM>>>(
        ch, cl, wh + 1 * WN, wl + 1 * WN, bk, k, kb);
    gemm_bf16x3<false, 1><<<dim3(VOC / 128, DIM / 128), blk, PROJ_SMEM>>>(
        ch, cl, wh + 2 * WN, wl + 2 * WN, bv, v, nullptr);

    dots_bf16<<<dim3(BATCH / MT, VOC / (NSUB * 128)), DT, DOTS_SMEM>>>(
        qb, kb, dots16);

    topk_softmax_gather<<<BATCH, TT, VOC * (int)sizeof(unsigned short)>>>(
        dots16, q, k, v, out);
}